// round 5
// baseline (speedup 1.0000x reference)
#include <cuda_runtime.h>
#include <cuda_fp16.h>
#include <math.h>
#include <stdint.h>

// Problem constants
#define BATCH 8
#define CIN   384
#define OCH   512
#define NTOK  2304   // 48*48

#define NTHREADS 256
// Block tile 128(M) x 256(N), K-tile = 32 halves. Warp tile 64x64 (2x4 warps).
#define SNT 40    // NT smem row stride (halves)
#define STRA 136  // TR smem row stride for A tiles (128 wide)
#define STRB 264  // TR smem row stride for B tiles (256 wide)

// Static scratch (no allocations allowed)
__device__ __half g_q [(size_t)BATCH * NTOK * OCH];   // [B][tok][och]
__device__ __half g_k [(size_t)BATCH * NTOK * OCH];   // [B][tok][och]
__device__ __half g_vt[(size_t)BATCH * OCH * NTOK];   // [B][och][tok]
__device__ __half g_p [(size_t)BATCH * NTOK * NTOK];  // probs
__device__ __half g_ao[(size_t)BATCH * NTOK * OCH];   // [B][tok][och]
__device__ float  g_s [(size_t)BATCH * NTOK * NTOK];  // scores fp32

// ---------------------------------------------------------------------------
// Helpers
// ---------------------------------------------------------------------------
__device__ __forceinline__ uint32_t smem_u32(const void* p) {
    uint32_t a;
    asm("{ .reg .u64 t; cvta.to.shared.u64 t, %1; cvt.u32.u64 %0, t; }" : "=r"(a) : "l"(p));
    return a;
}
__device__ __forceinline__ uint32_t pack_h2(float x, float y) {
    __half2 h = __floats2half2_rn(x, y);
    return *reinterpret_cast<uint32_t*>(&h);
}
__device__ __forceinline__ void ldsm4(uint32_t r[4], uint32_t addr) {
    asm volatile("ldmatrix.sync.aligned.m8n8.x4.shared.b16 {%0,%1,%2,%3}, [%4];"
                 : "=r"(r[0]), "=r"(r[1]), "=r"(r[2]), "=r"(r[3]) : "r"(addr));
}
__device__ __forceinline__ void ldsm4t(uint32_t r[4], uint32_t addr) {
    asm volatile("ldmatrix.sync.aligned.m8n8.x4.trans.shared.b16 {%0,%1,%2,%3}, [%4];"
                 : "=r"(r[0]), "=r"(r[1]), "=r"(r[2]), "=r"(r[3]) : "r"(addr));
}
__device__ __forceinline__ void mma16816(float c[4], const uint32_t a[4],
                                         uint32_t b0, uint32_t b1) {
    asm volatile(
        "mma.sync.aligned.m16n8k16.row.col.f32.f16.f16.f32 "
        "{%0,%1,%2,%3}, {%4,%5,%6,%7}, {%8,%9}, {%0,%1,%2,%3};"
        : "+f"(c[0]), "+f"(c[1]), "+f"(c[2]), "+f"(c[3])
        : "r"(a[0]), "r"(a[1]), "r"(a[2]), "r"(a[3]), "r"(b0), "r"(b1));
}
__device__ __forceinline__ void cp16(uint32_t saddr, const void* gaddr) {
    asm volatile("cp.async.cg.shared.global [%0], [%1], 16;" :: "r"(saddr), "l"(gaddr));
}
__device__ __forceinline__ void cp_commit() { asm volatile("cp.async.commit_group;"); }
__device__ __forceinline__ void cp_wait0()  { asm volatile("cp.async.wait_group 0;" ::: "memory"); }

// ---------------------------------------------------------------------------
// f16 source: cp.async straight into NT tile [ROWS][SNT].
// ---------------------------------------------------------------------------
template <int ROWS>
__device__ __forceinline__ void cp_stage(uint32_t sbase, const __half* __restrict__ S,
                                         int ld, int r0, int kt, int tid)
{
    constexpr int CH = ROWS / 64;   // 128 -> 2, 256 -> 4
#pragma unroll
    for (int i = 0; i < CH; i++) {
        const int idx = tid + i * 256;
        const int r = idx >> 2, c8 = (idx & 3) * 8;
        cp16(sbase + (uint32_t)(r * SNT + c8) * 2, &S[(size_t)(r0 + r) * ld + kt + c8]);
    }
}

// ---------------------------------------------------------------------------
// f32 source staging. MODE 1 = row-major [r][k]; MODE 2 = transposed [k][r].
// ---------------------------------------------------------------------------
template <int MODE, int ROWS>
__device__ __forceinline__ void reg_load(uint4* R, const float* __restrict__ S,
                                         int ld, int r0, int kt, int tid)
{
    constexpr int CH = ROWS / 32;
#pragma unroll
    for (int i = 0; i < CH; i++) {
        const int idx = tid + i * 256;
        if (MODE == 1) {
            const int r = idx >> 3, c4 = (idx & 7) * 4;
            R[i] = *reinterpret_cast<const uint4*>(&S[(size_t)(r0 + r) * ld + kt + c4]);
        } else {
            constexpr int RQ = ROWS / 4;
            const int k = idx / RQ, m4 = (idx % RQ) * 4;
            R[i] = *reinterpret_cast<const uint4*>(&S[(size_t)(kt + k) * ld + r0 + m4]);
        }
    }
}

template <int MODE, int ROWS>
__device__ __forceinline__ void reg_store(const uint4* R, __half* tile, int tid)
{
    constexpr int CH = ROWS / 32;
    constexpr int STR = (ROWS == 256) ? STRB : STRA;
#pragma unroll
    for (int i = 0; i < CH; i++) {
        const int idx = tid + i * 256;
        const float4 f = *reinterpret_cast<const float4*>(&R[i]);
        uint2 v; v.x = pack_h2(f.x, f.y); v.y = pack_h2(f.z, f.w);
        if (MODE == 1) {
            const int r = idx >> 3, c4 = (idx & 7) * 4;
            *reinterpret_cast<uint2*>(&tile[r * SNT + c4]) = v;
        } else {
            constexpr int RQ = ROWS / 4;
            const int k = idx / RQ, m4 = (idx % RQ) * 4;
            *reinterpret_cast<uint2*>(&tile[k * STR + m4]) = v;
        }
    }
}

// ---------------------------------------------------------------------------
// One 128x256x32 tile step. Warp tile 64x64 via m16n8k16 + ldmatrix.
// ---------------------------------------------------------------------------
template <int AM, int BM>
__device__ __forceinline__ void compute_bk(uint32_t sa, uint32_t sb,
                                           float acc[4][8][4], int lane, int wm, int wn)
{
    constexpr bool ATR = (AM == 2), BTR = (BM == 2);
#pragma unroll
    for (int ks = 0; ks < 32; ks += 16) {
        uint32_t a[4][4];
#pragma unroll
        for (int mb = 0; mb < 4; mb++) {
            if (!ATR) {
                const int row = wm + mb * 16 + (lane & 15);
                const int col = ks + ((lane >> 4) << 3);
                ldsm4(a[mb], sa + (uint32_t)(row * SNT + col) * 2);
            } else {
                const int k   = ks + (lane & 7) + ((lane & 16) >> 1);
                const int col = wm + mb * 16 + (lane & 8);
                ldsm4t(a[mb], sa + (uint32_t)(k * STRA + col) * 2);
            }
        }
        uint32_t bfr[4][4];
#pragma unroll
        for (int nb2 = 0; nb2 < 4; nb2++) {
            if (!BTR) {
                const int row = wn + nb2 * 16 + (lane & 15);
                const int col = ks + ((lane >> 4) << 3);
                ldsm4(bfr[nb2], sb + (uint32_t)(row * SNT + col) * 2);
            } else {
                const int k   = ks + (lane & 7) + (lane & 8);
                const int col = wn + nb2 * 16 + ((lane & 16) >> 1);
                ldsm4t(bfr[nb2], sb + (uint32_t)(k * STRB + col) * 2);
            }
        }
#pragma unroll
        for (int mb = 0; mb < 4; mb++)
#pragma unroll
            for (int nb = 0; nb < 8; nb++) {
                uint32_t b0, b1;
                if (!BTR) { b0 = bfr[nb >> 1][nb & 1];       b1 = bfr[nb >> 1][(nb & 1) + 2]; }
                else      { b0 = bfr[nb >> 1][2 * (nb & 1)]; b1 = bfr[nb >> 1][2 * (nb & 1) + 1]; }
                mma16816(acc[mb][nb], a[mb], b0, b1);
            }
    }
}

// ---------------------------------------------------------------------------
// Universal batched GEMM: C[m][n] = scale * sum_k opA(A)[m][k]*opB(B)[n][k] + bias
// AM/BM: 0 = f16 NT (cp.async), 1 = f32 NT, 2 = f32 transposed.
// OUTH: 1 = half out. BIAS: 0 none, 1 row, 2 col.
// ---------------------------------------------------------------------------
template <int AM, int BM, int OUTH, int BIAS>
__global__ __launch_bounds__(NTHREADS)
void hgemm(const void* __restrict__ A, const void* __restrict__ B, void* __restrict__ C,
           int K, int ldA, int ldB, int ldC,
           size_t sA, size_t sB, size_t sC,
           const float* __restrict__ bias, float scale)
{
    extern __shared__ __half dsm[];
    constexpr int ASZ = (AM == 2) ? 32 * STRA : 128 * SNT;
    constexpr int BSZ = (BM == 2) ? 32 * STRB : 256 * SNT;
    __half* smA[2] = {dsm, dsm + ASZ};
    __half* smB[2] = {dsm + 2 * ASZ, dsm + 2 * ASZ + BSZ};
    const uint32_t ua[2] = {smem_u32(smA[0]), smem_u32(smA[1])};
    const uint32_t ub[2] = {smem_u32(smB[0]), smem_u32(smB[1])};

    const int tid = threadIdx.x;
    const int warp = tid >> 5, lane = tid & 31;
    const int wm = (warp >> 2) * 64, wn = (warp & 3) * 64;
    const int b = blockIdx.z;
    const int row0 = blockIdx.y * 128;
    const int col0 = blockIdx.x * 256;

    const void* Ab = (AM == 0) ? (const void*)((const __half*)A + (size_t)b * sA)
                               : (const void*)((const float*)A + (size_t)b * sA);
    const void* Bb = (BM == 0) ? (const void*)((const __half*)B + (size_t)b * sB)
                               : (const void*)((const float*)B + (size_t)b * sB);
    constexpr bool ANY_CP = (AM == 0) || (BM == 0);

    float acc[4][8][4];
#pragma unroll
    for (int i = 0; i < 4; i++)
#pragma unroll
        for (int j = 0; j < 8; j++)
#pragma unroll
            for (int q = 0; q < 4; q++) acc[i][j][q] = 0.f;

    uint4 ra[4], rb[8];
    // prologue: stage tile 0 into buffer 0
    if (AM == 0) cp_stage<128>(ua[0], (const __half*)Ab, ldA, row0, 0, tid);
    else { reg_load<AM, 128>(ra, (const float*)Ab, ldA, row0, 0, tid);
           reg_store<AM, 128>(ra, smA[0], tid); }
    if (BM == 0) cp_stage<256>(ub[0], (const __half*)Bb, ldB, col0, 0, tid);
    else { reg_load<BM, 256>(rb, (const float*)Bb, ldB, col0, 0, tid);
           reg_store<BM, 256>(rb, smB[0], tid); }
    if (ANY_CP) { cp_commit(); cp_wait0(); }
    __syncthreads();

    const int T = K / 32;
    for (int t = 0; t < T; t++) {
        const int p = t & 1;
        const bool more = (t + 1 < T);
        if (more) {
            const int kt = (t + 1) * 32;
            if (AM != 0) reg_load<AM, 128>(ra, (const float*)Ab, ldA, row0, kt, tid);
            if (BM != 0) reg_load<BM, 256>(rb, (const float*)Bb, ldB, col0, kt, tid);
            if (AM == 0) cp_stage<128>(ua[p ^ 1], (const __half*)Ab, ldA, row0, kt, tid);
            if (BM == 0) cp_stage<256>(ub[p ^ 1], (const __half*)Bb, ldB, col0, kt, tid);
            if (ANY_CP) cp_commit();
        }
        compute_bk<AM, BM>(ua[p], ub[p], acc, lane, wm, wn);
        if (more) {
            if (AM != 0) reg_store<AM, 128>(ra, smA[p ^ 1], tid);
            if (BM != 0) reg_store<BM, 256>(rb, smB[p ^ 1], tid);
            if (ANY_CP) cp_wait0();
            __syncthreads();
        }
    }

    // Epilogue
#pragma unroll
    for (int mb = 0; mb < 4; mb++) {
        const int m0 = row0 + wm + mb * 16 + (lane >> 2);
        const float rb0 = (BIAS == 1) ? bias[m0] : 0.f;
        const float rb1 = (BIAS == 1) ? bias[m0 + 8] : 0.f;
#pragma unroll
        for (int nb = 0; nb < 8; nb++) {
            const int n = col0 + wn + nb * 8 + 2 * (lane & 3);
            float cb0 = 0.f, cb1 = 0.f;
            if (BIAS == 2) { cb0 = bias[n]; cb1 = bias[n + 1]; }
            float v0 = acc[mb][nb][0] * scale + rb0 + cb0;
            float v1 = acc[mb][nb][1] * scale + rb0 + cb1;
            float v2 = acc[mb][nb][2] * scale + rb1 + cb0;
            float v3 = acc[mb][nb][3] * scale + rb1 + cb1;
            if (OUTH) {
                __half* Ch = (__half*)C + (size_t)b * sC;
                *reinterpret_cast<__half2*>(&Ch[(size_t)m0 * ldC + n])       = __floats2half2_rn(v0, v1);
                *reinterpret_cast<__half2*>(&Ch[(size_t)(m0 + 8) * ldC + n]) = __floats2half2_rn(v2, v3);
            } else {
                float* Cf = (float*)C + (size_t)b * sC;
                *reinterpret_cast<float2*>(&Cf[(size_t)m0 * ldC + n])       = make_float2(v0, v1);
                *reinterpret_cast<float2*>(&Cf[(size_t)(m0 + 8) * ldC + n]) = make_float2(v2, v3);
            }
        }
    }
}

// ---------------------------------------------------------------------------
// Row softmax: fp32 scores in, half probs out. 2304 = 256 x 9.
// ---------------------------------------------------------------------------
__global__ __launch_bounds__(256)
void softmax_kernel(const float* __restrict__ S, __half* __restrict__ P)
{
    const float* p = S + blockIdx.x * (size_t)NTOK;
    __half* o = P + blockIdx.x * (size_t)NTOK;
    const int t = threadIdx.x;
    __shared__ float red[256];

    float v[9];
    float m = -INFINITY;
#pragma unroll
    for (int j = 0; j < 9; j++) { v[j] = p[t + j * 256]; m = fmaxf(m, v[j]); }
    red[t] = m; __syncthreads();
    for (int s = 128; s > 0; s >>= 1) {
        if (t < s) red[t] = fmaxf(red[t], red[t + s]);
        __syncthreads();
    }
    m = red[0];
    __syncthreads();

    float sum = 0.f;
#pragma unroll
    for (int j = 0; j < 9; j++) { v[j] = __expf(v[j] - m); sum += v[j]; }
    red[t] = sum; __syncthreads();
    for (int s = 128; s > 0; s >>= 1) {
        if (t < s) red[t] += red[t + s];
        __syncthreads();
    }
    const float inv = 1.0f / red[0];
#pragma unroll
    for (int j = 0; j < 9; j++) o[t + j * 256] = __float2half_rn(v[j] * inv);
}

// ---------------------------------------------------------------------------
extern "C" void kernel_launch(void* const* d_in, const int* in_sizes, int n_in,
                              void* d_out, int out_size)
{
    const float* x  = (const float*)d_in[0];
    const float* Wq = (const float*)d_in[1];
    const float* bq = (const float*)d_in[2];
    const float* Wk = (const float*)d_in[3];
    const float* bk = (const float*)d_in[4];
    const float* Wv = (const float*)d_in[5];
    const float* bv = (const float*)d_in[6];
    const float* Wo = (const float*)d_in[7];
    const float* bo = (const float*)d_in[8];
    float* out = (float*)d_out;

    __half *q, *k, *vt, *p, *ao;
    float* s;
    cudaGetSymbolAddress((void**)&q,  g_q);
    cudaGetSymbolAddress((void**)&k,  g_k);
    cudaGetSymbolAddress((void**)&vt, g_vt);
    cudaGetSymbolAddress((void**)&p,  g_p);
    cudaGetSymbolAddress((void**)&ao, g_ao);
    cudaGetSymbolAddress((void**)&s,  g_s);

    // Dynamic smem sizes per instantiation
    const int smQKV = (2 * 32 * STRA + 2 * 256 * SNT) * 2;   // <2,1>
    const int smVT  = (2 * 128 * SNT + 2 * 32 * STRB) * 2;   // <1,2>
    const int smFF  = (2 * 128 * SNT + 2 * 256 * SNT) * 2;   // <0,0>, <1,0>
    cudaFuncSetAttribute(hgemm<2,1,1,2>, cudaFuncAttributeMaxDynamicSharedMemorySize, smQKV);
    cudaFuncSetAttribute(hgemm<1,2,1,1>, cudaFuncAttributeMaxDynamicSharedMemorySize, smVT);
    cudaFuncSetAttribute(hgemm<0,0,0,0>, cudaFuncAttributeMaxDynamicSharedMemorySize, smFF);
    cudaFuncSetAttribute(hgemm<0,0,1,0>, cudaFuncAttributeMaxDynamicSharedMemorySize, smFF);
    cudaFuncSetAttribute(hgemm<1,0,0,1>, cudaFuncAttributeMaxDynamicSharedMemorySize, smFF);

    const dim3 blk(NTHREADS);
    const size_t sQKV = (size_t)NTOK * OCH;
    const size_t sS   = (size_t)NTOK * NTOK;
    const size_t sX   = (size_t)CIN * NTOK;
    const float scale = 0.044194173824159216f; // 1/sqrt(512)

    // 1) Q, K: [tok][och] = x^T W^T + b  (A = x f32-trans, B = W f32-NT, col bias)
    {
        dim3 g(OCH / 256, NTOK / 128, BATCH);
        hgemm<2,1,1,2><<<g, blk, smQKV>>>(x, Wq, q, CIN, NTOK, CIN, OCH, sX, 0, sQKV, bq, 1.0f);
        hgemm<2,1,1,2><<<g, blk, smQKV>>>(x, Wk, k, CIN, NTOK, CIN, OCH, sX, 0, sQKV, bk, 1.0f);
    }
    // 1b) V^T: [och][tok] = Wv x + bv   (A = Wv f32-NT, B = x f32-trans, row bias)
    {
        dim3 g(NTOK / 256, OCH / 128, BATCH);
        hgemm<1,2,1,1><<<g, blk, smVT>>>(Wv, x, vt, CIN, CIN, NTOK, NTOK, 0, sX, sQKV, bv, 1.0f);
    }
    // 2) S = scale * Q K^T  (fp32 out)
    {
        dim3 g(NTOK / 256, NTOK / 128, BATCH);
        hgemm<0,0,0,0><<<g, blk, smFF>>>(q, k, s, OCH, OCH, OCH, NTOK, sQKV, sQKV, sS, nullptr, scale);
    }
    // 3) softmax -> half probs
    softmax_kernel<<<BATCH * NTOK, 256>>>(s, p);

    // 4) AO[tok][och] = P V  (A = P f16, B = V^T f16)
    {
        dim3 g(OCH / 256, NTOK / 128, BATCH);
        hgemm<0,0,1,0><<<g, blk, smFF>>>(p, vt, ao, NTOK, NTOK, NTOK, OCH, sS, sQKV, sQKV, nullptr, 1.0f);
    }
    // 5) out[och][tok] = Wo AO^T + bo  (A = Wo f32-NT, B = AO f16-NT, fp32 out, row bias)
    {
        dim3 g(NTOK / 256, OCH / 128, BATCH);
        hgemm<1,0,0,1><<<g, blk, smFF>>>(Wo, ao, out, OCH, OCH, OCH, NTOK, 0, sQKV, (size_t)OCH * NTOK, bo, 1.0f);
    }
}

// round 6
// speedup vs baseline: 1.6835x; 1.6835x over previous
#include <cuda_runtime.h>
#include <cuda_fp16.h>
#include <math.h>
#include <stdint.h>

// Problem constants
#define BATCH 8
#define CIN   384
#define OCH   512
#define NTOK  2304   // 48*48

#define NTHREADS 256
// Block tile 128x128, K-tile = 32 halves, warp tile 64x32 (2x4 warps)
#define SNT 40    // NT smem tile row stride (halves): [128 r][40]
#define STR 136   // TR smem tile row stride (halves): [32 k][136]

// Static scratch (no allocations allowed)
__device__ __half g_q [(size_t)BATCH * NTOK * OCH];   // [B][tok][och]
__device__ __half g_k [(size_t)BATCH * NTOK * OCH];   // [B][tok][och]
__device__ __half g_vt[(size_t)BATCH * OCH * NTOK];   // [B][och][tok]  (V transposed)
__device__ __half g_p [(size_t)BATCH * NTOK * NTOK];  // probs [B][tok][tok]
__device__ __half g_ao[(size_t)BATCH * NTOK * OCH];   // [B][tok][och]
__device__ float  g_s [(size_t)BATCH * NTOK * NTOK];  // scores fp32

// ---------------------------------------------------------------------------
// Helpers
// ---------------------------------------------------------------------------
__device__ __forceinline__ uint32_t smem_u32(const void* p) {
    uint32_t a;
    asm("{ .reg .u64 t; cvta.to.shared.u64 t, %1; cvt.u32.u64 %0, t; }" : "=r"(a) : "l"(p));
    return a;
}
__device__ __forceinline__ uint32_t pack_h2(float x, float y) {
    __half2 h = __floats2half2_rn(x, y);
    return *reinterpret_cast<uint32_t*>(&h);
}
__device__ __forceinline__ void ldsm4(uint32_t r[4], uint32_t addr) {
    asm volatile("ldmatrix.sync.aligned.m8n8.x4.shared.b16 {%0,%1,%2,%3}, [%4];"
                 : "=r"(r[0]), "=r"(r[1]), "=r"(r[2]), "=r"(r[3]) : "r"(addr));
}
__device__ __forceinline__ void ldsm4t(uint32_t r[4], uint32_t addr) {
    asm volatile("ldmatrix.sync.aligned.m8n8.x4.trans.shared.b16 {%0,%1,%2,%3}, [%4];"
                 : "=r"(r[0]), "=r"(r[1]), "=r"(r[2]), "=r"(r[3]) : "r"(addr));
}
__device__ __forceinline__ void mma16816(float c[4], const uint32_t a[4],
                                         uint32_t b0, uint32_t b1) {
    asm volatile(
        "mma.sync.aligned.m16n8k16.row.col.f32.f16.f16.f32 "
        "{%0,%1,%2,%3}, {%4,%5,%6,%7}, {%8,%9}, {%0,%1,%2,%3};"
        : "+f"(c[0]), "+f"(c[1]), "+f"(c[2]), "+f"(c[3])
        : "r"(a[0]), "r"(a[1]), "r"(a[2]), "r"(a[3]), "r"(b0), "r"(b1));
}
__device__ __forceinline__ void cp16(uint32_t saddr, const void* gaddr) {
    asm volatile("cp.async.cg.shared.global [%0], [%1], 16;" :: "r"(saddr), "l"(gaddr));
}
__device__ __forceinline__ void cp_commit() { asm volatile("cp.async.commit_group;"); }
__device__ __forceinline__ void cp_wait0()  { asm volatile("cp.async.wait_group 0;" ::: "memory"); }

// ---------------------------------------------------------------------------
// f16 source: cp.async straight into NT tile [128][SNT].
// ---------------------------------------------------------------------------
__device__ __forceinline__ void cp_stage(uint32_t sbase, const __half* __restrict__ S,
                                         int ld, int r0, int kt, int tid)
{
#pragma unroll
    for (int i = 0; i < 2; i++) {
        const int idx = tid + i * 256;
        const int r = idx >> 2, c8 = (idx & 3) * 8;
        cp16(sbase + (uint32_t)(r * SNT + c8) * 2, &S[(size_t)(r0 + r) * ld + kt + c8]);
    }
}

// ---------------------------------------------------------------------------
// f32 source staging. MODE 1 = row-major [r][k]; MODE 2 = transposed [k][r].
// ---------------------------------------------------------------------------
template <int MODE>
__device__ __forceinline__ void reg_load(uint4 R[4], const float* __restrict__ S,
                                         int ld, int r0, int kt, int tid)
{
#pragma unroll
    for (int i = 0; i < 4; i++) {
        const int idx = tid + i * 256;
        if (MODE == 1) {
            const int r = idx >> 3, c4 = (idx & 7) * 4;
            R[i] = *reinterpret_cast<const uint4*>(&S[(size_t)(r0 + r) * ld + kt + c4]);
        } else {
            const int k = idx >> 5, m4 = (idx & 31) * 4;
            R[i] = *reinterpret_cast<const uint4*>(&S[(size_t)(kt + k) * ld + r0 + m4]);
        }
    }
}

template <int MODE>
__device__ __forceinline__ void reg_store(const uint4 R[4], __half* tile, int tid)
{
#pragma unroll
    for (int i = 0; i < 4; i++) {
        const int idx = tid + i * 256;
        const float4 f = *reinterpret_cast<const float4*>(&R[i]);
        uint2 v; v.x = pack_h2(f.x, f.y); v.y = pack_h2(f.z, f.w);
        if (MODE == 1) {
            const int r = idx >> 3, c4 = (idx & 7) * 4;
            *reinterpret_cast<uint2*>(&tile[r * SNT + c4]) = v;
        } else {
            const int k = idx >> 5, m4 = (idx & 31) * 4;
            *reinterpret_cast<uint2*>(&tile[k * STR + m4]) = v;
        }
    }
}

// ---------------------------------------------------------------------------
// One 128x128x32 tile step. Warp tile 64x32 via m16n8k16 + ldmatrix.
// ---------------------------------------------------------------------------
template <int AM, int BM>
__device__ __forceinline__ void compute_bk(uint32_t sa, uint32_t sb,
                                           float acc[4][4][4], int lane, int wm, int wn)
{
    constexpr bool ATR = (AM == 2), BTR = (BM == 2);
#pragma unroll
    for (int ks = 0; ks < 32; ks += 16) {
        uint32_t a[4][4];
#pragma unroll
        for (int mb = 0; mb < 4; mb++) {
            if (!ATR) {
                const int row = wm + mb * 16 + (lane & 15);
                const int col = ks + ((lane >> 4) << 3);
                ldsm4(a[mb], sa + (uint32_t)(row * SNT + col) * 2);
            } else {
                const int k   = ks + (lane & 7) + ((lane & 16) >> 1);
                const int col = wm + mb * 16 + (lane & 8);
                ldsm4t(a[mb], sa + (uint32_t)(k * STR + col) * 2);
            }
        }
        uint32_t bfr[2][4];
#pragma unroll
        for (int nb2 = 0; nb2 < 2; nb2++) {
            if (!BTR) {
                const int row = wn + nb2 * 16 + (lane & 15);
                const int col = ks + ((lane >> 4) << 3);
                ldsm4(bfr[nb2], sb + (uint32_t)(row * SNT + col) * 2);
            } else {
                const int k   = ks + (lane & 7) + (lane & 8);
                const int col = wn + nb2 * 16 + ((lane & 16) >> 1);
                ldsm4t(bfr[nb2], sb + (uint32_t)(k * STR + col) * 2);
            }
        }
#pragma unroll
        for (int mb = 0; mb < 4; mb++)
#pragma unroll
            for (int nb = 0; nb < 4; nb++) {
                uint32_t b0, b1;
                if (!BTR) { b0 = bfr[nb >> 1][nb & 1];       b1 = bfr[nb >> 1][(nb & 1) + 2]; }
                else      { b0 = bfr[nb >> 1][2 * (nb & 1)]; b1 = bfr[nb >> 1][2 * (nb & 1) + 1]; }
                mma16816(acc[mb][nb], a[mb], b0, b1);
            }
    }
}

// ---------------------------------------------------------------------------
// Universal batched GEMM: C[m][n] = scale * sum_k opA(A)[m][k]*opB(B)[n][k] + bias
// AM/BM: 0 = f16 NT (cp.async), 1 = f32 NT, 2 = f32 transposed.
// OUTH: 1 = half out. BIAS: 0 none, 1 row, 2 col.
// ---------------------------------------------------------------------------
template <int AM, int BM, int OUTH, int BIAS>
__global__ __launch_bounds__(NTHREADS)
void hgemm(const void* __restrict__ A, const void* __restrict__ B, void* __restrict__ C,
           int K, int ldA, int ldB, int ldC,
           size_t sA, size_t sB, size_t sC,
           const float* __restrict__ bias, float scale)
{
    __shared__ __align__(16) __half smA[2][5120];
    __shared__ __align__(16) __half smB[2][5120];

    const int tid = threadIdx.x;
    const int warp = tid >> 5, lane = tid & 31;
    const int wm = (warp >> 2) * 64, wn = (warp & 3) * 32;
    const int b = blockIdx.z;
    const int row0 = blockIdx.y * 128;
    const int col0 = blockIdx.x * 128;

    const void* Ab = (AM == 0) ? (const void*)((const __half*)A + (size_t)b * sA)
                               : (const void*)((const float*)A + (size_t)b * sA);
    const void* Bb = (BM == 0) ? (const void*)((const __half*)B + (size_t)b * sB)
                               : (const void*)((const float*)B + (size_t)b * sB);
    constexpr bool ANY_CP = (AM == 0) || (BM == 0);

    float acc[4][4][4];
#pragma unroll
    for (int i = 0; i < 4; i++)
#pragma unroll
        for (int j = 0; j < 4; j++)
#pragma unroll
            for (int q = 0; q < 4; q++) acc[i][j][q] = 0.f;

    const uint32_t ua[2] = {smem_u32(smA[0]), smem_u32(smA[1])};
    const uint32_t ub[2] = {smem_u32(smB[0]), smem_u32(smB[1])};

    uint4 ra[4], rb[4];
    // prologue: stage tile 0 into buffer 0
    if (AM == 0) cp_stage(ua[0], (const __half*)Ab, ldA, row0, 0, tid);
    else { reg_load<AM>(ra, (const float*)Ab, ldA, row0, 0, tid);
           reg_store<AM>(ra, smA[0], tid); }
    if (BM == 0) cp_stage(ub[0], (const __half*)Bb, ldB, col0, 0, tid);
    else { reg_load<BM>(rb, (const float*)Bb, ldB, col0, 0, tid);
           reg_store<BM>(rb, smB[0], tid); }
    if (ANY_CP) { cp_commit(); cp_wait0(); }
    __syncthreads();

    const int T = K / 32;
    for (int t = 0; t < T; t++) {
        const int p = t & 1;
        const bool more = (t + 1 < T);
        if (more) {
            const int kt = (t + 1) * 32;
            if (AM != 0) reg_load<AM>(ra, (const float*)Ab, ldA, row0, kt, tid);
            if (BM != 0) reg_load<BM>(rb, (const float*)Bb, ldB, col0, kt, tid);
            if (AM == 0) cp_stage(ua[p ^ 1], (const __half*)Ab, ldA, row0, kt, tid);
            if (BM == 0) cp_stage(ub[p ^ 1], (const __half*)Bb, ldB, col0, kt, tid);
            if (ANY_CP) cp_commit();
        }
        compute_bk<AM, BM>(ua[p], ub[p], acc, lane, wm, wn);
        if (more) {
            if (AM != 0) reg_store<AM>(ra, smA[p ^ 1], tid);
            if (BM != 0) reg_store<BM>(rb, smB[p ^ 1], tid);
            if (ANY_CP) cp_wait0();
            __syncthreads();
        }
    }

    // Epilogue
#pragma unroll
    for (int mb = 0; mb < 4; mb++) {
        const int m0 = row0 + wm + mb * 16 + (lane >> 2);
        const float rb0 = (BIAS == 1) ? bias[m0] : 0.f;
        const float rb1 = (BIAS == 1) ? bias[m0 + 8] : 0.f;
#pragma unroll
        for (int nb = 0; nb < 4; nb++) {
            const int n = col0 + wn + nb * 8 + 2 * (lane & 3);
            float cb0 = 0.f, cb1 = 0.f;
            if (BIAS == 2) { cb0 = bias[n]; cb1 = bias[n + 1]; }
            float v0 = acc[mb][nb][0] * scale + rb0 + cb0;
            float v1 = acc[mb][nb][1] * scale + rb0 + cb1;
            float v2 = acc[mb][nb][2] * scale + rb1 + cb0;
            float v3 = acc[mb][nb][3] * scale + rb1 + cb1;
            if (OUTH) {
                __half* Ch = (__half*)C + (size_t)b * sC;
                *reinterpret_cast<__half2*>(&Ch[(size_t)m0 * ldC + n])       = __floats2half2_rn(v0, v1);
                *reinterpret_cast<__half2*>(&Ch[(size_t)(m0 + 8) * ldC + n]) = __floats2half2_rn(v2, v3);
            } else {
                float* Cf = (float*)C + (size_t)b * sC;
                *reinterpret_cast<float2*>(&Cf[(size_t)m0 * ldC + n])       = make_float2(v0, v1);
                *reinterpret_cast<float2*>(&Cf[(size_t)(m0 + 8) * ldC + n]) = make_float2(v2, v3);
            }
        }
    }
}

// ---------------------------------------------------------------------------
// Row softmax: fp32 scores in, half probs out. 2304 = 256 x 9.
// ---------------------------------------------------------------------------
__global__ __launch_bounds__(256)
void softmax_kernel(const float* __restrict__ S, __half* __restrict__ P)
{
    const float* p = S + blockIdx.x * (size_t)NTOK;
    __half* o = P + blockIdx.x * (size_t)NTOK;
    const int t = threadIdx.x;
    __shared__ float red[256];

    float v[9];
    float m = -INFINITY;
#pragma unroll
    for (int j = 0; j < 9; j++) { v[j] = p[t + j * 256]; m = fmaxf(m, v[j]); }
    red[t] = m; __syncthreads();
    for (int s = 128; s > 0; s >>= 1) {
        if (t < s) red[t] = fmaxf(red[t], red[t + s]);
        __syncthreads();
    }
    m = red[0];
    __syncthreads();

    float sum = 0.f;
#pragma unroll
    for (int j = 0; j < 9; j++) { v[j] = __expf(v[j] - m); sum += v[j]; }
    red[t] = sum; __syncthreads();
    for (int s = 128; s > 0; s >>= 1) {
        if (t < s) red[t] += red[t + s];
        __syncthreads();
    }
    const float inv = 1.0f / red[0];
#pragma unroll
    for (int j = 0; j < 9; j++) o[t + j * 256] = __float2half_rn(v[j] * inv);
}

// ---------------------------------------------------------------------------
extern "C" void kernel_launch(void* const* d_in, const int* in_sizes, int n_in,
                              void* d_out, int out_size)
{
    const float* x  = (const float*)d_in[0];
    const float* Wq = (const float*)d_in[1];
    const float* bq = (const float*)d_in[2];
    const float* Wk = (const float*)d_in[3];
    const float* bk = (const float*)d_in[4];
    const float* Wv = (const float*)d_in[5];
    const float* bv = (const float*)d_in[6];
    const float* Wo = (const float*)d_in[7];
    const float* bo = (const float*)d_in[8];
    float* out = (float*)d_out;

    __half *q, *k, *vt, *p, *ao;
    float* s;
    cudaGetSymbolAddress((void**)&q,  g_q);
    cudaGetSymbolAddress((void**)&k,  g_k);
    cudaGetSymbolAddress((void**)&vt, g_vt);
    cudaGetSymbolAddress((void**)&p,  g_p);
    cudaGetSymbolAddress((void**)&ao, g_ao);
    cudaGetSymbolAddress((void**)&s,  g_s);

    const dim3 blk(NTHREADS);
    const size_t sQKV = (size_t)NTOK * OCH;
    const size_t sS   = (size_t)NTOK * NTOK;
    const size_t sX   = (size_t)CIN * NTOK;
    const float scale = 0.044194173824159216f; // 1/sqrt(512)

    // 1) Q, K: [tok][och] = x^T W^T + b  (A = x f32-trans, B = W f32-NT, col bias)
    {
        dim3 g(OCH / 128, NTOK / 128, BATCH);
        hgemm<2, 1, 1, 2><<<g, blk>>>(x, Wq, q, CIN, NTOK, CIN, OCH, sX, 0, sQKV, bq, 1.0f);
        hgemm<2, 1, 1, 2><<<g, blk>>>(x, Wk, k, CIN, NTOK, CIN, OCH, sX, 0, sQKV, bk, 1.0f);
    }
    // 1b) V^T: [och][tok] = Wv x + bv   (A = Wv f32-NT, B = x f32-trans, row bias)
    {
        dim3 g(NTOK / 128, OCH / 128, BATCH);
        hgemm<1, 2, 1, 1><<<g, blk>>>(Wv, x, vt, CIN, CIN, NTOK, NTOK, 0, sX, sQKV, bv, 1.0f);
    }
    // 2) S = scale * Q K^T  (fp32 out, cp.async both operands)
    {
        dim3 g(NTOK / 128, NTOK / 128, BATCH);
        hgemm<0, 0, 0, 0><<<g, blk>>>(q, k, s, OCH, OCH, OCH, NTOK, sQKV, sQKV, sS, nullptr, scale);
    }
    // 3) softmax -> half probs
    softmax_kernel<<<BATCH * NTOK, 256>>>(s, p);

    // 4) AO[tok][och] = P V  (A = P f16, B = V^T f16, cp.async both)
    {
        dim3 g(OCH / 128, NTOK / 128, BATCH);
        hgemm<0, 0, 1, 0><<<g, blk>>>(p, vt, ao, NTOK, NTOK, NTOK, OCH, sS, sQKV, sQKV, nullptr, 1.0f);
    }
    // 5) out[och][tok] = Wo AO^T + bo  (A = Wo f32-NT, B = AO f16 cp.async, fp32 out, row bias)
    {
        dim3 g(NTOK / 128, OCH / 128, BATCH);
        hgemm<1, 0, 0, 1><<<g, blk>>>(Wo, ao, out, OCH, OCH, OCH, NTOK, 0, sQKV, (size_t)OCH * NTOK, bo, 1.0f);
    }
}

// round 7
// speedup vs baseline: 1.9383x; 1.1513x over previous
#include <cuda_runtime.h>
#include <cuda_fp16.h>
#include <math.h>
#include <stdint.h>

// Problem constants
#define BATCH 8
#define CIN   384
#define OCH   512
#define NTOK  2304   // 48*48

#define NTHREADS 256
// Block tile 128x128, K-tile = 32 halves, warp tile 64x32 (2x4 warps)
#define SNT 40     // NT smem tile row stride (halves): [128 r][40]
#define STR 136    // TR smem tile row stride (halves): [32 k][136]
#define SLOT 5120  // halves per stage slot (10240 B)
#define SLOTB 10240
#define NSTAGE 4
#define SMEM_BYTES (2 * NSTAGE * SLOTB)   // 81920

// Static scratch (no allocations allowed)
__device__ __half g_q [(size_t)BATCH * NTOK * OCH];   // [B][tok][och]
__device__ __half g_k [(size_t)BATCH * NTOK * OCH];   // [B][tok][och]
__device__ __half g_vt[(size_t)BATCH * OCH * NTOK];   // [B][och][tok]  (V transposed)
__device__ __half g_p [(size_t)BATCH * NTOK * NTOK];  // probs [B][tok][tok]
__device__ __half g_ao[(size_t)BATCH * NTOK * OCH];   // [B][tok][och]
__device__ float  g_s [(size_t)BATCH * NTOK * NTOK];  // scores fp32

// ---------------------------------------------------------------------------
// Helpers
// ---------------------------------------------------------------------------
__device__ __forceinline__ uint32_t smem_u32(const void* p) {
    uint32_t a;
    asm("{ .reg .u64 t; cvta.to.shared.u64 t, %1; cvt.u32.u64 %0, t; }" : "=r"(a) : "l"(p));
    return a;
}
__device__ __forceinline__ uint32_t pack_h2(float x, float y) {
    __half2 h = __floats2half2_rn(x, y);
    return *reinterpret_cast<uint32_t*>(&h);
}
__device__ __forceinline__ void ldsm4(uint32_t r[4], uint32_t addr) {
    asm volatile("ldmatrix.sync.aligned.m8n8.x4.shared.b16 {%0,%1,%2,%3}, [%4];"
                 : "=r"(r[0]), "=r"(r[1]), "=r"(r[2]), "=r"(r[3]) : "r"(addr));
}
__device__ __forceinline__ void ldsm4t(uint32_t r[4], uint32_t addr) {
    asm volatile("ldmatrix.sync.aligned.m8n8.x4.trans.shared.b16 {%0,%1,%2,%3}, [%4];"
                 : "=r"(r[0]), "=r"(r[1]), "=r"(r[2]), "=r"(r[3]) : "r"(addr));
}
__device__ __forceinline__ void mma16816(float c[4], const uint32_t a[4],
                                         uint32_t b0, uint32_t b1) {
    asm volatile(
        "mma.sync.aligned.m16n8k16.row.col.f32.f16.f16.f32 "
        "{%0,%1,%2,%3}, {%4,%5,%6,%7}, {%8,%9}, {%0,%1,%2,%3};"
        : "+f"(c[0]), "+f"(c[1]), "+f"(c[2]), "+f"(c[3])
        : "r"(a[0]), "r"(a[1]), "r"(a[2]), "r"(a[3]), "r"(b0), "r"(b1));
}
__device__ __forceinline__ void cp16(uint32_t saddr, const void* gaddr) {
    asm volatile("cp.async.cg.shared.global [%0], [%1], 16;" :: "r"(saddr), "l"(gaddr));
}
__device__ __forceinline__ void cp_commit() { asm volatile("cp.async.commit_group;"); }
template <int N>
__device__ __forceinline__ void cp_waitg() {
    asm volatile("cp.async.wait_group %0;" :: "n"(N) : "memory");
}

// ---------------------------------------------------------------------------
// f16 source: cp.async straight into NT tile [128][SNT].
// ---------------------------------------------------------------------------
__device__ __forceinline__ void cp_stage(uint32_t sbase, const __half* __restrict__ S,
                                         int ld, int r0, int kt, int tid)
{
#pragma unroll
    for (int i = 0; i < 2; i++) {
        const int idx = tid + i * 256;
        const int r = idx >> 2, c8 = (idx & 3) * 8;
        cp16(sbase + (uint32_t)(r * SNT + c8) * 2, &S[(size_t)(r0 + r) * ld + kt + c8]);
    }
}

// ---------------------------------------------------------------------------
// f32 source staging. MODE 1 = row-major [r][k]; MODE 2 = transposed [k][r].
// ---------------------------------------------------------------------------
template <int MODE>
__device__ __forceinline__ void reg_load(uint4 R[4], const float* __restrict__ S,
                                         int ld, int r0, int kt, int tid)
{
#pragma unroll
    for (int i = 0; i < 4; i++) {
        const int idx = tid + i * 256;
        if (MODE == 1) {
            const int r = idx >> 3, c4 = (idx & 7) * 4;
            R[i] = *reinterpret_cast<const uint4*>(&S[(size_t)(r0 + r) * ld + kt + c4]);
        } else {
            const int k = idx >> 5, m4 = (idx & 31) * 4;
            R[i] = *reinterpret_cast<const uint4*>(&S[(size_t)(kt + k) * ld + r0 + m4]);
        }
    }
}

template <int MODE>
__device__ __forceinline__ void reg_store(const uint4 R[4], __half* tile, int tid)
{
#pragma unroll
    for (int i = 0; i < 4; i++) {
        const int idx = tid + i * 256;
        const float4 f = *reinterpret_cast<const float4*>(&R[i]);
        uint2 v; v.x = pack_h2(f.x, f.y); v.y = pack_h2(f.z, f.w);
        if (MODE == 1) {
            const int r = idx >> 3, c4 = (idx & 7) * 4;
            *reinterpret_cast<uint2*>(&tile[r * SNT + c4]) = v;
        } else {
            const int k = idx >> 5, m4 = (idx & 31) * 4;
            *reinterpret_cast<uint2*>(&tile[k * STR + m4]) = v;
        }
    }
}

// ---------------------------------------------------------------------------
// One 128x128x32 tile step. Warp tile 64x32 via m16n8k16 + ldmatrix.
// ---------------------------------------------------------------------------
template <int AM, int BM>
__device__ __forceinline__ void compute_bk(uint32_t sa, uint32_t sb,
                                           float acc[4][4][4], int lane, int wm, int wn)
{
    constexpr bool ATR = (AM == 2), BTR = (BM == 2);
#pragma unroll
    for (int ks = 0; ks < 32; ks += 16) {
        uint32_t a[4][4];
#pragma unroll
        for (int mb = 0; mb < 4; mb++) {
            if (!ATR) {
                const int row = wm + mb * 16 + (lane & 15);
                const int col = ks + ((lane >> 4) << 3);
                ldsm4(a[mb], sa + (uint32_t)(row * SNT + col) * 2);
            } else {
                const int k   = ks + (lane & 7) + ((lane & 16) >> 1);
                const int col = wm + mb * 16 + (lane & 8);
                ldsm4t(a[mb], sa + (uint32_t)(k * STR + col) * 2);
            }
        }
        uint32_t bfr[2][4];
#pragma unroll
        for (int nb2 = 0; nb2 < 2; nb2++) {
            if (!BTR) {
                const int row = wn + nb2 * 16 + (lane & 15);
                const int col = ks + ((lane >> 4) << 3);
                ldsm4(bfr[nb2], sb + (uint32_t)(row * SNT + col) * 2);
            } else {
                const int k   = ks + (lane & 7) + (lane & 8);
                const int col = wn + nb2 * 16 + ((lane & 16) >> 1);
                ldsm4t(bfr[nb2], sb + (uint32_t)(k * STR + col) * 2);
            }
        }
#pragma unroll
        for (int mb = 0; mb < 4; mb++)
#pragma unroll
            for (int nb = 0; nb < 4; nb++) {
                uint32_t b0, b1;
                if (!BTR) { b0 = bfr[nb >> 1][nb & 1];       b1 = bfr[nb >> 1][(nb & 1) + 2]; }
                else      { b0 = bfr[nb >> 1][2 * (nb & 1)]; b1 = bfr[nb >> 1][2 * (nb & 1) + 1]; }
                mma16816(acc[mb][nb], a[mb], b0, b1);
            }
    }
}

// ---------------------------------------------------------------------------
// Universal batched GEMM: C[m][n] = scale * sum_k opA(A)[m][k]*opB(B)[n][k] + bias
// AM/BM: 0 = f16 NT (cp.async 4-stage), 1 = f32 NT, 2 = f32 transposed.
// OUTH: 1 = half out. BIAS: 0 none, 1 row, 2 col.
// ---------------------------------------------------------------------------
template <int AM, int BM, int OUTH, int BIAS>
__global__ __launch_bounds__(NTHREADS, 2)
void hgemm(const void* __restrict__ A, const void* __restrict__ B, void* __restrict__ C,
           int K, int ldA, int ldB, int ldC,
           size_t sA, size_t sB, size_t sC,
           const float* __restrict__ bias, float scale)
{
    extern __shared__ __half dsm[];

    const int tid = threadIdx.x;
    const int warp = tid >> 5, lane = tid & 31;
    const int wm = (warp >> 2) * 64, wn = (warp & 3) * 32;
    const int b = blockIdx.z;
    const int row0 = blockIdx.y * 128;
    const int col0 = blockIdx.x * 128;

    const void* Ab = (AM == 0) ? (const void*)((const __half*)A + (size_t)b * sA)
                               : (const void*)((const float*)A + (size_t)b * sA);
    const void* Bb = (BM == 0) ? (const void*)((const __half*)B + (size_t)b * sB)
                               : (const void*)((const float*)B + (size_t)b * sB);
    constexpr bool ANY_CP = (AM == 0) || (BM == 0);

    const uint32_t uA = smem_u32(dsm);
    const uint32_t uB = uA + NSTAGE * SLOTB;
    __half* const bA = dsm;
    __half* const bB = dsm + NSTAGE * SLOT;

    float acc[4][4][4];
#pragma unroll
    for (int i = 0; i < 4; i++)
#pragma unroll
        for (int j = 0; j < 4; j++)
#pragma unroll
            for (int q = 0; q < 4; q++) acc[i][j][q] = 0.f;

    uint4 ra[4], rb[4];
    const int T = K / 32;   // >= 12 for all our shapes

    // Prologue: cp operands fill stages 0..2; f32 operands fill stage 0.
#pragma unroll
    for (int s = 0; s < NSTAGE - 1; s++) {
        if (AM == 0) cp_stage(uA + s * SLOTB, (const __half*)Ab, ldA, row0, s * 32, tid);
        if (BM == 0) cp_stage(uB + s * SLOTB, (const __half*)Bb, ldB, col0, s * 32, tid);
        if (ANY_CP) cp_commit();
    }
    if (AM != 0) { reg_load<AM>(ra, (const float*)Ab, ldA, row0, 0, tid);
                   reg_store<AM>(ra, bA, tid); }
    if (BM != 0) { reg_load<BM>(rb, (const float*)Bb, ldB, col0, 0, tid);
                   reg_store<BM>(rb, bB, tid); }

    for (int t = 0; t < T; t++) {
        // Stage t must have landed; stages t+1, t+2 may stay in flight.
        if (ANY_CP) cp_waitg<NSTAGE - 2>();
        __syncthreads();

        const int p = t & (NSTAGE - 1);
        const int tn = t + NSTAGE - 1;
        if (tn < T) {
            const int pn = tn & (NSTAGE - 1);
            if (AM == 0) cp_stage(uA + pn * SLOTB, (const __half*)Ab, ldA, row0, tn * 32, tid);
            if (BM == 0) cp_stage(uB + pn * SLOTB, (const __half*)Bb, ldB, col0, tn * 32, tid);
        }
        if (ANY_CP) cp_commit();   // empty group at tail keeps FIFO accounting uniform

        if (AM != 0 && t + 1 < T) reg_load<AM>(ra, (const float*)Ab, ldA, row0, (t + 1) * 32, tid);
        if (BM != 0 && t + 1 < T) reg_load<BM>(rb, (const float*)Bb, ldB, col0, (t + 1) * 32, tid);

        compute_bk<AM, BM>(uA + p * SLOTB, uB + p * SLOTB, acc, lane, wm, wn);

        if (AM != 0 && t + 1 < T) reg_store<AM>(ra, bA + ((t + 1) & (NSTAGE - 1)) * SLOT, tid);
        if (BM != 0 && t + 1 < T) reg_store<BM>(rb, bB + ((t + 1) & (NSTAGE - 1)) * SLOT, tid);
    }

    // Epilogue
#pragma unroll
    for (int mb = 0; mb < 4; mb++) {
        const int m0 = row0 + wm + mb * 16 + (lane >> 2);
        const float rb0 = (BIAS == 1) ? bias[m0] : 0.f;
        const float rb1 = (BIAS == 1) ? bias[m0 + 8] : 0.f;
#pragma unroll
        for (int nb = 0; nb < 4; nb++) {
            const int n = col0 + wn + nb * 8 + 2 * (lane & 3);
            float cb0 = 0.f, cb1 = 0.f;
            if (BIAS == 2) { cb0 = bias[n]; cb1 = bias[n + 1]; }
            float v0 = acc[mb][nb][0] * scale + rb0 + cb0;
            float v1 = acc[mb][nb][1] * scale + rb0 + cb1;
            float v2 = acc[mb][nb][2] * scale + rb1 + cb0;
            float v3 = acc[mb][nb][3] * scale + rb1 + cb1;
            if (OUTH) {
                __half* Ch = (__half*)C + (size_t)b * sC;
                *reinterpret_cast<__half2*>(&Ch[(size_t)m0 * ldC + n])       = __floats2half2_rn(v0, v1);
                *reinterpret_cast<__half2*>(&Ch[(size_t)(m0 + 8) * ldC + n]) = __floats2half2_rn(v2, v3);
            } else {
                float* Cf = (float*)C + (size_t)b * sC;
                *reinterpret_cast<float2*>(&Cf[(size_t)m0 * ldC + n])       = make_float2(v0, v1);
                *reinterpret_cast<float2*>(&Cf[(size_t)(m0 + 8) * ldC + n]) = make_float2(v2, v3);
            }
        }
    }
}

// ---------------------------------------------------------------------------
// Row softmax: fp32 scores in, half probs out. 2304 = 256 x 9.
// ---------------------------------------------------------------------------
__global__ __launch_bounds__(256)
void softmax_kernel(const float* __restrict__ S, __half* __restrict__ P)
{
    const float* p = S + blockIdx.x * (size_t)NTOK;
    __half* o = P + blockIdx.x * (size_t)NTOK;
    const int t = threadIdx.x;
    __shared__ float red[256];

    float v[9];
    float m = -INFINITY;
#pragma unroll
    for (int j = 0; j < 9; j++) { v[j] = p[t + j * 256]; m = fmaxf(m, v[j]); }
    red[t] = m; __syncthreads();
    for (int s = 128; s > 0; s >>= 1) {
        if (t < s) red[t] = fmaxf(red[t], red[t + s]);
        __syncthreads();
    }
    m = red[0];
    __syncthreads();

    float sum = 0.f;
#pragma unroll
    for (int j = 0; j < 9; j++) { v[j] = __expf(v[j] - m); sum += v[j]; }
    red[t] = sum; __syncthreads();
    for (int s = 128; s > 0; s >>= 1) {
        if (t < s) red[t] += red[t + s];
        __syncthreads();
    }
    const float inv = 1.0f / red[0];
#pragma unroll
    for (int j = 0; j < 9; j++) o[t + j * 256] = __float2half_rn(v[j] * inv);
}

// ---------------------------------------------------------------------------
extern "C" void kernel_launch(void* const* d_in, const int* in_sizes, int n_in,
                              void* d_out, int out_size)
{
    const float* x  = (const float*)d_in[0];
    const float* Wq = (const float*)d_in[1];
    const float* bq = (const float*)d_in[2];
    const float* Wk = (const float*)d_in[3];
    const float* bk = (const float*)d_in[4];
    const float* Wv = (const float*)d_in[5];
    const float* bv = (const float*)d_in[6];
    const float* Wo = (const float*)d_in[7];
    const float* bo = (const float*)d_in[8];
    float* out = (float*)d_out;

    __half *q, *k, *vt, *p, *ao;
    float* s;
    cudaGetSymbolAddress((void**)&q,  g_q);
    cudaGetSymbolAddress((void**)&k,  g_k);
    cudaGetSymbolAddress((void**)&vt, g_vt);
    cudaGetSymbolAddress((void**)&p,  g_p);
    cudaGetSymbolAddress((void**)&ao, g_ao);
    cudaGetSymbolAddress((void**)&s,  g_s);

    cudaFuncSetAttribute(hgemm<2,1,1,2>, cudaFuncAttributeMaxDynamicSharedMemorySize, SMEM_BYTES);
    cudaFuncSetAttribute(hgemm<1,2,1,1>, cudaFuncAttributeMaxDynamicSharedMemorySize, SMEM_BYTES);
    cudaFuncSetAttribute(hgemm<0,0,0,0>, cudaFuncAttributeMaxDynamicSharedMemorySize, SMEM_BYTES);
    cudaFuncSetAttribute(hgemm<0,0,1,0>, cudaFuncAttributeMaxDynamicSharedMemorySize, SMEM_BYTES);
    cudaFuncSetAttribute(hgemm<1,0,0,1>, cudaFuncAttributeMaxDynamicSharedMemorySize, SMEM_BYTES);

    const dim3 blk(NTHREADS);
    const size_t sQKV = (size_t)NTOK * OCH;
    const size_t sS   = (size_t)NTOK * NTOK;
    const size_t sX   = (size_t)CIN * NTOK;
    const float scale = 0.044194173824159216f; // 1/sqrt(512)

    // 1) Q, K: [tok][och] = x^T W^T + b  (A = x f32-trans, B = W f32-NT, col bias)
    {
        dim3 g(OCH / 128, NTOK / 128, BATCH);
        hgemm<2,1,1,2><<<g, blk, SMEM_BYTES>>>(x, Wq, q, CIN, NTOK, CIN, OCH, sX, 0, sQKV, bq, 1.0f);
        hgemm<2,1,1,2><<<g, blk, SMEM_BYTES>>>(x, Wk, k, CIN, NTOK, CIN, OCH, sX, 0, sQKV, bk, 1.0f);
    }
    // 1b) V^T: [och][tok] = Wv x + bv   (A = Wv f32-NT, B = x f32-trans, row bias)
    {
        dim3 g(NTOK / 128, OCH / 128, BATCH);
        hgemm<1,2,1,1><<<g, blk, SMEM_BYTES>>>(Wv, x, vt, CIN, CIN, NTOK, NTOK, 0, sX, sQKV, bv, 1.0f);
    }
    // 2) S = scale * Q K^T  (fp32 out, cp.async 4-stage both operands)
    {
        dim3 g(NTOK / 128, NTOK / 128, BATCH);
        hgemm<0,0,0,0><<<g, blk, SMEM_BYTES>>>(q, k, s, OCH, OCH, OCH, NTOK, sQKV, sQKV, sS, nullptr, scale);
    }
    // 3) softmax -> half probs
    softmax_kernel<<<BATCH * NTOK, 256>>>(s, p);

    // 4) AO[tok][och] = P V  (A = P f16, B = V^T f16)
    {
        dim3 g(OCH / 128, NTOK / 128, BATCH);
        hgemm<0,0,1,0><<<g, blk, SMEM_BYTES>>>(p, vt, ao, NTOK, NTOK, NTOK, OCH, sS, sQKV, sQKV, nullptr, 1.0f);
    }
    // 5) out[och][tok] = Wo AO^T + bo  (A = Wo f32-NT, B = AO f16, fp32 out, row bias)
    {
        dim3 g(NTOK / 128, OCH / 128, BATCH);
        hgemm<1,0,0,1><<<g, blk, SMEM_BYTES>>>(Wo, ao, out, OCH, OCH, OCH, NTOK, 0, sQKV, (size_t)OCH * NTOK, bo, 1.0f);
    }
}

// round 8
// speedup vs baseline: 1.9565x; 1.0094x over previous
#include <cuda_runtime.h>
#include <cuda_fp16.h>
#include <math.h>
#include <stdint.h>

// Problem constants
#define BATCH 8
#define CIN   384
#define OCH   512
#define NTOK  2304   // 48*48

#define NTHREADS 128
// Block tile 128x128, K-tile = 32 halves, warp tile 64x64 (2x2 warps)
#define SNT 40     // NT smem tile row stride (halves): [128 r][40]
#define STR 136    // TR smem tile row stride (halves): [32 k][136]
#define SLOT 5120  // halves per stage slot (10240 B)
#define SLOTB 10240
#define NSTAGE 4
#define SMEM_BYTES (2 * NSTAGE * SLOTB)   // 81920

// Static scratch (no allocations allowed)
__device__ __half g_q [(size_t)BATCH * NTOK * OCH];   // [B][tok][och]
__device__ __half g_k [(size_t)BATCH * NTOK * OCH];   // [B][tok][och]
__device__ __half g_vt[(size_t)BATCH * OCH * NTOK];   // [B][och][tok]  (V transposed)
__device__ __half g_p [(size_t)BATCH * NTOK * NTOK];  // probs [B][tok][tok]
__device__ __half g_ao[(size_t)BATCH * NTOK * OCH];   // [B][tok][och]
__device__ float  g_s [(size_t)BATCH * NTOK * NTOK];  // scores fp32

// ---------------------------------------------------------------------------
// Helpers
// ---------------------------------------------------------------------------
__device__ __forceinline__ uint32_t smem_u32(const void* p) {
    uint32_t a;
    asm("{ .reg .u64 t; cvta.to.shared.u64 t, %1; cvt.u32.u64 %0, t; }" : "=r"(a) : "l"(p));
    return a;
}
__device__ __forceinline__ uint32_t pack_h2(float x, float y) {
    __half2 h = __floats2half2_rn(x, y);
    return *reinterpret_cast<uint32_t*>(&h);
}
__device__ __forceinline__ void ldsm4(uint32_t r[4], uint32_t addr) {
    asm volatile("ldmatrix.sync.aligned.m8n8.x4.shared.b16 {%0,%1,%2,%3}, [%4];"
                 : "=r"(r[0]), "=r"(r[1]), "=r"(r[2]), "=r"(r[3]) : "r"(addr));
}
__device__ __forceinline__ void ldsm4t(uint32_t r[4], uint32_t addr) {
    asm volatile("ldmatrix.sync.aligned.m8n8.x4.trans.shared.b16 {%0,%1,%2,%3}, [%4];"
                 : "=r"(r[0]), "=r"(r[1]), "=r"(r[2]), "=r"(r[3]) : "r"(addr));
}
__device__ __forceinline__ void mma16816(float c[4], const uint32_t a[4],
                                         uint32_t b0, uint32_t b1) {
    asm volatile(
        "mma.sync.aligned.m16n8k16.row.col.f32.f16.f16.f32 "
        "{%0,%1,%2,%3}, {%4,%5,%6,%7}, {%8,%9}, {%0,%1,%2,%3};"
        : "+f"(c[0]), "+f"(c[1]), "+f"(c[2]), "+f"(c[3])
        : "r"(a[0]), "r"(a[1]), "r"(a[2]), "r"(a[3]), "r"(b0), "r"(b1));
}
__device__ __forceinline__ void cp16(uint32_t saddr, const void* gaddr) {
    asm volatile("cp.async.cg.shared.global [%0], [%1], 16;" :: "r"(saddr), "l"(gaddr));
}
__device__ __forceinline__ void cp_commit() { asm volatile("cp.async.commit_group;"); }
template <int N>
__device__ __forceinline__ void cp_waitg() {
    asm volatile("cp.async.wait_group %0;" :: "n"(N) : "memory");
}

// ---------------------------------------------------------------------------
// f16 source: cp.async straight into NT tile [128][SNT]. 128 threads.
// ---------------------------------------------------------------------------
__device__ __forceinline__ void cp_stage(uint32_t sbase, const __half* __restrict__ S,
                                         int ld, int r0, int kt, int tid)
{
#pragma unroll
    for (int i = 0; i < 4; i++) {
        const int idx = tid + i * 128;
        const int r = idx >> 2, c8 = (idx & 3) * 8;
        cp16(sbase + (uint32_t)(r * SNT + c8) * 2, &S[(size_t)(r0 + r) * ld + kt + c8]);
    }
}

// ---------------------------------------------------------------------------
// f32 source staging (128 threads). MODE 1 = row-major [r][k]; 2 = transposed [k][r].
// ---------------------------------------------------------------------------
template <int MODE>
__device__ __forceinline__ void reg_load(uint4 R[8], const float* __restrict__ S,
                                         int ld, int r0, int kt, int tid)
{
#pragma unroll
    for (int i = 0; i < 8; i++) {
        const int idx = tid + i * 128;
        if (MODE == 1) {
            const int r = idx >> 3, c4 = (idx & 7) * 4;
            R[i] = *reinterpret_cast<const uint4*>(&S[(size_t)(r0 + r) * ld + kt + c4]);
        } else {
            const int k = idx >> 5, m4 = (idx & 31) * 4;
            R[i] = *reinterpret_cast<const uint4*>(&S[(size_t)(kt + k) * ld + r0 + m4]);
        }
    }
}

template <int MODE>
__device__ __forceinline__ void reg_store(const uint4 R[8], __half* tile, int tid)
{
#pragma unroll
    for (int i = 0; i < 8; i++) {
        const int idx = tid + i * 128;
        const float4 f = *reinterpret_cast<const float4*>(&R[i]);
        uint2 v; v.x = pack_h2(f.x, f.y); v.y = pack_h2(f.z, f.w);
        if (MODE == 1) {
            const int r = idx >> 3, c4 = (idx & 7) * 4;
            *reinterpret_cast<uint2*>(&tile[r * SNT + c4]) = v;
        } else {
            const int k = idx >> 5, m4 = (idx & 31) * 4;
            *reinterpret_cast<uint2*>(&tile[k * STR + m4]) = v;
        }
    }
}

// ---------------------------------------------------------------------------
// One 128x128x32 tile step. Warp tile 64x64 via m16n8k16 + ldmatrix.
// ---------------------------------------------------------------------------
template <int AM, int BM>
__device__ __forceinline__ void compute_bk(uint32_t sa, uint32_t sb,
                                           float acc[4][8][4], int lane, int wm, int wn)
{
    constexpr bool ATR = (AM == 2), BTR = (BM == 2);
#pragma unroll
    for (int ks = 0; ks < 32; ks += 16) {
        uint32_t a[4][4];
#pragma unroll
        for (int mb = 0; mb < 4; mb++) {
            if (!ATR) {
                const int row = wm + mb * 16 + (lane & 15);
                const int col = ks + ((lane >> 4) << 3);
                ldsm4(a[mb], sa + (uint32_t)(row * SNT + col) * 2);
            } else {
                const int k   = ks + (lane & 7) + ((lane & 16) >> 1);
                const int col = wm + mb * 16 + (lane & 8);
                ldsm4t(a[mb], sa + (uint32_t)(k * STR + col) * 2);
            }
        }
        uint32_t bfr[4][4];
#pragma unroll
        for (int nb2 = 0; nb2 < 4; nb2++) {
            if (!BTR) {
                const int row = wn + nb2 * 16 + (lane & 15);
                const int col = ks + ((lane >> 4) << 3);
                ldsm4(bfr[nb2], sb + (uint32_t)(row * SNT + col) * 2);
            } else {
                const int k   = ks + (lane & 7) + (lane & 8);
                const int col = wn + nb2 * 16 + ((lane & 16) >> 1);
                ldsm4t(bfr[nb2], sb + (uint32_t)(k * STR + col) * 2);
            }
        }
#pragma unroll
        for (int mb = 0; mb < 4; mb++)
#pragma unroll
            for (int nb = 0; nb < 8; nb++) {
                uint32_t b0, b1;
                if (!BTR) { b0 = bfr[nb >> 1][nb & 1];       b1 = bfr[nb >> 1][(nb & 1) + 2]; }
                else      { b0 = bfr[nb >> 1][2 * (nb & 1)]; b1 = bfr[nb >> 1][2 * (nb & 1) + 1]; }
                mma16816(acc[mb][nb], a[mb], b0, b1);
            }
    }
}

// ---------------------------------------------------------------------------
// Universal batched GEMM: C[m][n] = scale * sum_k opA(A)[m][k]*opB(B)[n][k] + bias
// AM/BM: 0 = f16 NT (cp.async 4-stage), 1 = f32 NT, 2 = f32 transposed.
// OUTH: 1 = half out. BIAS: 0 none, 1 row, 2 col.
// ---------------------------------------------------------------------------
template <int AM, int BM, int OUTH, int BIAS>
__global__ __launch_bounds__(NTHREADS, 2)
void hgemm(const void* __restrict__ A, const void* __restrict__ B, void* __restrict__ C,
           int K, int ldA, int ldB, int ldC,
           size_t sA, size_t sB, size_t sC,
           const float* __restrict__ bias, float scale)
{
    extern __shared__ __half dsm[];

    const int tid = threadIdx.x;
    const int warp = tid >> 5, lane = tid & 31;
    const int wm = (warp >> 1) * 64, wn = (warp & 1) * 64;
    const int b = blockIdx.z;
    const int row0 = blockIdx.y * 128;
    const int col0 = blockIdx.x * 128;

    const void* Ab = (AM == 0) ? (const void*)((const __half*)A + (size_t)b * sA)
                               : (const void*)((const float*)A + (size_t)b * sA);
    const void* Bb = (BM == 0) ? (const void*)((const __half*)B + (size_t)b * sB)
                               : (const void*)((const float*)B + (size_t)b * sB);
    constexpr bool ANY_CP = (AM == 0) || (BM == 0);

    const uint32_t uA = smem_u32(dsm);
    const uint32_t uB = uA + NSTAGE * SLOTB;
    __half* const bA = dsm;
    __half* const bB = dsm + NSTAGE * SLOT;

    float acc[4][8][4];
#pragma unroll
    for (int i = 0; i < 4; i++)
#pragma unroll
        for (int j = 0; j < 8; j++)
#pragma unroll
            for (int q = 0; q < 4; q++) acc[i][j][q] = 0.f;

    uint4 ra[8], rb[8];
    const int T = K / 32;

    // Prologue: cp operands fill stages 0..2; f32 operands fill stage 0.
#pragma unroll
    for (int s = 0; s < NSTAGE - 1; s++) {
        if (AM == 0) cp_stage(uA + s * SLOTB, (const __half*)Ab, ldA, row0, s * 32, tid);
        if (BM == 0) cp_stage(uB + s * SLOTB, (const __half*)Bb, ldB, col0, s * 32, tid);
        if (ANY_CP) cp_commit();
    }
    if (AM != 0) { reg_load<AM>(ra, (const float*)Ab, ldA, row0, 0, tid);
                   reg_store<AM>(ra, bA, tid); }
    if (BM != 0) { reg_load<BM>(rb, (const float*)Bb, ldB, col0, 0, tid);
                   reg_store<BM>(rb, bB, tid); }

    for (int t = 0; t < T; t++) {
        // Stage t must have landed; stages t+1, t+2 may stay in flight.
        if (ANY_CP) cp_waitg<NSTAGE - 2>();
        __syncthreads();

        const int p = t & (NSTAGE - 1);
        const int tn = t + NSTAGE - 1;
        if (tn < T) {
            const int pn = tn & (NSTAGE - 1);
            if (AM == 0) cp_stage(uA + pn * SLOTB, (const __half*)Ab, ldA, row0, tn * 32, tid);
            if (BM == 0) cp_stage(uB + pn * SLOTB, (const __half*)Bb, ldB, col0, tn * 32, tid);
        }
        if (ANY_CP) cp_commit();   // empty group at tail keeps FIFO accounting uniform

        if (AM != 0 && t + 1 < T) reg_load<AM>(ra, (const float*)Ab, ldA, row0, (t + 1) * 32, tid);
        if (BM != 0 && t + 1 < T) reg_load<BM>(rb, (const float*)Bb, ldB, col0, (t + 1) * 32, tid);

        compute_bk<AM, BM>(uA + p * SLOTB, uB + p * SLOTB, acc, lane, wm, wn);

        if (AM != 0 && t + 1 < T) reg_store<AM>(ra, bA + ((t + 1) & (NSTAGE - 1)) * SLOT, tid);
        if (BM != 0 && t + 1 < T) reg_store<BM>(rb, bB + ((t + 1) & (NSTAGE - 1)) * SLOT, tid);
    }

    // Epilogue
#pragma unroll
    for (int mb = 0; mb < 4; mb++) {
        const int m0 = row0 + wm + mb * 16 + (lane >> 2);
        const float rb0 = (BIAS == 1) ? bias[m0] : 0.f;
        const float rb1 = (BIAS == 1) ? bias[m0 + 8] : 0.f;
#pragma unroll
        for (int nb = 0; nb < 8; nb++) {
            const int n = col0 + wn + nb * 8 + 2 * (lane & 3);
            float cb0 = 0.f, cb1 = 0.f;
            if (BIAS == 2) { cb0 = bias[n]; cb1 = bias[n + 1]; }
            float v0 = acc[mb][nb][0] * scale + rb0 + cb0;
            float v1 = acc[mb][nb][1] * scale + rb0 + cb1;
            float v2 = acc[mb][nb][2] * scale + rb1 + cb0;
            float v3 = acc[mb][nb][3] * scale + rb1 + cb1;
            if (OUTH) {
                __half* Ch = (__half*)C + (size_t)b * sC;
                *reinterpret_cast<__half2*>(&Ch[(size_t)m0 * ldC + n])       = __floats2half2_rn(v0, v1);
                *reinterpret_cast<__half2*>(&Ch[(size_t)(m0 + 8) * ldC + n]) = __floats2half2_rn(v2, v3);
            } else {
                float* Cf = (float*)C + (size_t)b * sC;
                *reinterpret_cast<float2*>(&Cf[(size_t)m0 * ldC + n])       = make_float2(v0, v1);
                *reinterpret_cast<float2*>(&Cf[(size_t)(m0 + 8) * ldC + n]) = make_float2(v2, v3);
            }
        }
    }
}

// ---------------------------------------------------------------------------
// Row softmax: fp32 scores in, half probs out. 2304 = 256 x 9.
// ---------------------------------------------------------------------------
__global__ __launch_bounds__(256)
void softmax_kernel(const float* __restrict__ S, __half* __restrict__ P)
{
    const float* p = S + blockIdx.x * (size_t)NTOK;
    __half* o = P + blockIdx.x * (size_t)NTOK;
    const int t = threadIdx.x;
    __shared__ float red[256];

    float v[9];
    float m = -INFINITY;
#pragma unroll
    for (int j = 0; j < 9; j++) { v[j] = p[t + j * 256]; m = fmaxf(m, v[j]); }
    red[t] = m; __syncthreads();
    for (int s = 128; s > 0; s >>= 1) {
        if (t < s) red[t] = fmaxf(red[t], red[t + s]);
        __syncthreads();
    }
    m = red[0];
    __syncthreads();

    float sum = 0.f;
#pragma unroll
    for (int j = 0; j < 9; j++) { v[j] = __expf(v[j] - m); sum += v[j]; }
    red[t] = sum; __syncthreads();
    for (int s = 128; s > 0; s >>= 1) {
        if (t < s) red[t] += red[t + s];
        __syncthreads();
    }
    const float inv = 1.0f / red[0];
#pragma unroll
    for (int j = 0; j < 9; j++) o[t + j * 256] = __float2half_rn(v[j] * inv);
}

// ---------------------------------------------------------------------------
extern "C" void kernel_launch(void* const* d_in, const int* in_sizes, int n_in,
                              void* d_out, int out_size)
{
    const float* x  = (const float*)d_in[0];
    const float* Wq = (const float*)d_in[1];
    const float* bq = (const float*)d_in[2];
    const float* Wk = (const float*)d_in[3];
    const float* bk = (const float*)d_in[4];
    const float* Wv = (const float*)d_in[5];
    const float* bv = (const float*)d_in[6];
    const float* Wo = (const float*)d_in[7];
    const float* bo = (const float*)d_in[8];
    float* out = (float*)d_out;

    __half *q, *k, *vt, *p, *ao;
    float* s;
    cudaGetSymbolAddress((void**)&q,  g_q);
    cudaGetSymbolAddress((void**)&k,  g_k);
    cudaGetSymbolAddress((void**)&vt, g_vt);
    cudaGetSymbolAddress((void**)&p,  g_p);
    cudaGetSymbolAddress((void**)&ao, g_ao);
    cudaGetSymbolAddress((void**)&s,  g_s);

    cudaFuncSetAttribute(hgemm<2,1,1,2>, cudaFuncAttributeMaxDynamicSharedMemorySize, SMEM_BYTES);
    cudaFuncSetAttribute(hgemm<1,2,1,1>, cudaFuncAttributeMaxDynamicSharedMemorySize, SMEM_BYTES);
    cudaFuncSetAttribute(hgemm<0,0,0,0>, cudaFuncAttributeMaxDynamicSharedMemorySize, SMEM_BYTES);
    cudaFuncSetAttribute(hgemm<0,0,1,0>, cudaFuncAttributeMaxDynamicSharedMemorySize, SMEM_BYTES);
    cudaFuncSetAttribute(hgemm<1,0,0,1>, cudaFuncAttributeMaxDynamicSharedMemorySize, SMEM_BYTES);

    const dim3 blk(NTHREADS);
    const size_t sQKV = (size_t)NTOK * OCH;
    const size_t sS   = (size_t)NTOK * NTOK;
    const size_t sX   = (size_t)CIN * NTOK;
    const float scale = 0.044194173824159216f; // 1/sqrt(512)

    // 1) Q, K: [tok][och] = x^T W^T + b  (A = x f32-trans, B = W f32-NT, col bias)
    {
        dim3 g(OCH / 128, NTOK / 128, BATCH);
        hgemm<2,1,1,2><<<g, blk, SMEM_BYTES>>>(x, Wq, q, CIN, NTOK, CIN, OCH, sX, 0, sQKV, bq, 1.0f);
        hgemm<2,1,1,2><<<g, blk, SMEM_BYTES>>>(x, Wk, k, CIN, NTOK, CIN, OCH, sX, 0, sQKV, bk, 1.0f);
    }
    // 1b) V^T: [och][tok] = Wv x + bv   (A = Wv f32-NT, B = x f32-trans, row bias)
    {
        dim3 g(NTOK / 128, OCH / 128, BATCH);
        hgemm<1,2,1,1><<<g, blk, SMEM_BYTES>>>(Wv, x, vt, CIN, CIN, NTOK, NTOK, 0, sX, sQKV, bv, 1.0f);
    }
    // 2) S = scale * Q K^T  (fp32 out, cp.async 4-stage both operands)
    {
        dim3 g(NTOK / 128, NTOK / 128, BATCH);
        hgemm<0,0,0,0><<<g, blk, SMEM_BYTES>>>(q, k, s, OCH, OCH, OCH, NTOK, sQKV, sQKV, sS, nullptr, scale);
    }
    // 3) softmax -> half probs
    softmax_kernel<<<BATCH * NTOK, 256>>>(s, p);

    // 4) AO[tok][och] = P V  (A = P f16, B = V^T f16)
    {
        dim3 g(OCH / 128, NTOK / 128, BATCH);
        hgemm<0,0,1,0><<<g, blk, SMEM_BYTES>>>(p, vt, ao, NTOK, NTOK, NTOK, OCH, sS, sQKV, sQKV, nullptr, 1.0f);
    }
    // 5) out[och][tok] = Wo AO^T + bo  (A = Wo f32-NT, B = AO f16, fp32 out, row bias)
    {
        dim3 g(NTOK / 128, OCH / 128, BATCH);
        hgemm<1,0,0,1><<<g, blk, SMEM_BYTES>>>(Wo, ao, out, OCH, OCH, OCH, NTOK, 0, sQKV, (size_t)OCH * NTOK, bo, 1.0f);
    }
}

// round 9
// speedup vs baseline: 2.2897x; 1.1703x over previous
#include <cuda_runtime.h>
#include <cuda_fp16.h>
#include <math.h>
#include <stdint.h>

// Problem constants
#define BATCH 8
#define CIN   384
#define OCH   512
#define QKVN  1536   // 3*OCH packed
#define NTOK  2304   // 48*48

#define NTHREADS 128
// Block tile 128x128, K-tile = 32 halves, warp tile 64x64 (2x2 warps)
#define SNT 40     // NT smem tile row stride (halves): [128 r][40]
#define STR 136    // TR smem tile row stride (halves): [32 k][136]
#define SLOT 5120  // halves per stage slot (10240 B)
#define SLOTB 10240
#define NSTAGE 4
#define SMEM_BYTES (2 * NSTAGE * SLOTB)   // 81920

// Static scratch (no allocations allowed)
__device__ __half g_qkv[(size_t)BATCH * NTOK * QKVN];  // [B][tok][1536] : Q|K|V
__device__ __half g_p  [(size_t)BATCH * NTOK * NTOK];  // P' = exp(scores), half
__device__ __half g_ao [(size_t)BATCH * NTOK * OCH];   // [B][tok][och]
__device__ float  g_iz [(size_t)BATCH * NTOK];         // 1/rowsum(P')
__device__ float  g_wp [(size_t)QKVN * CIN];           // packed Wq;Wk;Wv
__device__ float  g_bp [QKVN];                          // packed bq;bk;bv

// ---------------------------------------------------------------------------
// Helpers
// ---------------------------------------------------------------------------
__device__ __forceinline__ uint32_t smem_u32(const void* p) {
    uint32_t a;
    asm("{ .reg .u64 t; cvta.to.shared.u64 t, %1; cvt.u32.u64 %0, t; }" : "=r"(a) : "l"(p));
    return a;
}
__device__ __forceinline__ uint32_t pack_h2(float x, float y) {
    __half2 h = __floats2half2_rn(x, y);
    return *reinterpret_cast<uint32_t*>(&h);
}
__device__ __forceinline__ void ldsm4(uint32_t r[4], uint32_t addr) {
    asm volatile("ldmatrix.sync.aligned.m8n8.x4.shared.b16 {%0,%1,%2,%3}, [%4];"
                 : "=r"(r[0]), "=r"(r[1]), "=r"(r[2]), "=r"(r[3]) : "r"(addr));
}
__device__ __forceinline__ void ldsm4t(uint32_t r[4], uint32_t addr) {
    asm volatile("ldmatrix.sync.aligned.m8n8.x4.trans.shared.b16 {%0,%1,%2,%3}, [%4];"
                 : "=r"(r[0]), "=r"(r[1]), "=r"(r[2]), "=r"(r[3]) : "r"(addr));
}
__device__ __forceinline__ void mma16816(float c[4], const uint32_t a[4],
                                         uint32_t b0, uint32_t b1) {
    asm volatile(
        "mma.sync.aligned.m16n8k16.row.col.f32.f16.f16.f32 "
        "{%0,%1,%2,%3}, {%4,%5,%6,%7}, {%8,%9}, {%0,%1,%2,%3};"
        : "+f"(c[0]), "+f"(c[1]), "+f"(c[2]), "+f"(c[3])
        : "r"(a[0]), "r"(a[1]), "r"(a[2]), "r"(a[3]), "r"(b0), "r"(b1));
}
__device__ __forceinline__ void cp16(uint32_t saddr, const void* gaddr) {
    asm volatile("cp.async.cg.shared.global [%0], [%1], 16;" :: "r"(saddr), "l"(gaddr));
}
__device__ __forceinline__ void cp_commit() { asm volatile("cp.async.commit_group;"); }
template <int N>
__device__ __forceinline__ void cp_waitg() {
    asm volatile("cp.async.wait_group %0;" :: "n"(N) : "memory");
}

// ---------------------------------------------------------------------------
// cp.async staging for half sources. TRT=0: NT tile [128][SNT] ([r][k] src).
// TRT=1: TR tile [32][STR] (src rows [k][r], r contiguous).
// ---------------------------------------------------------------------------
template <int TRT>
__device__ __forceinline__ void cp_stage(uint32_t sbase, const __half* __restrict__ S,
                                         int ld, int r0, int kt, int tid)
{
    if (TRT == 0) {
#pragma unroll
        for (int i = 0; i < 4; i++) {
            const int idx = tid + i * 128;
            const int r = idx >> 2, c8 = (idx & 3) * 8;
            cp16(sbase + (uint32_t)(r * SNT + c8) * 2, &S[(size_t)(r0 + r) * ld + kt + c8]);
        }
    } else {
#pragma unroll
        for (int i = 0; i < 4; i++) {
            const int idx = tid + i * 128;
            const int k = idx >> 4, c8 = (idx & 15) * 8;
            cp16(sbase + (uint32_t)(k * STR + c8) * 2, &S[(size_t)(kt + k) * ld + r0 + c8]);
        }
    }
}

// ---------------------------------------------------------------------------
// f32 source staging (128 threads). MODE 1 = row-major [r][k]; 2 = transposed [k][r].
// ---------------------------------------------------------------------------
template <int MODE>
__device__ __forceinline__ void reg_load(uint4 R[8], const float* __restrict__ S,
                                         int ld, int r0, int kt, int tid)
{
#pragma unroll
    for (int i = 0; i < 8; i++) {
        const int idx = tid + i * 128;
        if (MODE == 1) {
            const int r = idx >> 3, c4 = (idx & 7) * 4;
            R[i] = *reinterpret_cast<const uint4*>(&S[(size_t)(r0 + r) * ld + kt + c4]);
        } else {
            const int k = idx >> 5, m4 = (idx & 31) * 4;
            R[i] = *reinterpret_cast<const uint4*>(&S[(size_t)(kt + k) * ld + r0 + m4]);
        }
    }
}

template <int MODE>
__device__ __forceinline__ void reg_store(const uint4 R[8], __half* tile, int tid)
{
#pragma unroll
    for (int i = 0; i < 8; i++) {
        const int idx = tid + i * 128;
        const float4 f = *reinterpret_cast<const float4*>(&R[i]);
        uint2 v; v.x = pack_h2(f.x, f.y); v.y = pack_h2(f.z, f.w);
        if (MODE == 1) {
            const int r = idx >> 3, c4 = (idx & 7) * 4;
            *reinterpret_cast<uint2*>(&tile[r * SNT + c4]) = v;
        } else {
            const int k = idx >> 5, m4 = (idx & 31) * 4;
            *reinterpret_cast<uint2*>(&tile[k * STR + m4]) = v;
        }
    }
}

// ---------------------------------------------------------------------------
// One 128x128x32 tile step. Warp tile 64x64 via m16n8k16 + ldmatrix.
// TR modes (2 = f32 src, 3 = f16 src) share the [k][STR] tile + ldsm4t path.
// ---------------------------------------------------------------------------
template <int AM, int BM>
__device__ __forceinline__ void compute_bk(uint32_t sa, uint32_t sb,
                                           float acc[4][8][4], int lane, int wm, int wn)
{
    constexpr bool ATR = (AM >= 2), BTR = (BM >= 2);
#pragma unroll
    for (int ks = 0; ks < 32; ks += 16) {
        uint32_t a[4][4];
#pragma unroll
        for (int mb = 0; mb < 4; mb++) {
            if (!ATR) {
                const int row = wm + mb * 16 + (lane & 15);
                const int col = ks + ((lane >> 4) << 3);
                ldsm4(a[mb], sa + (uint32_t)(row * SNT + col) * 2);
            } else {
                const int k   = ks + (lane & 7) + ((lane & 16) >> 1);
                const int col = wm + mb * 16 + (lane & 8);
                ldsm4t(a[mb], sa + (uint32_t)(k * STR + col) * 2);
            }
        }
        uint32_t bfr[4][4];
#pragma unroll
        for (int nb2 = 0; nb2 < 4; nb2++) {
            if (!BTR) {
                const int row = wn + nb2 * 16 + (lane & 15);
                const int col = ks + ((lane >> 4) << 3);
                ldsm4(bfr[nb2], sb + (uint32_t)(row * SNT + col) * 2);
            } else {
                const int k   = ks + (lane & 7) + (lane & 8);
                const int col = wn + nb2 * 16 + ((lane & 16) >> 1);
                ldsm4t(bfr[nb2], sb + (uint32_t)(k * STR + col) * 2);
            }
        }
#pragma unroll
        for (int mb = 0; mb < 4; mb++)
#pragma unroll
            for (int nb = 0; nb < 8; nb++) {
                uint32_t b0, b1;
                if (!BTR) { b0 = bfr[nb >> 1][nb & 1];       b1 = bfr[nb >> 1][(nb & 1) + 2]; }
                else      { b0 = bfr[nb >> 1][2 * (nb & 1)]; b1 = bfr[nb >> 1][2 * (nb & 1) + 1]; }
                mma16816(acc[mb][nb], a[mb], b0, b1);
            }
    }
}

// ---------------------------------------------------------------------------
// Universal batched GEMM: C[m][n] = f(scale * sum_k opA(A)[m][k]*opB(B)[n][k])
// AM/BM: 0 = f16 NT cp.async, 1 = f32 NT, 2 = f32 TR, 3 = f16 TR cp.async.
// OUTH: 1 = half out. BIAS: 0 none, 1 row add, 2 col add, 3 row MULT (invZ).
// EXPM: 1 = apply __expf before bias/store (fused softmax numerator).
// ---------------------------------------------------------------------------
template <int AM, int BM, int OUTH, int BIAS, int EXPM>
__global__ __launch_bounds__(NTHREADS, 2)
void hgemm(const void* __restrict__ A, const void* __restrict__ B, void* __restrict__ C,
           int K, int ldA, int ldB, int ldC,
           size_t sA, size_t sB, size_t sC,
           const float* __restrict__ bias, size_t sBias, float scale)
{
    extern __shared__ __half dsm[];

    const int tid = threadIdx.x;
    const int warp = tid >> 5, lane = tid & 31;
    const int wm = (warp >> 1) * 64, wn = (warp & 1) * 64;
    const int b = blockIdx.z;
    const int row0 = blockIdx.y * 128;
    const int col0 = blockIdx.x * 128;

    constexpr bool A_CP = (AM == 0) || (AM == 3);
    constexpr bool B_CP = (BM == 0) || (BM == 3);
    constexpr bool ANY_CP = A_CP || B_CP;

    const void* Ab = A_CP ? (const void*)((const __half*)A + (size_t)b * sA)
                          : (const void*)((const float*)A + (size_t)b * sA);
    const void* Bb = B_CP ? (const void*)((const __half*)B + (size_t)b * sB)
                          : (const void*)((const float*)B + (size_t)b * sB);
    const float* biasb = bias + (size_t)b * sBias;

    const uint32_t uA = smem_u32(dsm);
    const uint32_t uB = uA + NSTAGE * SLOTB;
    __half* const bA = dsm;
    __half* const bB = dsm + NSTAGE * SLOT;

    float acc[4][8][4];
#pragma unroll
    for (int i = 0; i < 4; i++)
#pragma unroll
        for (int j = 0; j < 8; j++)
#pragma unroll
            for (int q = 0; q < 4; q++) acc[i][j][q] = 0.f;

    uint4 ra[8], rb[8];
    const int T = K / 32;

    // Prologue: cp operands fill stages 0..2; f32 operands fill stage 0.
#pragma unroll
    for (int s = 0; s < NSTAGE - 1; s++) {
        if (A_CP) cp_stage<(AM == 3)>(uA + s * SLOTB, (const __half*)Ab, ldA, row0, s * 32, tid);
        if (B_CP) cp_stage<(BM == 3)>(uB + s * SLOTB, (const __half*)Bb, ldB, col0, s * 32, tid);
        if (ANY_CP) cp_commit();
    }
    if (!A_CP) { reg_load<AM>(ra, (const float*)Ab, ldA, row0, 0, tid);
                 reg_store<AM>(ra, bA, tid); }
    if (!B_CP) { reg_load<BM>(rb, (const float*)Bb, ldB, col0, 0, tid);
                 reg_store<BM>(rb, bB, tid); }

    for (int t = 0; t < T; t++) {
        if (ANY_CP) cp_waitg<NSTAGE - 2>();
        __syncthreads();

        const int p = t & (NSTAGE - 1);
        const int tn = t + NSTAGE - 1;
        if (tn < T) {
            const int pn = tn & (NSTAGE - 1);
            if (A_CP) cp_stage<(AM == 3)>(uA + pn * SLOTB, (const __half*)Ab, ldA, row0, tn * 32, tid);
            if (B_CP) cp_stage<(BM == 3)>(uB + pn * SLOTB, (const __half*)Bb, ldB, col0, tn * 32, tid);
        }
        if (ANY_CP) cp_commit();

        if (!A_CP && t + 1 < T) reg_load<AM>(ra, (const float*)Ab, ldA, row0, (t + 1) * 32, tid);
        if (!B_CP && t + 1 < T) reg_load<BM>(rb, (const float*)Bb, ldB, col0, (t + 1) * 32, tid);

        compute_bk<AM, BM>(uA + p * SLOTB, uB + p * SLOTB, acc, lane, wm, wn);

        if (!A_CP && t + 1 < T) reg_store<AM>(ra, bA + ((t + 1) & (NSTAGE - 1)) * SLOT, tid);
        if (!B_CP && t + 1 < T) reg_store<BM>(rb, bB + ((t + 1) & (NSTAGE - 1)) * SLOT, tid);
    }

    // Epilogue
#pragma unroll
    for (int mb = 0; mb < 4; mb++) {
        const int m0 = row0 + wm + mb * 16 + (lane >> 2);
        const float rb0 = (BIAS == 1) ? biasb[m0] : 0.f;
        const float rb1 = (BIAS == 1) ? biasb[m0 + 8] : 0.f;
        const float rs0 = (BIAS == 3) ? biasb[m0] : 1.f;
        const float rs1 = (BIAS == 3) ? biasb[m0 + 8] : 1.f;
#pragma unroll
        for (int nb = 0; nb < 8; nb++) {
            const int n = col0 + wn + nb * 8 + 2 * (lane & 3);
            float cb0 = 0.f, cb1 = 0.f;
            if (BIAS == 2) { cb0 = biasb[n]; cb1 = biasb[n + 1]; }
            float v0 = acc[mb][nb][0] * scale;
            float v1 = acc[mb][nb][1] * scale;
            float v2 = acc[mb][nb][2] * scale;
            float v3 = acc[mb][nb][3] * scale;
            if (EXPM) { v0 = __expf(v0); v1 = __expf(v1); v2 = __expf(v2); v3 = __expf(v3); }
            if (BIAS == 1) { v0 += rb0; v1 += rb0; v2 += rb1; v3 += rb1; }
            if (BIAS == 2) { v0 += cb0; v1 += cb1; v2 += cb0; v3 += cb1; }
            if (BIAS == 3) { v0 *= rs0; v1 *= rs0; v2 *= rs1; v3 *= rs1; }
            if (OUTH) {
                __half* Ch = (__half*)C + (size_t)b * sC;
                *reinterpret_cast<__half2*>(&Ch[(size_t)m0 * ldC + n])       = __floats2half2_rn(v0, v1);
                *reinterpret_cast<__half2*>(&Ch[(size_t)(m0 + 8) * ldC + n]) = __floats2half2_rn(v2, v3);
            } else {
                float* Cf = (float*)C + (size_t)b * sC;
                *reinterpret_cast<float2*>(&Cf[(size_t)m0 * ldC + n])       = make_float2(v0, v1);
                *reinterpret_cast<float2*>(&Cf[(size_t)(m0 + 8) * ldC + n]) = make_float2(v2, v3);
            }
        }
    }
}

// ---------------------------------------------------------------------------
// Pack Wq/Wk/Wv and biases into contiguous buffers.
// ---------------------------------------------------------------------------
__global__ __launch_bounds__(256)
void pack_kernel(const float* __restrict__ Wq, const float* __restrict__ Wk,
                 const float* __restrict__ Wv, const float* __restrict__ bq,
                 const float* __restrict__ bk, const float* __restrict__ bv,
                 float* __restrict__ Wp, float* __restrict__ bp)
{
    const int i = blockIdx.x * 256 + threadIdx.x;
    const int per = OCH * CIN;
    if (i < 3 * per) {
        const float* src = (i < per) ? Wq : ((i < 2 * per) ? Wk : Wv);
        Wp[i] = src[i < per ? i : (i < 2 * per ? i - per : i - 2 * per)];
    }
    if (i < QKVN)
        bp[i] = (i < OCH) ? bq[i] : ((i < 2 * OCH) ? bk[i - OCH] : bv[i - 2 * OCH]);
}

// ---------------------------------------------------------------------------
// Row sums of P' -> invZ. One warp per row (2304 halves = 9 uint4 per lane).
// ---------------------------------------------------------------------------
__global__ __launch_bounds__(256)
void rowsum_kernel(const __half* __restrict__ P, float* __restrict__ invZ)
{
    const int warp = threadIdx.x >> 5, lane = threadIdx.x & 31;
    const size_t row = (size_t)blockIdx.x * 8 + warp;
    const uint4* pr = reinterpret_cast<const uint4*>(P + row * NTOK);
    float s = 0.f;
#pragma unroll
    for (int j = 0; j < 9; j++) {
        const uint4 u = pr[j * 32 + lane];
        const __half2* h = reinterpret_cast<const __half2*>(&u);
#pragma unroll
        for (int q = 0; q < 4; q++) {
            const float2 f = __half22float2(h[q]);
            s += f.x + f.y;
        }
    }
#pragma unroll
    for (int o = 16; o > 0; o >>= 1) s += __shfl_xor_sync(0xffffffff, s, o);
    if (lane == 0) invZ[row] = 1.0f / s;
}

// ---------------------------------------------------------------------------
extern "C" void kernel_launch(void* const* d_in, const int* in_sizes, int n_in,
                              void* d_out, int out_size)
{
    const float* x  = (const float*)d_in[0];
    const float* Wq = (const float*)d_in[1];
    const float* bq = (const float*)d_in[2];
    const float* Wk = (const float*)d_in[3];
    const float* bk = (const float*)d_in[4];
    const float* Wv = (const float*)d_in[5];
    const float* bv = (const float*)d_in[6];
    const float* Wo = (const float*)d_in[7];
    const float* bo = (const float*)d_in[8];
    float* out = (float*)d_out;

    __half *qkv, *p, *ao;
    float *iz, *wp, *bp;
    cudaGetSymbolAddress((void**)&qkv, g_qkv);
    cudaGetSymbolAddress((void**)&p,   g_p);
    cudaGetSymbolAddress((void**)&ao,  g_ao);
    cudaGetSymbolAddress((void**)&iz,  g_iz);
    cudaGetSymbolAddress((void**)&wp,  g_wp);
    cudaGetSymbolAddress((void**)&bp,  g_bp);

    cudaFuncSetAttribute(hgemm<2,1,1,2,0>, cudaFuncAttributeMaxDynamicSharedMemorySize, SMEM_BYTES);
    cudaFuncSetAttribute(hgemm<0,0,1,0,1>, cudaFuncAttributeMaxDynamicSharedMemorySize, SMEM_BYTES);
    cudaFuncSetAttribute(hgemm<0,3,1,3,0>, cudaFuncAttributeMaxDynamicSharedMemorySize, SMEM_BYTES);
    cudaFuncSetAttribute(hgemm<1,0,0,1,0>, cudaFuncAttributeMaxDynamicSharedMemorySize, SMEM_BYTES);

    const dim3 blk(NTHREADS);
    const size_t sQKV = (size_t)NTOK * QKVN;
    const size_t sS   = (size_t)NTOK * NTOK;
    const size_t sAO  = (size_t)NTOK * OCH;
    const size_t sX   = (size_t)CIN * NTOK;
    const float scale = 0.044194173824159216f; // 1/sqrt(512)

    // 0) pack weights/biases
    pack_kernel<<<(3 * OCH * CIN + 255) / 256, 256>>>(Wq, Wk, Wv, bq, bk, bv, wp, bp);

    // 1) QKV (one GEMM): qkv[tok][0:1536] = x^T Wp^T + bp
    {
        dim3 g(QKVN / 128, NTOK / 128, BATCH);
        hgemm<2,1,1,2,0><<<g, blk, SMEM_BYTES>>>(x, wp, qkv, CIN, NTOK, CIN, QKVN,
                                                 sX, 0, sQKV, bp, 0, 1.0f);
    }
    // 2) P' = exp(scale * Q K^T)  (half out, fused exp; no max-sub needed: |s| small)
    {
        dim3 g(NTOK / 128, NTOK / 128, BATCH);
        hgemm<0,0,1,0,1><<<g, blk, SMEM_BYTES>>>(qkv, qkv + OCH, p, OCH, QKVN, QKVN, NTOK,
                                                 sQKV, sQKV, sS, nullptr, 0, scale);
    }
    // 3) invZ = 1 / rowsum(P')
    rowsum_kernel<<<BATCH * NTOK / 8, 256>>>(p, iz);

    // 4) AO[tok][och] = (P' V) * invZ[tok]   (B = V half-TR mode)
    {
        dim3 g(OCH / 128, NTOK / 128, BATCH);
        hgemm<0,3,1,3,0><<<g, blk, SMEM_BYTES>>>(p, qkv + 2 * OCH, ao, NTOK, NTOK, QKVN, OCH,
                                                 sS, sQKV, sAO, iz, NTOK, 1.0f);
    }
    // 5) out[och][tok] = Wo AO^T + bo
    {
        dim3 g(NTOK / 128, OCH / 128, BATCH);
        hgemm<1,0,0,1,0><<<g, blk, SMEM_BYTES>>>(Wo, ao, out, OCH, OCH, OCH, NTOK,
                                                 0, sAO, (size_t)OCH * NTOK, bo, 0, 1.0f);
    }
}

// round 10
// speedup vs baseline: 2.3751x; 1.0373x over previous
#include <cuda_runtime.h>
#include <cuda_fp16.h>
#include <math.h>
#include <stdint.h>

// Problem constants
#define BATCH 8
#define CIN   384
#define OCH   512
#define QKVN  1536   // 3*OCH packed
#define NTOK  2304   // 48*48

#define NTHREADS 128
// Block tile 128x128, K-tile = 32 halves, warp tile 64x64 (2x2 warps)
#define SNT 40     // NT smem tile row stride (halves): [128 r][40]
#define STR 136    // TR smem tile row stride (halves): [32 k][136]
#define SLOT 5120  // halves per stage slot (10240 B)
#define SLOTB 10240
#define NSTAGE 4
#define SMEM_BYTES (2 * NSTAGE * SLOTB)   // 81920

// Static scratch (no allocations allowed)
__device__ __half g_qkv[(size_t)BATCH * NTOK * QKVN];  // [B][tok][1536] : Q|K|V
__device__ __half g_p  [(size_t)BATCH * NTOK * NTOK];  // P' = exp(scores), half
__device__ __half g_ao [(size_t)BATCH * NTOK * OCH];   // [B][tok][och]
__device__ __half g_xh [(size_t)BATCH * CIN * NTOK];   // x in half, [B][c][tok]
__device__ float  g_z  [(size_t)BATCH * NTOK];         // rowsum(P') via atomics
__device__ __half g_wph[(size_t)QKVN * CIN];           // packed Wq;Wk;Wv (half)
__device__ __half g_woh[(size_t)OCH * OCH];            // Wo (half)
__device__ float  g_bp [QKVN];                          // packed bq;bk;bv

// ---------------------------------------------------------------------------
// Helpers
// ---------------------------------------------------------------------------
__device__ __forceinline__ uint32_t smem_u32(const void* p) {
    uint32_t a;
    asm("{ .reg .u64 t; cvta.to.shared.u64 t, %1; cvt.u32.u64 %0, t; }" : "=r"(a) : "l"(p));
    return a;
}
__device__ __forceinline__ void ldsm4(uint32_t r[4], uint32_t addr) {
    asm volatile("ldmatrix.sync.aligned.m8n8.x4.shared.b16 {%0,%1,%2,%3}, [%4];"
                 : "=r"(r[0]), "=r"(r[1]), "=r"(r[2]), "=r"(r[3]) : "r"(addr));
}
__device__ __forceinline__ void ldsm4t(uint32_t r[4], uint32_t addr) {
    asm volatile("ldmatrix.sync.aligned.m8n8.x4.trans.shared.b16 {%0,%1,%2,%3}, [%4];"
                 : "=r"(r[0]), "=r"(r[1]), "=r"(r[2]), "=r"(r[3]) : "r"(addr));
}
__device__ __forceinline__ void mma16816(float c[4], const uint32_t a[4],
                                         uint32_t b0, uint32_t b1) {
    asm volatile(
        "mma.sync.aligned.m16n8k16.row.col.f32.f16.f16.f32 "
        "{%0,%1,%2,%3}, {%4,%5,%6,%7}, {%8,%9}, {%0,%1,%2,%3};"
        : "+f"(c[0]), "+f"(c[1]), "+f"(c[2]), "+f"(c[3])
        : "r"(a[0]), "r"(a[1]), "r"(a[2]), "r"(a[3]), "r"(b0), "r"(b1));
}
__device__ __forceinline__ void cp16(uint32_t saddr, const void* gaddr) {
    asm volatile("cp.async.cg.shared.global [%0], [%1], 16;" :: "r"(saddr), "l"(gaddr));
}
__device__ __forceinline__ void cp_commit() { asm volatile("cp.async.commit_group;"); }
template <int N>
__device__ __forceinline__ void cp_waitg() {
    asm volatile("cp.async.wait_group %0;" :: "n"(N) : "memory");
}

// ---------------------------------------------------------------------------
// cp.async staging. TRT=0: NT tile [128][SNT] from [r][k] src.
// TRT=1: TR tile [32][STR] from [k][r] src (r contiguous).
// ---------------------------------------------------------------------------
template <int TRT>
__device__ __forceinline__ void cp_stage(uint32_t sbase, const __half* __restrict__ S,
                                         int ld, int r0, int kt, int tid)
{
    if (TRT == 0) {
#pragma unroll
        for (int i = 0; i < 4; i++) {
            const int idx = tid + i * 128;
            const int r = idx >> 2, c8 = (idx & 3) * 8;
            cp16(sbase + (uint32_t)(r * SNT + c8) * 2, &S[(size_t)(r0 + r) * ld + kt + c8]);
        }
    } else {
#pragma unroll
        for (int i = 0; i < 4; i++) {
            const int idx = tid + i * 128;
            const int k = idx >> 4, c8 = (idx & 15) * 8;
            cp16(sbase + (uint32_t)(k * STR + c8) * 2, &S[(size_t)(kt + k) * ld + r0 + c8]);
        }
    }
}

// ---------------------------------------------------------------------------
// One 128x128x32 tile step. Warp tile 64x64 via m16n8k16 + ldmatrix.
// Mode: 0 = NT tile (ldsm4), 3 = TR tile (ldsm4t).
// ---------------------------------------------------------------------------
template <int AM, int BM>
__device__ __forceinline__ void compute_bk(uint32_t sa, uint32_t sb,
                                           float acc[4][8][4], int lane, int wm, int wn)
{
    constexpr bool ATR = (AM == 3), BTR = (BM == 3);
#pragma unroll
    for (int ks = 0; ks < 32; ks += 16) {
        uint32_t a[4][4];
#pragma unroll
        for (int mb = 0; mb < 4; mb++) {
            if (!ATR) {
                const int row = wm + mb * 16 + (lane & 15);
                const int col = ks + ((lane >> 4) << 3);
                ldsm4(a[mb], sa + (uint32_t)(row * SNT + col) * 2);
            } else {
                const int k   = ks + (lane & 7) + ((lane & 16) >> 1);
                const int col = wm + mb * 16 + (lane & 8);
                ldsm4t(a[mb], sa + (uint32_t)(k * STR + col) * 2);
            }
        }
        uint32_t bfr[4][4];
#pragma unroll
        for (int nb2 = 0; nb2 < 4; nb2++) {
            if (!BTR) {
                const int row = wn + nb2 * 16 + (lane & 15);
                const int col = ks + ((lane >> 4) << 3);
                ldsm4(bfr[nb2], sb + (uint32_t)(row * SNT + col) * 2);
            } else {
                const int k   = ks + (lane & 7) + (lane & 8);
                const int col = wn + nb2 * 16 + ((lane & 16) >> 1);
                ldsm4t(bfr[nb2], sb + (uint32_t)(k * STR + col) * 2);
            }
        }
#pragma unroll
        for (int mb = 0; mb < 4; mb++)
#pragma unroll
            for (int nb = 0; nb < 8; nb++) {
                uint32_t b0, b1;
                if (!BTR) { b0 = bfr[nb >> 1][nb & 1];       b1 = bfr[nb >> 1][(nb & 1) + 2]; }
                else      { b0 = bfr[nb >> 1][2 * (nb & 1)]; b1 = bfr[nb >> 1][2 * (nb & 1) + 1]; }
                mma16816(acc[mb][nb], a[mb], b0, b1);
            }
    }
}

// ---------------------------------------------------------------------------
// Universal batched all-f16 GEMM:
//   C[m][n] = f(scale * sum_k opA(A)[m][k]*opB(B)[n][k])
// AM/BM: 0 = f16 NT, 3 = f16 TR (both cp.async 4-stage).
// OUTH: 1 = half out. BIAS: 0 none, 1 row add, 2 col add, 3 row DIVIDE (by Z).
// EXPM: 1 = __expf before bias/store. SUMZ: 1 = atomic row sums into zsum.
// ---------------------------------------------------------------------------
template <int AM, int BM, int OUTH, int BIAS, int EXPM, int SUMZ>
__global__ __launch_bounds__(NTHREADS, 2)
void hgemm(const __half* __restrict__ A, const __half* __restrict__ B, void* __restrict__ C,
           int K, int ldA, int ldB, int ldC,
           size_t sA, size_t sB, size_t sC,
           const float* __restrict__ bias, float* __restrict__ zsum,
           size_t sBias, float scale)
{
    extern __shared__ __half dsm[];

    const int tid = threadIdx.x;
    const int warp = tid >> 5, lane = tid & 31;
    const int wm = (warp >> 1) * 64, wn = (warp & 1) * 64;
    const int b = blockIdx.z;
    const int row0 = blockIdx.y * 128;
    const int col0 = blockIdx.x * 128;

    const __half* Ab = A + (size_t)b * sA;
    const __half* Bb = B + (size_t)b * sB;
    const float* biasb = bias ? bias + (size_t)b * sBias : nullptr;
    float* zsumb = zsum ? zsum + (size_t)b * sBias : nullptr;

    const uint32_t uA = smem_u32(dsm);
    const uint32_t uB = uA + NSTAGE * SLOTB;

    float acc[4][8][4];
#pragma unroll
    for (int i = 0; i < 4; i++)
#pragma unroll
        for (int j = 0; j < 8; j++)
#pragma unroll
            for (int q = 0; q < 4; q++) acc[i][j][q] = 0.f;

    const int T = K / 32;

    // Prologue: fill stages 0..2
#pragma unroll
    for (int s = 0; s < NSTAGE - 1; s++) {
        cp_stage<(AM == 3)>(uA + s * SLOTB, Ab, ldA, row0, s * 32, tid);
        cp_stage<(BM == 3)>(uB + s * SLOTB, Bb, ldB, col0, s * 32, tid);
        cp_commit();
    }

    for (int t = 0; t < T; t++) {
        cp_waitg<NSTAGE - 2>();
        __syncthreads();

        const int p = t & (NSTAGE - 1);
        const int tn = t + NSTAGE - 1;
        if (tn < T) {
            const int pn = tn & (NSTAGE - 1);
            cp_stage<(AM == 3)>(uA + pn * SLOTB, Ab, ldA, row0, tn * 32, tid);
            cp_stage<(BM == 3)>(uB + pn * SLOTB, Bb, ldB, col0, tn * 32, tid);
        }
        cp_commit();   // empty group at tail keeps FIFO accounting uniform

        compute_bk<AM, BM>(uA + p * SLOTB, uB + p * SLOTB, acc, lane, wm, wn);
    }

    // Epilogue
#pragma unroll
    for (int mb = 0; mb < 4; mb++) {
        const int m0 = row0 + wm + mb * 16 + (lane >> 2);
        const float rb0 = (BIAS == 1) ? biasb[m0] : 0.f;
        const float rb1 = (BIAS == 1) ? biasb[m0 + 8] : 0.f;
        const float rs0 = (BIAS == 3) ? (1.0f / biasb[m0]) : 1.f;
        const float rs1 = (BIAS == 3) ? (1.0f / biasb[m0 + 8]) : 1.f;
        float s0 = 0.f, s1 = 0.f;
#pragma unroll
        for (int nb = 0; nb < 8; nb++) {
            const int n = col0 + wn + nb * 8 + 2 * (lane & 3);
            float cb0 = 0.f, cb1 = 0.f;
            if (BIAS == 2) { cb0 = biasb[n]; cb1 = biasb[n + 1]; }
            float v0 = acc[mb][nb][0] * scale;
            float v1 = acc[mb][nb][1] * scale;
            float v2 = acc[mb][nb][2] * scale;
            float v3 = acc[mb][nb][3] * scale;
            if (EXPM) { v0 = __expf(v0); v1 = __expf(v1); v2 = __expf(v2); v3 = __expf(v3); }
            if (BIAS == 1) { v0 += rb0; v1 += rb0; v2 += rb1; v3 += rb1; }
            if (BIAS == 2) { v0 += cb0; v1 += cb1; v2 += cb0; v3 += cb1; }
            if (BIAS == 3) { v0 *= rs0; v1 *= rs0; v2 *= rs1; v3 *= rs1; }
            if (SUMZ) { s0 += v0 + v1; s1 += v2 + v3; }
            if (OUTH) {
                __half* Ch = (__half*)C + (size_t)b * sC;
                *reinterpret_cast<__half2*>(&Ch[(size_t)m0 * ldC + n])       = __floats2half2_rn(v0, v1);
                *reinterpret_cast<__half2*>(&Ch[(size_t)(m0 + 8) * ldC + n]) = __floats2half2_rn(v2, v3);
            } else {
                float* Cf = (float*)C + (size_t)b * sC;
                *reinterpret_cast<float2*>(&Cf[(size_t)m0 * ldC + n])       = make_float2(v0, v1);
                *reinterpret_cast<float2*>(&Cf[(size_t)(m0 + 8) * ldC + n]) = make_float2(v2, v3);
            }
        }
        if (SUMZ) {
            s0 += __shfl_xor_sync(0xffffffffu, s0, 1);
            s0 += __shfl_xor_sync(0xffffffffu, s0, 2);
            s1 += __shfl_xor_sync(0xffffffffu, s1, 1);
            s1 += __shfl_xor_sync(0xffffffffu, s1, 2);
            if ((lane & 3) == 0) {
                atomicAdd(&zsumb[m0], s0);
                atomicAdd(&zsumb[m0 + 8], s1);
            }
        }
    }
}

// ---------------------------------------------------------------------------
// Pack Wq/Wk/Wv -> half, biases -> f32, Wo -> half, zero Z.
// ---------------------------------------------------------------------------
__global__ __launch_bounds__(256)
void pack_kernel(const float* __restrict__ Wq, const float* __restrict__ Wk,
                 const float* __restrict__ Wv, const float* __restrict__ bq,
                 const float* __restrict__ bk, const float* __restrict__ bv,
                 const float* __restrict__ Wo,
                 __half* __restrict__ Wp, __half* __restrict__ Woh,
                 float* __restrict__ bp, float* __restrict__ Z)
{
    const int i = blockIdx.x * 256 + threadIdx.x;
    const int per = OCH * CIN;
    if (i < 3 * per) {
        const float* src = (i < per) ? Wq : ((i < 2 * per) ? Wk : Wv);
        const int j = (i < per) ? i : ((i < 2 * per) ? i - per : i - 2 * per);
        Wp[i] = __float2half_rn(src[j]);
    }
    if (i < OCH * OCH) Woh[i] = __float2half_rn(Wo[i]);
    if (i < BATCH * NTOK) Z[i] = 0.f;
    if (i < QKVN)
        bp[i] = (i < OCH) ? bq[i] : ((i < 2 * OCH) ? bk[i - OCH] : bv[i - 2 * OCH]);
}

// ---------------------------------------------------------------------------
// Convert x (f32) -> half, same layout.
// ---------------------------------------------------------------------------
__global__ __launch_bounds__(256)
void xconv_kernel(const float* __restrict__ x, __half* __restrict__ xh)
{
    const size_t i = (size_t)blockIdx.x * 256 + threadIdx.x;
    const float4 f = reinterpret_cast<const float4*>(x)[i];
    __half2 h0 = __floats2half2_rn(f.x, f.y);
    __half2 h1 = __floats2half2_rn(f.z, f.w);
    uint2 v;
    v.x = *reinterpret_cast<uint32_t*>(&h0);
    v.y = *reinterpret_cast<uint32_t*>(&h1);
    reinterpret_cast<uint2*>(xh)[i] = v;
}

// ---------------------------------------------------------------------------
extern "C" void kernel_launch(void* const* d_in, const int* in_sizes, int n_in,
                              void* d_out, int out_size)
{
    const float* x  = (const float*)d_in[0];
    const float* Wq = (const float*)d_in[1];
    const float* bq = (const float*)d_in[2];
    const float* Wk = (const float*)d_in[3];
    const float* bk = (const float*)d_in[4];
    const float* Wv = (const float*)d_in[5];
    const float* bv = (const float*)d_in[6];
    const float* Wo = (const float*)d_in[7];
    const float* bo = (const float*)d_in[8];
    float* out = (float*)d_out;

    __half *qkv, *p, *ao, *xh, *wph, *woh;
    float *z, *bp;
    cudaGetSymbolAddress((void**)&qkv, g_qkv);
    cudaGetSymbolAddress((void**)&p,   g_p);
    cudaGetSymbolAddress((void**)&ao,  g_ao);
    cudaGetSymbolAddress((void**)&xh,  g_xh);
    cudaGetSymbolAddress((void**)&z,   g_z);
    cudaGetSymbolAddress((void**)&wph, g_wph);
    cudaGetSymbolAddress((void**)&woh, g_woh);
    cudaGetSymbolAddress((void**)&bp,  g_bp);

    cudaFuncSetAttribute(hgemm<3,0,1,2,0,0>, cudaFuncAttributeMaxDynamicSharedMemorySize, SMEM_BYTES);
    cudaFuncSetAttribute(hgemm<0,0,1,0,1,1>, cudaFuncAttributeMaxDynamicSharedMemorySize, SMEM_BYTES);
    cudaFuncSetAttribute(hgemm<0,3,1,3,0,0>, cudaFuncAttributeMaxDynamicSharedMemorySize, SMEM_BYTES);
    cudaFuncSetAttribute(hgemm<0,0,0,1,0,0>, cudaFuncAttributeMaxDynamicSharedMemorySize, SMEM_BYTES);

    const dim3 blk(NTHREADS);
    const size_t sQKV = (size_t)NTOK * QKVN;
    const size_t sS   = (size_t)NTOK * NTOK;
    const size_t sAO  = (size_t)NTOK * OCH;
    const size_t sX   = (size_t)CIN * NTOK;
    const float scale = 0.044194173824159216f; // 1/sqrt(512)

    // 0) pack weights/biases to half, zero Z; convert x to half
    pack_kernel<<<(3 * OCH * CIN + 255) / 256, 256>>>(Wq, Wk, Wv, bq, bk, bv, Wo,
                                                      wph, woh, bp, z);
    xconv_kernel<<<(int)((size_t)BATCH * CIN * NTOK / 4 / 256), 256>>>(x, xh);

    // 1) QKV (one GEMM): qkv[tok][0:1536] = x^T Wp^T + bp  (A = xh TR, B = wph NT)
    {
        dim3 g(QKVN / 128, NTOK / 128, BATCH);
        hgemm<3,0,1,2,0,0><<<g, blk, SMEM_BYTES>>>(xh, wph, qkv, CIN, NTOK, CIN, QKVN,
                                                   sX, 0, sQKV, bp, nullptr, 0, 1.0f);
    }
    // 2) P' = exp(scale * Q K^T) (half out, fused exp + atomic row sums into Z)
    {
        dim3 g(NTOK / 128, NTOK / 128, BATCH);
        hgemm<0,0,1,0,1,1><<<g, blk, SMEM_BYTES>>>(qkv, qkv + OCH, p, OCH, QKVN, QKVN, NTOK,
                                                   sQKV, sQKV, sS, nullptr, z, NTOK, scale);
    }
    // 3) AO[tok][och] = (P' V) / Z[tok]   (B = V half-TR)
    {
        dim3 g(OCH / 128, NTOK / 128, BATCH);
        hgemm<0,3,1,3,0,0><<<g, blk, SMEM_BYTES>>>(p, qkv + 2 * OCH, ao, NTOK, NTOK, QKVN, OCH,
                                                   sS, sQKV, sAO, z, nullptr, NTOK, 1.0f);
    }
    // 4) out[och][tok] = Wo AO^T + bo  (A = woh NT, B = AO NT)
    {
        dim3 g(NTOK / 128, OCH / 128, BATCH);
        hgemm<0,0,0,1,0,0><<<g, blk, SMEM_BYTES>>>(woh, ao, out, OCH, OCH, OCH, NTOK,
                                                   0, sAO, (size_t)OCH * NTOK, bo, nullptr, 0, 1.0f);
    }
}

// round 11
// speedup vs baseline: 2.4397x; 1.0272x over previous
#include <cuda_runtime.h>
#include <cuda_fp16.h>
#include <math.h>
#include <stdint.h>

// Problem constants
#define BATCH 8
#define CIN   384
#define OCH   512
#define NTOK  2304   // 48*48

#define NTHREADS 128
// Block tile 128x128, K-tile = 32 halves, warp tile 64x64 (2x2 warps)
#define SNT 40     // NT smem tile row stride (halves): [128 r][40]
#define STR 136    // TR smem tile row stride (halves): [32 k][136]
#define SLOT 5120  // halves per stage slot (10240 B)
#define SLOTB 10240
#define NSTAGE 4
#define SMEM_BYTES (2 * NSTAGE * SLOTB)   // 81920

// Static scratch (no allocations allowed)
__device__ __half g_xh [(size_t)BATCH * CIN * NTOK];   // x half, [B][c][tok]
__device__ __half g_yh [(size_t)BATCH * CIN * NTOK];   // Y = M*X, [B][c][tok]
__device__ __half g_vh [(size_t)BATCH * NTOK * OCH];   // V proj, [B][tok][och]
__device__ __half g_p  [(size_t)BATCH * NTOK * NTOK];  // P' = exp(scores), half
__device__ __half g_ao [(size_t)BATCH * NTOK * OCH];   // [B][tok][och]
__device__ float  g_z  [(size_t)BATCH * NTOK];         // rowsum(P') via atomics
__device__ float  g_rv [(size_t)BATCH * NTOK];         // v[n] + c0 (row bias of S)
__device__ float  g_cu [(size_t)BATCH * NTOK];         // u[m]      (col bias of S)
__device__ __half g_wqh[(size_t)OCH * CIN];            // Wq half
__device__ __half g_wkh[(size_t)OCH * CIN];            // Wk half
__device__ __half g_wvh[(size_t)OCH * CIN];            // Wv half
__device__ __half g_woh[(size_t)OCH * OCH];            // Wo half
__device__ __half g_mh [(size_t)CIN * CIN];            // M = Wq^T Wk (half)
__device__ float  g_wv [CIN];                           // Wq^T bk
__device__ float  g_wu [CIN];                           // Wk^T bq
__device__ float  g_c0 [1];                             // bq . bk

// ---------------------------------------------------------------------------
// Helpers
// ---------------------------------------------------------------------------
__device__ __forceinline__ uint32_t smem_u32(const void* p) {
    uint32_t a;
    asm("{ .reg .u64 t; cvta.to.shared.u64 t, %1; cvt.u32.u64 %0, t; }" : "=r"(a) : "l"(p));
    return a;
}
__device__ __forceinline__ void ldsm4(uint32_t r[4], uint32_t addr) {
    asm volatile("ldmatrix.sync.aligned.m8n8.x4.shared.b16 {%0,%1,%2,%3}, [%4];"
                 : "=r"(r[0]), "=r"(r[1]), "=r"(r[2]), "=r"(r[3]) : "r"(addr));
}
__device__ __forceinline__ void ldsm4t(uint32_t r[4], uint32_t addr) {
    asm volatile("ldmatrix.sync.aligned.m8n8.x4.trans.shared.b16 {%0,%1,%2,%3}, [%4];"
                 : "=r"(r[0]), "=r"(r[1]), "=r"(r[2]), "=r"(r[3]) : "r"(addr));
}
__device__ __forceinline__ void mma16816(float c[4], const uint32_t a[4],
                                         uint32_t b0, uint32_t b1) {
    asm volatile(
        "mma.sync.aligned.m16n8k16.row.col.f32.f16.f16.f32 "
        "{%0,%1,%2,%3}, {%4,%5,%6,%7}, {%8,%9}, {%0,%1,%2,%3};"
        : "+f"(c[0]), "+f"(c[1]), "+f"(c[2]), "+f"(c[3])
        : "r"(a[0]), "r"(a[1]), "r"(a[2]), "r"(a[3]), "r"(b0), "r"(b1));
}
__device__ __forceinline__ void cp16(uint32_t saddr, const void* gaddr) {
    asm volatile("cp.async.cg.shared.global [%0], [%1], 16;" :: "r"(saddr), "l"(gaddr));
}
__device__ __forceinline__ void cp_commit() { asm volatile("cp.async.commit_group;"); }
template <int N>
__device__ __forceinline__ void cp_waitg() {
    asm volatile("cp.async.wait_group %0;" :: "n"(N) : "memory");
}

// ---------------------------------------------------------------------------
// cp.async staging. TRT=0: NT tile [128][SNT] from [r][k] src.
// TRT=1: TR tile [32][STR] from [k][r] src (r contiguous).
// ---------------------------------------------------------------------------
template <int TRT>
__device__ __forceinline__ void cp_stage(uint32_t sbase, const __half* __restrict__ S,
                                         int ld, int r0, int kt, int tid)
{
    if (TRT == 0) {
#pragma unroll
        for (int i = 0; i < 4; i++) {
            const int idx = tid + i * 128;
            const int r = idx >> 2, c8 = (idx & 3) * 8;
            cp16(sbase + (uint32_t)(r * SNT + c8) * 2, &S[(size_t)(r0 + r) * ld + kt + c8]);
        }
    } else {
#pragma unroll
        for (int i = 0; i < 4; i++) {
            const int idx = tid + i * 128;
            const int k = idx >> 4, c8 = (idx & 15) * 8;
            cp16(sbase + (uint32_t)(k * STR + c8) * 2, &S[(size_t)(kt + k) * ld + r0 + c8]);
        }
    }
}

// ---------------------------------------------------------------------------
// One 128x128x32 tile step. Warp tile 64x64 via m16n8k16 + ldmatrix.
// Mode: 0 = NT tile (ldsm4), 3 = TR tile (ldsm4t).
// ---------------------------------------------------------------------------
template <int AM, int BM>
__device__ __forceinline__ void compute_bk(uint32_t sa, uint32_t sb,
                                           float acc[4][8][4], int lane, int wm, int wn)
{
    constexpr bool ATR = (AM == 3), BTR = (BM == 3);
#pragma unroll
    for (int ks = 0; ks < 32; ks += 16) {
        uint32_t a[4][4];
#pragma unroll
        for (int mb = 0; mb < 4; mb++) {
            if (!ATR) {
                const int row = wm + mb * 16 + (lane & 15);
                const int col = ks + ((lane >> 4) << 3);
                ldsm4(a[mb], sa + (uint32_t)(row * SNT + col) * 2);
            } else {
                const int k   = ks + (lane & 7) + ((lane & 16) >> 1);
                const int col = wm + mb * 16 + (lane & 8);
                ldsm4t(a[mb], sa + (uint32_t)(k * STR + col) * 2);
            }
        }
        uint32_t bfr[4][4];
#pragma unroll
        for (int nb2 = 0; nb2 < 4; nb2++) {
            if (!BTR) {
                const int row = wn + nb2 * 16 + (lane & 15);
                const int col = ks + ((lane >> 4) << 3);
                ldsm4(bfr[nb2], sb + (uint32_t)(row * SNT + col) * 2);
            } else {
                const int k   = ks + (lane & 7) + (lane & 8);
                const int col = wn + nb2 * 16 + ((lane & 16) >> 1);
                ldsm4t(bfr[nb2], sb + (uint32_t)(k * STR + col) * 2);
            }
        }
#pragma unroll
        for (int mb = 0; mb < 4; mb++)
#pragma unroll
            for (int nb = 0; nb < 8; nb++) {
                uint32_t b0, b1;
                if (!BTR) { b0 = bfr[nb >> 1][nb & 1];       b1 = bfr[nb >> 1][(nb & 1) + 2]; }
                else      { b0 = bfr[nb >> 1][2 * (nb & 1)]; b1 = bfr[nb >> 1][2 * (nb & 1) + 1]; }
                mma16816(acc[mb][nb], a[mb], b0, b1);
            }
    }
}

// ---------------------------------------------------------------------------
// Universal batched all-f16 GEMM:
//   C[m][n] = f((acc + biases) * scale)
// AM/BM: 0 = f16 NT, 3 = f16 TR (both cp.async 4-stage).
// OUTH: 1 = half out. BIAS: 0 none, 1 row add, 2 col add, 3 row DIVIDE (by Z),
//       4 row add (bias) + col add (bias2).
// EXPM: 1 = __expf after scale. SUMZ: 1 = atomic row sums into zsum.
// ---------------------------------------------------------------------------
template <int AM, int BM, int OUTH, int BIAS, int EXPM, int SUMZ>
__global__ __launch_bounds__(NTHREADS, 2)
void hgemm(const __half* __restrict__ A, const __half* __restrict__ B, void* __restrict__ C,
           int K, int ldA, int ldB, int ldC,
           size_t sA, size_t sB, size_t sC,
           const float* __restrict__ bias, const float* __restrict__ bias2,
           float* __restrict__ zsum, size_t sBias, float scale)
{
    extern __shared__ __half dsm[];

    const int tid = threadIdx.x;
    const int warp = tid >> 5, lane = tid & 31;
    const int wm = (warp >> 1) * 64, wn = (warp & 1) * 64;
    const int b = blockIdx.z;
    const int row0 = blockIdx.y * 128;
    const int col0 = blockIdx.x * 128;

    const __half* Ab = A + (size_t)b * sA;
    const __half* Bb = B + (size_t)b * sB;
    const float* biasb  = bias  ? bias  + (size_t)b * sBias : nullptr;
    const float* bias2b = bias2 ? bias2 + (size_t)b * sBias : nullptr;
    float* zsumb = zsum ? zsum + (size_t)b * sBias : nullptr;

    const uint32_t uA = smem_u32(dsm);
    const uint32_t uB = uA + NSTAGE * SLOTB;

    float acc[4][8][4];
#pragma unroll
    for (int i = 0; i < 4; i++)
#pragma unroll
        for (int j = 0; j < 8; j++)
#pragma unroll
            for (int q = 0; q < 4; q++) acc[i][j][q] = 0.f;

    const int T = K / 32;

    // Prologue: fill stages 0..2
#pragma unroll
    for (int s = 0; s < NSTAGE - 1; s++) {
        cp_stage<(AM == 3)>(uA + s * SLOTB, Ab, ldA, row0, s * 32, tid);
        cp_stage<(BM == 3)>(uB + s * SLOTB, Bb, ldB, col0, s * 32, tid);
        cp_commit();
    }

    for (int t = 0; t < T; t++) {
        cp_waitg<NSTAGE - 2>();
        __syncthreads();

        const int p = t & (NSTAGE - 1);
        const int tn = t + NSTAGE - 1;
        if (tn < T) {
            const int pn = tn & (NSTAGE - 1);
            cp_stage<(AM == 3)>(uA + pn * SLOTB, Ab, ldA, row0, tn * 32, tid);
            cp_stage<(BM == 3)>(uB + pn * SLOTB, Bb, ldB, col0, tn * 32, tid);
        }
        cp_commit();   // empty group at tail keeps FIFO accounting uniform

        compute_bk<AM, BM>(uA + p * SLOTB, uB + p * SLOTB, acc, lane, wm, wn);
    }

    // Epilogue
#pragma unroll
    for (int mb = 0; mb < 4; mb++) {
        const int m0 = row0 + wm + mb * 16 + (lane >> 2);
        const float ar0 = (BIAS == 1 || BIAS == 4) ? biasb[m0] : 0.f;
        const float ar1 = (BIAS == 1 || BIAS == 4) ? biasb[m0 + 8] : 0.f;
        const float rs0 = (BIAS == 3) ? (1.0f / biasb[m0]) : 1.f;
        const float rs1 = (BIAS == 3) ? (1.0f / biasb[m0 + 8]) : 1.f;
        float s0 = 0.f, s1 = 0.f;
#pragma unroll
        for (int nb = 0; nb < 8; nb++) {
            const int n = col0 + wn + nb * 8 + 2 * (lane & 3);
            float ac0 = 0.f, ac1 = 0.f;
            if (BIAS == 2) { ac0 = biasb[n]; ac1 = biasb[n + 1]; }
            if (BIAS == 4) { ac0 = bias2b[n]; ac1 = bias2b[n + 1]; }
            float v0 = (acc[mb][nb][0] + ar0 + ac0) * scale;
            float v1 = (acc[mb][nb][1] + ar0 + ac1) * scale;
            float v2 = (acc[mb][nb][2] + ar1 + ac0) * scale;
            float v3 = (acc[mb][nb][3] + ar1 + ac1) * scale;
            if (EXPM) { v0 = __expf(v0); v1 = __expf(v1); v2 = __expf(v2); v3 = __expf(v3); }
            if (BIAS == 3) { v0 *= rs0; v1 *= rs0; v2 *= rs1; v3 *= rs1; }
            if (SUMZ) { s0 += v0 + v1; s1 += v2 + v3; }
            if (OUTH) {
                __half* Ch = (__half*)C + (size_t)b * sC;
                *reinterpret_cast<__half2*>(&Ch[(size_t)m0 * ldC + n])       = __floats2half2_rn(v0, v1);
                *reinterpret_cast<__half2*>(&Ch[(size_t)(m0 + 8) * ldC + n]) = __floats2half2_rn(v2, v3);
            } else {
                float* Cf = (float*)C + (size_t)b * sC;
                *reinterpret_cast<float2*>(&Cf[(size_t)m0 * ldC + n])       = make_float2(v0, v1);
                *reinterpret_cast<float2*>(&Cf[(size_t)(m0 + 8) * ldC + n]) = make_float2(v2, v3);
            }
        }
        if (SUMZ) {
            s0 += __shfl_xor_sync(0xffffffffu, s0, 1);
            s0 += __shfl_xor_sync(0xffffffffu, s0, 2);
            s1 += __shfl_xor_sync(0xffffffffu, s1, 1);
            s1 += __shfl_xor_sync(0xffffffffu, s1, 2);
            if ((lane & 3) == 0) {
                atomicAdd(&zsumb[m0], s0);
                atomicAdd(&zsumb[m0 + 8], s1);
            }
        }
    }
}

// ---------------------------------------------------------------------------
// Pack weights -> half; zero Z.
// ---------------------------------------------------------------------------
__global__ __launch_bounds__(256)
void pack_kernel(const float* __restrict__ Wq, const float* __restrict__ Wk,
                 const float* __restrict__ Wv, const float* __restrict__ Wo,
                 __half* __restrict__ wqh, __half* __restrict__ wkh,
                 __half* __restrict__ wvh, __half* __restrict__ woh,
                 float* __restrict__ Z)
{
    const int i = blockIdx.x * 256 + threadIdx.x;
    if (i < OCH * CIN) {
        wqh[i] = __float2half_rn(Wq[i]);
        wkh[i] = __float2half_rn(Wk[i]);
        wvh[i] = __float2half_rn(Wv[i]);
    }
    if (i < OCH * OCH) woh[i] = __float2half_rn(Wo[i]);
    if (i < BATCH * NTOK) Z[i] = 0.f;
}

// ---------------------------------------------------------------------------
// Convert x (f32) -> half, same layout.
// ---------------------------------------------------------------------------
__global__ __launch_bounds__(256)
void xconv_kernel(const float* __restrict__ x, __half* __restrict__ xh)
{
    const size_t i = (size_t)blockIdx.x * 256 + threadIdx.x;
    const float4 f = reinterpret_cast<const float4*>(x)[i];
    __half2 h0 = __floats2half2_rn(f.x, f.y);
    __half2 h1 = __floats2half2_rn(f.z, f.w);
    uint2 v;
    v.x = *reinterpret_cast<uint32_t*>(&h0);
    v.y = *reinterpret_cast<uint32_t*>(&h1);
    reinterpret_cast<uint2*>(xh)[i] = v;
}

// ---------------------------------------------------------------------------
// w_v = Wq^T bk, w_u = Wk^T bq, c0 = bq.bk  (one block, 384 threads)
// ---------------------------------------------------------------------------
__global__ __launch_bounds__(384)
void uvw_kernel(const float* __restrict__ Wq, const float* __restrict__ Wk,
                const float* __restrict__ bq, const float* __restrict__ bk,
                float* __restrict__ wv, float* __restrict__ wu, float* __restrict__ c0)
{
    const int i = threadIdx.x;
    float sv = 0.f, su = 0.f;
    for (int o = 0; o < OCH; o++) {
        sv += Wq[o * CIN + i] * bk[o];
        su += Wk[o * CIN + i] * bq[o];
    }
    wv[i] = sv; wu[i] = su;

    __shared__ float red[256];
    if (i < 256) red[i] = bq[i] * bk[i] + bq[i + 256] * bk[i + 256];
    __syncthreads();
    for (int s = 128; s > 0; s >>= 1) {
        if (i < s) red[i] += red[i + s];
        __syncthreads();
    }
    if (i == 0) c0[0] = red[0];
}

// ---------------------------------------------------------------------------
// Per-token rank-1 terms: rv[b][n] = w_v . x_n + c0 ; cu[b][m] = w_u . x_m
// ---------------------------------------------------------------------------
__global__ __launch_bounds__(256)
void uv_kernel(const float* __restrict__ x, const float* __restrict__ wv,
               const float* __restrict__ wu, const float* __restrict__ c0,
               float* __restrict__ rv, float* __restrict__ cu)
{
    const int idx = blockIdx.x * 256 + threadIdx.x;
    const int b = idx / NTOK, n = idx % NTOK;
    const float* xb = x + (size_t)b * CIN * NTOK;
    float sv = 0.f, su = 0.f;
    for (int c = 0; c < CIN; c++) {
        const float xv = xb[(size_t)c * NTOK + n];
        sv += wv[c] * xv;
        su += wu[c] * xv;
    }
    rv[idx] = sv + c0[0];
    cu[idx] = su;
}

// ---------------------------------------------------------------------------
extern "C" void kernel_launch(void* const* d_in, const int* in_sizes, int n_in,
                              void* d_out, int out_size)
{
    const float* x  = (const float*)d_in[0];
    const float* Wq = (const float*)d_in[1];
    const float* bq = (const float*)d_in[2];
    const float* Wk = (const float*)d_in[3];
    const float* bk = (const float*)d_in[4];
    const float* Wv = (const float*)d_in[5];
    const float* bv = (const float*)d_in[6];
    const float* Wo = (const float*)d_in[7];
    const float* bo = (const float*)d_in[8];
    float* out = (float*)d_out;

    __half *xh, *yh, *vh, *p, *ao, *wqh, *wkh, *wvh, *woh, *mh;
    float *z, *rv, *cu, *wv, *wu, *c0;
    cudaGetSymbolAddress((void**)&xh,  g_xh);
    cudaGetSymbolAddress((void**)&yh,  g_yh);
    cudaGetSymbolAddress((void**)&vh,  g_vh);
    cudaGetSymbolAddress((void**)&p,   g_p);
    cudaGetSymbolAddress((void**)&ao,  g_ao);
    cudaGetSymbolAddress((void**)&z,   g_z);
    cudaGetSymbolAddress((void**)&rv,  g_rv);
    cudaGetSymbolAddress((void**)&cu,  g_cu);
    cudaGetSymbolAddress((void**)&wqh, g_wqh);
    cudaGetSymbolAddress((void**)&wkh, g_wkh);
    cudaGetSymbolAddress((void**)&wvh, g_wvh);
    cudaGetSymbolAddress((void**)&woh, g_woh);
    cudaGetSymbolAddress((void**)&mh,  g_mh);
    cudaGetSymbolAddress((void**)&wv,  g_wv);
    cudaGetSymbolAddress((void**)&wu,  g_wu);
    cudaGetSymbolAddress((void**)&c0,  g_c0);

    cudaFuncSetAttribute(hgemm<3,3,1,0,0,0>, cudaFuncAttributeMaxDynamicSharedMemorySize, SMEM_BYTES);
    cudaFuncSetAttribute(hgemm<3,0,1,2,0,0>, cudaFuncAttributeMaxDynamicSharedMemorySize, SMEM_BYTES);
    cudaFuncSetAttribute(hgemm<0,3,1,0,0,0>, cudaFuncAttributeMaxDynamicSharedMemorySize, SMEM_BYTES);
    cudaFuncSetAttribute(hgemm<3,3,1,4,1,1>, cudaFuncAttributeMaxDynamicSharedMemorySize, SMEM_BYTES);
    cudaFuncSetAttribute(hgemm<0,3,1,3,0,0>, cudaFuncAttributeMaxDynamicSharedMemorySize, SMEM_BYTES);
    cudaFuncSetAttribute(hgemm<0,0,0,1,0,0>, cudaFuncAttributeMaxDynamicSharedMemorySize, SMEM_BYTES);

    const dim3 blk(NTHREADS);
    const size_t sX  = (size_t)CIN * NTOK;
    const size_t sY  = (size_t)CIN * NTOK;
    const size_t sV  = (size_t)NTOK * OCH;
    const size_t sS  = (size_t)NTOK * NTOK;
    const size_t sAO = (size_t)NTOK * OCH;
    const float scale = 0.044194173824159216f; // 1/sqrt(512)

    // 0) weight packing, x conversion, rank-1 bias terms
    pack_kernel<<<(OCH * OCH + 255) / 256, 256>>>(Wq, Wk, Wv, Wo, wqh, wkh, wvh, woh, z);
    xconv_kernel<<<(int)((size_t)BATCH * CIN * NTOK / 4 / 256), 256>>>(x, xh);
    uvw_kernel<<<1, 384>>>(Wq, Wk, bq, bk, wv, wu, c0);
    uv_kernel<<<BATCH * NTOK / 256, 256>>>(x, wv, wu, c0, rv, cu);

    // 1) M = Wq^T Wk  (384x384, K=512; both operands TR)
    {
        dim3 g(CIN / 128, CIN / 128, 1);
        hgemm<3,3,1,0,0,0><<<g, blk, SMEM_BYTES>>>(wqh, wkh, mh, OCH, CIN, CIN, CIN,
                                                   0, 0, 0, nullptr, nullptr, nullptr, 0, 1.0f);
    }
    // 2) V[tok][och] = x^T Wv^T + bv  (A = xh TR, B = wvh NT, col bias)
    {
        dim3 g(OCH / 128, NTOK / 128, BATCH);
        hgemm<3,0,1,2,0,0><<<g, blk, SMEM_BYTES>>>(xh, wvh, vh, CIN, NTOK, CIN, OCH,
                                                   sX, 0, sV, bv, nullptr, nullptr, 0, 1.0f);
    }
    // 3) Y[c][tok] = M x   (A = mh NT, B = xh TR)
    {
        dim3 g(NTOK / 128, CIN / 128, BATCH);
        hgemm<0,3,1,0,0,0><<<g, blk, SMEM_BYTES>>>(mh, xh, yh, CIN, CIN, NTOK, NTOK,
                                                   0, sX, sY, nullptr, nullptr, nullptr, 0, 1.0f);
    }
    // 4) P' = exp(scale*(x^T Y + rv[n] + cu[m]))  (K=384, fused exp + atomic Z)
    {
        dim3 g(NTOK / 128, NTOK / 128, BATCH);
        hgemm<3,3,1,4,1,1><<<g, blk, SMEM_BYTES>>>(xh, yh, p, CIN, NTOK, NTOK, NTOK,
                                                   sX, sY, sS, rv, cu, z, NTOK, scale);
    }
    // 5) AO[tok][och] = (P' V) / Z[tok]   (B = vh TR)
    {
        dim3 g(OCH / 128, NTOK / 128, BATCH);
        hgemm<0,3,1,3,0,0><<<g, blk, SMEM_BYTES>>>(p, vh, ao, NTOK, NTOK, OCH, OCH,
                                                   sS, sV, sAO, z, nullptr, nullptr, NTOK, 1.0f);
    }
    // 6) out[och][tok] = Wo AO^T + bo
    {
        dim3 g(NTOK / 128, OCH / 128, BATCH);
        hgemm<0,0,0,1,0,0><<<g, blk, SMEM_BYTES>>>(woh, ao, out, OCH, OCH, OCH, NTOK,
                                                   0, sAO, (size_t)OCH * NTOK, bo, nullptr, nullptr, 0, 1.0f);
    }
}

// round 12
// speedup vs baseline: 2.8127x; 1.1529x over previous
#include <cuda_runtime.h>
#include <cuda_fp16.h>
#include <math.h>
#include <stdint.h>

// Problem constants
#define BATCH 8
#define CIN   384
#define OCH   512
#define NTOK  2304   // 48*48

#define NTHREADS 128
// Block tile 128x128, K-tile = 32 halves, warp tile 64x64 (2x2 warps)
#define SNT 40     // NT smem tile row stride (halves): [128 r][40]
#define STR 136    // TR smem tile row stride (halves): [32 k][136]
#define SLOT 5120  // halves per stage slot (10240 B)
#define SLOTB 10240
#define NSTAGE 4
#define SMEM_BYTES (2 * NSTAGE * SLOTB)   // 81920

// Static scratch (no allocations allowed)
__device__ __half g_xh [(size_t)BATCH * CIN * NTOK];   // x half, [B][c][tok]
__device__ __half g_yh [(size_t)BATCH * CIN * NTOK];   // Y = M*X, [B][c][tok]
__device__ __half g_vh [(size_t)BATCH * NTOK * OCH];   // V proj, [B][tok][och]
__device__ __half g_p  [(size_t)BATCH * NTOK * NTOK];  // P' = exp(scores), half
__device__ __half g_ao [(size_t)BATCH * NTOK * OCH];   // [B][tok][och]
__device__ float  g_z  [(size_t)BATCH * NTOK];         // rowsum(P') via atomics
__device__ float  g_rv [(size_t)BATCH * NTOK];         // v[n] + c0 (row bias of S)
__device__ float  g_cu [(size_t)BATCH * NTOK];         // u[m]      (col bias of S)
__device__ __half g_wqh[(size_t)OCH * CIN];            // Wq half
__device__ __half g_wkh[(size_t)OCH * CIN];            // Wk half
__device__ __half g_wvh[(size_t)OCH * CIN];            // Wv half
__device__ __half g_woh[(size_t)OCH * OCH];            // Wo half
__device__ __half g_mh [(size_t)CIN * CIN];            // M = Wq^T Wk (half)
__device__ float  g_wv [CIN];                           // Wq^T bk
__device__ float  g_wu [CIN];                           // Wk^T bq
__device__ float  g_c0 [1];                             // bq . bk

// ---------------------------------------------------------------------------
// Helpers
// ---------------------------------------------------------------------------
__device__ __forceinline__ uint32_t smem_u32(const void* p) {
    uint32_t a;
    asm("{ .reg .u64 t; cvta.to.shared.u64 t, %1; cvt.u32.u64 %0, t; }" : "=r"(a) : "l"(p));
    return a;
}
__device__ __forceinline__ void ldsm4(uint32_t r[4], uint32_t addr) {
    asm volatile("ldmatrix.sync.aligned.m8n8.x4.shared.b16 {%0,%1,%2,%3}, [%4];"
                 : "=r"(r[0]), "=r"(r[1]), "=r"(r[2]), "=r"(r[3]) : "r"(addr));
}
__device__ __forceinline__ void ldsm4t(uint32_t r[4], uint32_t addr) {
    asm volatile("ldmatrix.sync.aligned.m8n8.x4.trans.shared.b16 {%0,%1,%2,%3}, [%4];"
                 : "=r"(r[0]), "=r"(r[1]), "=r"(r[2]), "=r"(r[3]) : "r"(addr));
}
__device__ __forceinline__ void mma16816(float c[4], const uint32_t a[4],
                                         uint32_t b0, uint32_t b1) {
    asm volatile(
        "mma.sync.aligned.m16n8k16.row.col.f32.f16.f16.f32 "
        "{%0,%1,%2,%3}, {%4,%5,%6,%7}, {%8,%9}, {%0,%1,%2,%3};"
        : "+f"(c[0]), "+f"(c[1]), "+f"(c[2]), "+f"(c[3])
        : "r"(a[0]), "r"(a[1]), "r"(a[2]), "r"(a[3]), "r"(b0), "r"(b1));
}
__device__ __forceinline__ void cp16(uint32_t saddr, const void* gaddr) {
    asm volatile("cp.async.cg.shared.global [%0], [%1], 16;" :: "r"(saddr), "l"(gaddr));
}
__device__ __forceinline__ void cp_commit() { asm volatile("cp.async.commit_group;"); }
template <int N>
__device__ __forceinline__ void cp_waitg() {
    asm volatile("cp.async.wait_group %0;" :: "n"(N) : "memory");
}

// ---------------------------------------------------------------------------
// cp.async staging. TRT=0: NT tile [128][SNT] from [r][k] src.
// TRT=1: TR tile [32][STR] from [k][r] src (r contiguous).
// ---------------------------------------------------------------------------
template <int TRT>
__device__ __forceinline__ void cp_stage(uint32_t sbase, const __half* __restrict__ S,
                                         int ld, int r0, int kt, int tid)
{
    if (TRT == 0) {
#pragma unroll
        for (int i = 0; i < 4; i++) {
            const int idx = tid + i * 128;
            const int r = idx >> 2, c8 = (idx & 3) * 8;
            cp16(sbase + (uint32_t)(r * SNT + c8) * 2, &S[(size_t)(r0 + r) * ld + kt + c8]);
        }
    } else {
#pragma unroll
        for (int i = 0; i < 4; i++) {
            const int idx = tid + i * 128;
            const int k = idx >> 4, c8 = (idx & 15) * 8;
            cp16(sbase + (uint32_t)(k * STR + c8) * 2, &S[(size_t)(kt + k) * ld + r0 + c8]);
        }
    }
}

// ---------------------------------------------------------------------------
// One 128x128x32 tile step. Warp tile 64x64 via m16n8k16 + ldmatrix.
// Mode: 0 = NT tile (ldsm4), 3 = TR tile (ldsm4t).
// ---------------------------------------------------------------------------
template <int AM, int BM>
__device__ __forceinline__ void compute_bk(uint32_t sa, uint32_t sb,
                                           float acc[4][8][4], int lane, int wm, int wn)
{
    constexpr bool ATR = (AM == 3), BTR = (BM == 3);
#pragma unroll
    for (int ks = 0; ks < 32; ks += 16) {
        uint32_t a[4][4];
#pragma unroll
        for (int mb = 0; mb < 4; mb++) {
            if (!ATR) {
                const int row = wm + mb * 16 + (lane & 15);
                const int col = ks + ((lane >> 4) << 3);
                ldsm4(a[mb], sa + (uint32_t)(row * SNT + col) * 2);
            } else {
                const int k   = ks + (lane & 7) + ((lane & 16) >> 1);
                const int col = wm + mb * 16 + (lane & 8);
                ldsm4t(a[mb], sa + (uint32_t)(k * STR + col) * 2);
            }
        }
        uint32_t bfr[4][4];
#pragma unroll
        for (int nb2 = 0; nb2 < 4; nb2++) {
            if (!BTR) {
                const int row = wn + nb2 * 16 + (lane & 15);
                const int col = ks + ((lane >> 4) << 3);
                ldsm4(bfr[nb2], sb + (uint32_t)(row * SNT + col) * 2);
            } else {
                const int k   = ks + (lane & 7) + (lane & 8);
                const int col = wn + nb2 * 16 + ((lane & 16) >> 1);
                ldsm4t(bfr[nb2], sb + (uint32_t)(k * STR + col) * 2);
            }
        }
#pragma unroll
        for (int mb = 0; mb < 4; mb++)
#pragma unroll
            for (int nb = 0; nb < 8; nb++) {
                uint32_t b0, b1;
                if (!BTR) { b0 = bfr[nb >> 1][nb & 1];       b1 = bfr[nb >> 1][(nb & 1) + 2]; }
                else      { b0 = bfr[nb >> 1][2 * (nb & 1)]; b1 = bfr[nb >> 1][2 * (nb & 1) + 1]; }
                mma16816(acc[mb][nb], a[mb], b0, b1);
            }
    }
}

// ---------------------------------------------------------------------------
// Universal batched all-f16 GEMM:
//   C[m][n] = f((acc + biases) * scale)
// AM/BM: 0 = f16 NT, 3 = f16 TR (both cp.async 4-stage).
// OUTH: 1 = half out. BIAS: 0 none, 1 row add, 2 col add, 3 row DIVIDE (by Z),
//       4 row add (bias) + col add (bias2).
// EXPM: 1 = __expf after scale. SUMZ: 1 = atomic row sums into zsum.
// ---------------------------------------------------------------------------
template <int AM, int BM, int OUTH, int BIAS, int EXPM, int SUMZ>
__global__ __launch_bounds__(NTHREADS, 2)
void hgemm(const __half* __restrict__ A, const __half* __restrict__ B, void* __restrict__ C,
           int K, int ldA, int ldB, int ldC,
           size_t sA, size_t sB, size_t sC,
           const float* __restrict__ bias, const float* __restrict__ bias2,
           float* __restrict__ zsum, size_t sBias, float scale)
{
    extern __shared__ __half dsm[];

    const int tid = threadIdx.x;
    const int warp = tid >> 5, lane = tid & 31;
    const int wm = (warp >> 1) * 64, wn = (warp & 1) * 64;
    const int b = blockIdx.z;
    const int row0 = blockIdx.y * 128;
    const int col0 = blockIdx.x * 128;

    const __half* Ab = A + (size_t)b * sA;
    const __half* Bb = B + (size_t)b * sB;
    const float* biasb  = bias  ? bias  + (size_t)b * sBias : nullptr;
    const float* bias2b = bias2 ? bias2 + (size_t)b * sBias : nullptr;
    float* zsumb = zsum ? zsum + (size_t)b * sBias : nullptr;

    const uint32_t uA = smem_u32(dsm);
    const uint32_t uB = uA + NSTAGE * SLOTB;

    float acc[4][8][4];
#pragma unroll
    for (int i = 0; i < 4; i++)
#pragma unroll
        for (int j = 0; j < 8; j++)
#pragma unroll
            for (int q = 0; q < 4; q++) acc[i][j][q] = 0.f;

    const int T = K / 32;

    // Prologue: fill stages 0..2
#pragma unroll
    for (int s = 0; s < NSTAGE - 1; s++) {
        cp_stage<(AM == 3)>(uA + s * SLOTB, Ab, ldA, row0, s * 32, tid);
        cp_stage<(BM == 3)>(uB + s * SLOTB, Bb, ldB, col0, s * 32, tid);
        cp_commit();
    }

    for (int t = 0; t < T; t++) {
        cp_waitg<NSTAGE - 2>();
        __syncthreads();

        const int p = t & (NSTAGE - 1);
        const int tn = t + NSTAGE - 1;
        if (tn < T) {
            const int pn = tn & (NSTAGE - 1);
            cp_stage<(AM == 3)>(uA + pn * SLOTB, Ab, ldA, row0, tn * 32, tid);
            cp_stage<(BM == 3)>(uB + pn * SLOTB, Bb, ldB, col0, tn * 32, tid);
        }
        cp_commit();   // empty group at tail keeps FIFO accounting uniform

        compute_bk<AM, BM>(uA + p * SLOTB, uB + p * SLOTB, acc, lane, wm, wn);
    }

    // Epilogue
#pragma unroll
    for (int mb = 0; mb < 4; mb++) {
        const int m0 = row0 + wm + mb * 16 + (lane >> 2);
        const float ar0 = (BIAS == 1 || BIAS == 4) ? biasb[m0] : 0.f;
        const float ar1 = (BIAS == 1 || BIAS == 4) ? biasb[m0 + 8] : 0.f;
        const float rs0 = (BIAS == 3) ? (1.0f / biasb[m0]) : 1.f;
        const float rs1 = (BIAS == 3) ? (1.0f / biasb[m0 + 8]) : 1.f;
        float s0 = 0.f, s1 = 0.f;
#pragma unroll
        for (int nb = 0; nb < 8; nb++) {
            const int n = col0 + wn + nb * 8 + 2 * (lane & 3);
            float ac0 = 0.f, ac1 = 0.f;
            if (BIAS == 2) { ac0 = biasb[n]; ac1 = biasb[n + 1]; }
            if (BIAS == 4) { ac0 = bias2b[n]; ac1 = bias2b[n + 1]; }
            float v0 = (acc[mb][nb][0] + ar0 + ac0) * scale;
            float v1 = (acc[mb][nb][1] + ar0 + ac1) * scale;
            float v2 = (acc[mb][nb][2] + ar1 + ac0) * scale;
            float v3 = (acc[mb][nb][3] + ar1 + ac1) * scale;
            if (EXPM) { v0 = __expf(v0); v1 = __expf(v1); v2 = __expf(v2); v3 = __expf(v3); }
            if (BIAS == 3) { v0 *= rs0; v1 *= rs0; v2 *= rs1; v3 *= rs1; }
            if (SUMZ) { s0 += v0 + v1; s1 += v2 + v3; }
            if (OUTH) {
                __half* Ch = (__half*)C + (size_t)b * sC;
                *reinterpret_cast<__half2*>(&Ch[(size_t)m0 * ldC + n])       = __floats2half2_rn(v0, v1);
                *reinterpret_cast<__half2*>(&Ch[(size_t)(m0 + 8) * ldC + n]) = __floats2half2_rn(v2, v3);
            } else {
                float* Cf = (float*)C + (size_t)b * sC;
                *reinterpret_cast<float2*>(&Cf[(size_t)m0 * ldC + n])       = make_float2(v0, v1);
                *reinterpret_cast<float2*>(&Cf[(size_t)(m0 + 8) * ldC + n]) = make_float2(v2, v3);
            }
        }
        if (SUMZ) {
            s0 += __shfl_xor_sync(0xffffffffu, s0, 1);
            s0 += __shfl_xor_sync(0xffffffffu, s0, 2);
            s1 += __shfl_xor_sync(0xffffffffu, s1, 1);
            s1 += __shfl_xor_sync(0xffffffffu, s1, 2);
            if ((lane & 3) == 0) {
                atomicAdd(&zsumb[m0], s0);
                atomicAdd(&zsumb[m0 + 8], s1);
            }
        }
    }
}

// ---------------------------------------------------------------------------
// Pack weights -> half; zero Z.
// ---------------------------------------------------------------------------
__global__ __launch_bounds__(256)
void pack_kernel(const float* __restrict__ Wq, const float* __restrict__ Wk,
                 const float* __restrict__ Wv, const float* __restrict__ Wo,
                 __half* __restrict__ wqh, __half* __restrict__ wkh,
                 __half* __restrict__ wvh, __half* __restrict__ woh,
                 float* __restrict__ Z)
{
    const int i = blockIdx.x * 256 + threadIdx.x;
    if (i < OCH * CIN) {
        wqh[i] = __float2half_rn(Wq[i]);
        wkh[i] = __float2half_rn(Wk[i]);
        wvh[i] = __float2half_rn(Wv[i]);
    }
    if (i < OCH * OCH) woh[i] = __float2half_rn(Wo[i]);
    if (i < BATCH * NTOK) Z[i] = 0.f;
}

// ---------------------------------------------------------------------------
// Convert x (f32) -> half, same layout.
// ---------------------------------------------------------------------------
__global__ __launch_bounds__(256)
void xconv_kernel(const float* __restrict__ x, __half* __restrict__ xh)
{
    const size_t i = (size_t)blockIdx.x * 256 + threadIdx.x;
    const float4 f = reinterpret_cast<const float4*>(x)[i];
    __half2 h0 = __floats2half2_rn(f.x, f.y);
    __half2 h1 = __floats2half2_rn(f.z, f.w);
    uint2 v;
    v.x = *reinterpret_cast<uint32_t*>(&h0);
    v.y = *reinterpret_cast<uint32_t*>(&h1);
    reinterpret_cast<uint2*>(xh)[i] = v;
}

// ---------------------------------------------------------------------------
// w_v = Wq^T bk, w_u = Wk^T bq, c0 = bq.bk
// grid = 3 blocks x 512 threads: 128 i-columns per block, 4 o-groups of 128.
// ---------------------------------------------------------------------------
__global__ __launch_bounds__(512)
void uvw_kernel(const float* __restrict__ Wq, const float* __restrict__ Wk,
                const float* __restrict__ bq, const float* __restrict__ bk,
                float* __restrict__ wv, float* __restrict__ wu, float* __restrict__ c0)
{
    __shared__ float sv[4][128], su[4][128], red[256];
    const int t = threadIdx.x & 127, g = threadIdx.x >> 7;
    const int i = blockIdx.x * 128 + t;

    float av = 0.f, au = 0.f;
#pragma unroll 4
    for (int o = g * 128; o < (g + 1) * 128; o++) {
        av += Wq[(size_t)o * CIN + i] * bk[o];
        au += Wk[(size_t)o * CIN + i] * bq[o];
    }
    sv[g][t] = av; su[g][t] = au;

    if (threadIdx.x < 256)
        red[threadIdx.x] = bq[threadIdx.x] * bk[threadIdx.x]
                         + bq[threadIdx.x + 256] * bk[threadIdx.x + 256];
    __syncthreads();

    if (g == 0) {
        wv[i] = sv[0][t] + sv[1][t] + sv[2][t] + sv[3][t];
        wu[i] = su[0][t] + su[1][t] + su[2][t] + su[3][t];
    }
    for (int s = 128; s > 0; s >>= 1) {
        if (threadIdx.x < s) red[threadIdx.x] += red[threadIdx.x + s];
        __syncthreads();
    }
    if (blockIdx.x == 0 && threadIdx.x == 0) c0[0] = red[0];
}

// ---------------------------------------------------------------------------
// Per-token rank-1 terms: rv[b][n] = w_v.x_n + c0 ; cu[b][m] = w_u.x_m
// grid = B*NTOK/64 = 288 blocks x 256 threads: 64 tokens, 4 channel-groups of 96.
// ---------------------------------------------------------------------------
__global__ __launch_bounds__(256)
void uv_kernel(const float* __restrict__ x, const float* __restrict__ wv,
               const float* __restrict__ wu, const float* __restrict__ c0,
               float* __restrict__ rv, float* __restrict__ cu)
{
    __shared__ float swv[CIN], swu[CIN], redv[4][64], redu[4][64];
    const int tid = threadIdx.x;
    for (int i = tid; i < CIN; i += 256) { swv[i] = wv[i]; swu[i] = wu[i]; }
    __syncthreads();

    const int tile = blockIdx.x;
    const int b = tile / (NTOK / 64);
    const int n0 = (tile % (NTOK / 64)) * 64;
    const float* xb = x + (size_t)b * CIN * NTOK;
    const int t = tid & 63, g = tid >> 6;

    float sv = 0.f, su = 0.f;
#pragma unroll 4
    for (int c = g * 96; c < (g + 1) * 96; c++) {
        const float xv = xb[(size_t)c * NTOK + n0 + t];
        sv += swv[c] * xv;
        su += swu[c] * xv;
    }
    redv[g][t] = sv; redu[g][t] = su;
    __syncthreads();

    if (g == 0) {
        const int idx = b * NTOK + n0 + t;
        rv[idx] = redv[0][t] + redv[1][t] + redv[2][t] + redv[3][t] + c0[0];
        cu[idx] = redu[0][t] + redu[1][t] + redu[2][t] + redu[3][t];
    }
}

// ---------------------------------------------------------------------------
extern "C" void kernel_launch(void* const* d_in, const int* in_sizes, int n_in,
                              void* d_out, int out_size)
{
    const float* x  = (const float*)d_in[0];
    const float* Wq = (const float*)d_in[1];
    const float* bq = (const float*)d_in[2];
    const float* Wk = (const float*)d_in[3];
    const float* bk = (const float*)d_in[4];
    const float* Wv = (const float*)d_in[5];
    const float* bv = (const float*)d_in[6];
    const float* Wo = (const float*)d_in[7];
    const float* bo = (const float*)d_in[8];
    float* out = (float*)d_out;

    __half *xh, *yh, *vh, *p, *ao, *wqh, *wkh, *wvh, *woh, *mh;
    float *z, *rv, *cu, *wv, *wu, *c0;
    cudaGetSymbolAddress((void**)&xh,  g_xh);
    cudaGetSymbolAddress((void**)&yh,  g_yh);
    cudaGetSymbolAddress((void**)&vh,  g_vh);
    cudaGetSymbolAddress((void**)&p,   g_p);
    cudaGetSymbolAddress((void**)&ao,  g_ao);
    cudaGetSymbolAddress((void**)&z,   g_z);
    cudaGetSymbolAddress((void**)&rv,  g_rv);
    cudaGetSymbolAddress((void**)&cu,  g_cu);
    cudaGetSymbolAddress((void**)&wqh, g_wqh);
    cudaGetSymbolAddress((void**)&wkh, g_wkh);
    cudaGetSymbolAddress((void**)&wvh, g_wvh);
    cudaGetSymbolAddress((void**)&woh, g_woh);
    cudaGetSymbolAddress((void**)&mh,  g_mh);
    cudaGetSymbolAddress((void**)&wv,  g_wv);
    cudaGetSymbolAddress((void**)&wu,  g_wu);
    cudaGetSymbolAddress((void**)&c0,  g_c0);

    cudaFuncSetAttribute(hgemm<3,3,1,0,0,0>, cudaFuncAttributeMaxDynamicSharedMemorySize, SMEM_BYTES);
    cudaFuncSetAttribute(hgemm<3,0,1,2,0,0>, cudaFuncAttributeMaxDynamicSharedMemorySize, SMEM_BYTES);
    cudaFuncSetAttribute(hgemm<0,3,1,0,0,0>, cudaFuncAttributeMaxDynamicSharedMemorySize, SMEM_BYTES);
    cudaFuncSetAttribute(hgemm<3,3,1,4,1,1>, cudaFuncAttributeMaxDynamicSharedMemorySize, SMEM_BYTES);
    cudaFuncSetAttribute(hgemm<0,3,1,3,0,0>, cudaFuncAttributeMaxDynamicSharedMemorySize, SMEM_BYTES);
    cudaFuncSetAttribute(hgemm<0,0,0,1,0,0>, cudaFuncAttributeMaxDynamicSharedMemorySize, SMEM_BYTES);

    const dim3 blk(NTHREADS);
    const size_t sX  = (size_t)CIN * NTOK;
    const size_t sY  = (size_t)CIN * NTOK;
    const size_t sV  = (size_t)NTOK * OCH;
    const size_t sS  = (size_t)NTOK * NTOK;
    const size_t sAO = (size_t)NTOK * OCH;
    const float scale = 0.044194173824159216f; // 1/sqrt(512)

    // 0) weight packing, x conversion, rank-1 bias terms
    pack_kernel<<<(OCH * OCH + 255) / 256, 256>>>(Wq, Wk, Wv, Wo, wqh, wkh, wvh, woh, z);
    xconv_kernel<<<(int)((size_t)BATCH * CIN * NTOK / 4 / 256), 256>>>(x, xh);
    uvw_kernel<<<CIN / 128, 512>>>(Wq, Wk, bq, bk, wv, wu, c0);
    uv_kernel<<<BATCH * NTOK / 64, 256>>>(x, wv, wu, c0, rv, cu);

    // 1) M = Wq^T Wk  (384x384, K=512; both operands TR)
    {
        dim3 g(CIN / 128, CIN / 128, 1);
        hgemm<3,3,1,0,0,0><<<g, blk, SMEM_BYTES>>>(wqh, wkh, mh, OCH, CIN, CIN, CIN,
                                                   0, 0, 0, nullptr, nullptr, nullptr, 0, 1.0f);
    }
    // 2) V[tok][och] = x^T Wv^T + bv  (A = xh TR, B = wvh NT, col bias)
    {
        dim3 g(OCH / 128, NTOK / 128, BATCH);
        hgemm<3,0,1,2,0,0><<<g, blk, SMEM_BYTES>>>(xh, wvh, vh, CIN, NTOK, CIN, OCH,
                                                   sX, 0, sV, bv, nullptr, nullptr, 0, 1.0f);
    }
    // 3) Y[c][tok] = M x   (A = mh NT, B = xh TR)
    {
        dim3 g(NTOK / 128, CIN / 128, BATCH);
        hgemm<0,3,1,0,0,0><<<g, blk, SMEM_BYTES>>>(mh, xh, yh, CIN, CIN, NTOK, NTOK,
                                                   0, sX, sY, nullptr, nullptr, nullptr, 0, 1.0f);
    }
    // 4) P' = exp(scale*(x^T Y + rv[n] + cu[m]))  (K=384, fused exp + atomic Z)
    {
        dim3 g(NTOK / 128, NTOK / 128, BATCH);
        hgemm<3,3,1,4,1,1><<<g, blk, SMEM_BYTES>>>(xh, yh, p, CIN, NTOK, NTOK, NTOK,
                                                   sX, sY, sS, rv, cu, z, NTOK, scale);
    }
    // 5) AO[tok][och] = (P' V) / Z[tok]   (B = vh TR)
    {
        dim3 g(OCH / 128, NTOK / 128, BATCH);
        hgemm<0,3,1,3,0,0><<<g, blk, SMEM_BYTES>>>(p, vh, ao, NTOK, NTOK, OCH, OCH,
                                                   sS, sV, sAO, z, nullptr, nullptr, NTOK, 1.0f);
    }
    // 6) out[och][tok] = Wo AO^T + bo
    {
        dim3 g(NTOK / 128, OCH / 128, BATCH);
        hgemm<0,0,0,1,0,0><<<g, blk, SMEM_BYTES>>>(woh, ao, out, OCH, OCH, OCH, NTOK,
                                                   0, sAO, (size_t)OCH * NTOK, bo, nullptr, nullptr, 0, 1.0f);
    }
}

// round 13
// speedup vs baseline: 2.8929x; 1.0285x over previous
#include <cuda_runtime.h>
#include <cuda_fp16.h>
#include <math.h>
#include <stdint.h>

// Problem constants
#define BATCH 8
#define CIN   384
#define OCH   512
#define NTOK  2304   // 48*48

#define NTHREADS 128
// Block tile 128x128, K-tile = 32 halves, warp tile 64x64 (2x2 warps)
#define SNT 40     // NT smem tile row stride (halves): [128 r][40]
#define STR 136    // TR smem tile row stride (halves): [32 k][136]
#define SLOT 5120  // halves per stage slot (10240 B)
#define SLOTB 10240
#define NSTAGE 4
#define SMEM_BYTES (2 * NSTAGE * SLOTB)   // 81920

// Static scratch (no allocations allowed)
__device__ __half g_xh [(size_t)BATCH * CIN * NTOK];   // x half, [B][c][tok]
__device__ __half g_yh [(size_t)BATCH * CIN * NTOK];   // Y = M*X, [B][c][tok]
__device__ __half g_vh [(size_t)BATCH * NTOK * OCH];   // V proj, [B][tok][och]
__device__ __half g_p  [(size_t)BATCH * NTOK * NTOK];  // P' = exp(scores), half
__device__ __half g_ao [(size_t)BATCH * NTOK * OCH];   // [B][tok][och]
__device__ float  g_z  [(size_t)BATCH * NTOK];         // rowsum(P') via atomics
__device__ float  g_rv [(size_t)BATCH * NTOK];         // v[n] + c0 (row bias of S)
__device__ float  g_cu [(size_t)BATCH * NTOK];         // u[m]      (col bias of S)
__device__ __half g_wqh[(size_t)OCH * CIN];            // Wq half
__device__ __half g_wkh[(size_t)OCH * CIN];            // Wk half
__device__ __half g_wvh[(size_t)OCH * CIN];            // Wv half
__device__ __half g_woh[(size_t)OCH * OCH];            // Wo half
__device__ __half g_mh [(size_t)CIN * CIN];            // M = Wq^T Wk (half)
__device__ float  g_wv [CIN];                           // Wq^T bk
__device__ float  g_wu [CIN];                           // Wk^T bq
__device__ float  g_c0 [1];                             // bq . bk

// ---------------------------------------------------------------------------
// Helpers
// ---------------------------------------------------------------------------
__device__ __forceinline__ uint32_t smem_u32(const void* p) {
    uint32_t a;
    asm("{ .reg .u64 t; cvta.to.shared.u64 t, %1; cvt.u32.u64 %0, t; }" : "=r"(a) : "l"(p));
    return a;
}
__device__ __forceinline__ void ldsm4(uint32_t r[4], uint32_t addr) {
    asm volatile("ldmatrix.sync.aligned.m8n8.x4.shared.b16 {%0,%1,%2,%3}, [%4];"
                 : "=r"(r[0]), "=r"(r[1]), "=r"(r[2]), "=r"(r[3]) : "r"(addr));
}
__device__ __forceinline__ void ldsm4t(uint32_t r[4], uint32_t addr) {
    asm volatile("ldmatrix.sync.aligned.m8n8.x4.trans.shared.b16 {%0,%1,%2,%3}, [%4];"
                 : "=r"(r[0]), "=r"(r[1]), "=r"(r[2]), "=r"(r[3]) : "r"(addr));
}
__device__ __forceinline__ void mma16816(float c[4], const uint32_t a[4],
                                         uint32_t b0, uint32_t b1) {
    asm volatile(
        "mma.sync.aligned.m16n8k16.row.col.f32.f16.f16.f32 "
        "{%0,%1,%2,%3}, {%4,%5,%6,%7}, {%8,%9}, {%0,%1,%2,%3};"
        : "+f"(c[0]), "+f"(c[1]), "+f"(c[2]), "+f"(c[3])
        : "r"(a[0]), "r"(a[1]), "r"(a[2]), "r"(a[3]), "r"(b0), "r"(b1));
}
__device__ __forceinline__ void cp16(uint32_t saddr, const void* gaddr) {
    asm volatile("cp.async.cg.shared.global [%0], [%1], 16;" :: "r"(saddr), "l"(gaddr));
}
__device__ __forceinline__ void cp_commit() { asm volatile("cp.async.commit_group;"); }
template <int N>
__device__ __forceinline__ void cp_waitg() {
    asm volatile("cp.async.wait_group %0;" :: "n"(N) : "memory");
}

// ---------------------------------------------------------------------------
// cp.async staging. TRT=0: NT tile [128][SNT] from [r][k] src.
// TRT=1: TR tile [32][STR] from [k][r] src (r contiguous).
// ---------------------------------------------------------------------------
template <int TRT>
__device__ __forceinline__ void cp_stage(uint32_t sbase, const __half* __restrict__ S,
                                         int ld, int r0, int kt, int tid)
{
    if (TRT == 0) {
#pragma unroll
        for (int i = 0; i < 4; i++) {
            const int idx = tid + i * 128;
            const int r = idx >> 2, c8 = (idx & 3) * 8;
            cp16(sbase + (uint32_t)(r * SNT + c8) * 2, &S[(size_t)(r0 + r) * ld + kt + c8]);
        }
    } else {
#pragma unroll
        for (int i = 0; i < 4; i++) {
            const int idx = tid + i * 128;
            const int k = idx >> 4, c8 = (idx & 15) * 8;
            cp16(sbase + (uint32_t)(k * STR + c8) * 2, &S[(size_t)(kt + k) * ld + r0 + c8]);
        }
    }
}

// ---------------------------------------------------------------------------
// One 128x128x32 tile step. Warp tile 64x64 via m16n8k16 + ldmatrix.
// Mode: 0 = NT tile (ldsm4), 3 = TR tile (ldsm4t).
// ---------------------------------------------------------------------------
template <int AM, int BM>
__device__ __forceinline__ void compute_bk(uint32_t sa, uint32_t sb,
                                           float acc[4][8][4], int lane, int wm, int wn)
{
    constexpr bool ATR = (AM == 3), BTR = (BM == 3);
#pragma unroll
    for (int ks = 0; ks < 32; ks += 16) {
        uint32_t a[4][4];
#pragma unroll
        for (int mb = 0; mb < 4; mb++) {
            if (!ATR) {
                const int row = wm + mb * 16 + (lane & 15);
                const int col = ks + ((lane >> 4) << 3);
                ldsm4(a[mb], sa + (uint32_t)(row * SNT + col) * 2);
            } else {
                const int k   = ks + (lane & 7) + ((lane & 16) >> 1);
                const int col = wm + mb * 16 + (lane & 8);
                ldsm4t(a[mb], sa + (uint32_t)(k * STR + col) * 2);
            }
        }
        uint32_t bfr[4][4];
#pragma unroll
        for (int nb2 = 0; nb2 < 4; nb2++) {
            if (!BTR) {
                const int row = wn + nb2 * 16 + (lane & 15);
                const int col = ks + ((lane >> 4) << 3);
                ldsm4(bfr[nb2], sb + (uint32_t)(row * SNT + col) * 2);
            } else {
                const int k   = ks + (lane & 7) + (lane & 8);
                const int col = wn + nb2 * 16 + ((lane & 16) >> 1);
                ldsm4t(bfr[nb2], sb + (uint32_t)(k * STR + col) * 2);
            }
        }
#pragma unroll
        for (int mb = 0; mb < 4; mb++)
#pragma unroll
            for (int nb = 0; nb < 8; nb++) {
                uint32_t b0, b1;
                if (!BTR) { b0 = bfr[nb >> 1][nb & 1];       b1 = bfr[nb >> 1][(nb & 1) + 2]; }
                else      { b0 = bfr[nb >> 1][2 * (nb & 1)]; b1 = bfr[nb >> 1][2 * (nb & 1) + 1]; }
                mma16816(acc[mb][nb], a[mb], b0, b1);
            }
    }
}

// ---------------------------------------------------------------------------
// Universal batched all-f16 GEMM:
//   C[m][n] = f((acc + biases) * scale)
// AM/BM: 0 = f16 NT, 3 = f16 TR (both cp.async 4-stage).
// OUTH: 1 = half out. BIAS: 0 none, 1 row add, 2 col add, 3 row DIVIDE (by Z),
//       4 row add (bias) + col add (bias2).
// EXPM: 1 = __expf after scale. SUMZ: 1 = atomic row sums into zsum.
// ---------------------------------------------------------------------------
template <int AM, int BM, int OUTH, int BIAS, int EXPM, int SUMZ>
__global__ __launch_bounds__(NTHREADS, 2)
void hgemm(const __half* __restrict__ A, const __half* __restrict__ B, void* __restrict__ C,
           int K, int ldA, int ldB, int ldC,
           size_t sA, size_t sB, size_t sC,
           const float* __restrict__ bias, const float* __restrict__ bias2,
           float* __restrict__ zsum, size_t sBias, float scale)
{
    extern __shared__ __half dsm[];

    const int tid = threadIdx.x;
    const int warp = tid >> 5, lane = tid & 31;
    const int wm = (warp >> 1) * 64, wn = (warp & 1) * 64;
    const int b = blockIdx.z;
    const int row0 = blockIdx.y * 128;
    const int col0 = blockIdx.x * 128;

    const __half* Ab = A + (size_t)b * sA;
    const __half* Bb = B + (size_t)b * sB;
    const float* biasb  = bias  ? bias  + (size_t)b * sBias : nullptr;
    const float* bias2b = bias2 ? bias2 + (size_t)b * sBias : nullptr;
    float* zsumb = zsum ? zsum + (size_t)b * sBias : nullptr;

    const uint32_t uA = smem_u32(dsm);
    const uint32_t uB = uA + NSTAGE * SLOTB;

    float acc[4][8][4];
#pragma unroll
    for (int i = 0; i < 4; i++)
#pragma unroll
        for (int j = 0; j < 8; j++)
#pragma unroll
            for (int q = 0; q < 4; q++) acc[i][j][q] = 0.f;

    const int T = K / 32;

    // Prologue: fill stages 0..2
#pragma unroll
    for (int s = 0; s < NSTAGE - 1; s++) {
        cp_stage<(AM == 3)>(uA + s * SLOTB, Ab, ldA, row0, s * 32, tid);
        cp_stage<(BM == 3)>(uB + s * SLOTB, Bb, ldB, col0, s * 32, tid);
        cp_commit();
    }

    for (int t = 0; t < T; t++) {
        cp_waitg<NSTAGE - 2>();
        __syncthreads();

        const int p = t & (NSTAGE - 1);
        const int tn = t + NSTAGE - 1;
        if (tn < T) {
            const int pn = tn & (NSTAGE - 1);
            cp_stage<(AM == 3)>(uA + pn * SLOTB, Ab, ldA, row0, tn * 32, tid);
            cp_stage<(BM == 3)>(uB + pn * SLOTB, Bb, ldB, col0, tn * 32, tid);
        }
        cp_commit();   // empty group at tail keeps FIFO accounting uniform

        compute_bk<AM, BM>(uA + p * SLOTB, uB + p * SLOTB, acc, lane, wm, wn);
    }

    // Epilogue
#pragma unroll
    for (int mb = 0; mb < 4; mb++) {
        const int m0 = row0 + wm + mb * 16 + (lane >> 2);
        const float ar0 = (BIAS == 1 || BIAS == 4) ? biasb[m0] : 0.f;
        const float ar1 = (BIAS == 1 || BIAS == 4) ? biasb[m0 + 8] : 0.f;
        const float rs0 = (BIAS == 3) ? (1.0f / biasb[m0]) : 1.f;
        const float rs1 = (BIAS == 3) ? (1.0f / biasb[m0 + 8]) : 1.f;
        float s0 = 0.f, s1 = 0.f;
#pragma unroll
        for (int nb = 0; nb < 8; nb++) {
            const int n = col0 + wn + nb * 8 + 2 * (lane & 3);
            float ac0 = 0.f, ac1 = 0.f;
            if (BIAS == 2) { ac0 = biasb[n]; ac1 = biasb[n + 1]; }
            if (BIAS == 4) { ac0 = bias2b[n]; ac1 = bias2b[n + 1]; }
            float v0 = (acc[mb][nb][0] + ar0 + ac0) * scale;
            float v1 = (acc[mb][nb][1] + ar0 + ac1) * scale;
            float v2 = (acc[mb][nb][2] + ar1 + ac0) * scale;
            float v3 = (acc[mb][nb][3] + ar1 + ac1) * scale;
            if (EXPM) { v0 = __expf(v0); v1 = __expf(v1); v2 = __expf(v2); v3 = __expf(v3); }
            if (BIAS == 3) { v0 *= rs0; v1 *= rs0; v2 *= rs1; v3 *= rs1; }
            if (SUMZ) { s0 += v0 + v1; s1 += v2 + v3; }
            if (OUTH) {
                __half* Ch = (__half*)C + (size_t)b * sC;
                *reinterpret_cast<__half2*>(&Ch[(size_t)m0 * ldC + n])       = __floats2half2_rn(v0, v1);
                *reinterpret_cast<__half2*>(&Ch[(size_t)(m0 + 8) * ldC + n]) = __floats2half2_rn(v2, v3);
            } else {
                float* Cf = (float*)C + (size_t)b * sC;
                *reinterpret_cast<float2*>(&Cf[(size_t)m0 * ldC + n])       = make_float2(v0, v1);
                *reinterpret_cast<float2*>(&Cf[(size_t)(m0 + 8) * ldC + n]) = make_float2(v2, v3);
            }
        }
        if (SUMZ) {
            s0 += __shfl_xor_sync(0xffffffffu, s0, 1);
            s0 += __shfl_xor_sync(0xffffffffu, s0, 2);
            s1 += __shfl_xor_sync(0xffffffffu, s1, 1);
            s1 += __shfl_xor_sync(0xffffffffu, s1, 2);
            if ((lane & 3) == 0) {
                atomicAdd(&zsumb[m0], s0);
                atomicAdd(&zsumb[m0 + 8], s1);
            }
        }
    }
}

// ---------------------------------------------------------------------------
// Pack weights -> half; zero Z.
// ---------------------------------------------------------------------------
__global__ __launch_bounds__(256)
void pack_kernel(const float* __restrict__ Wq, const float* __restrict__ Wk,
                 const float* __restrict__ Wv, const float* __restrict__ Wo,
                 __half* __restrict__ wqh, __half* __restrict__ wkh,
                 __half* __restrict__ wvh, __half* __restrict__ woh,
                 float* __restrict__ Z)
{
    const int i = blockIdx.x * 256 + threadIdx.x;
    if (i < OCH * CIN) {
        wqh[i] = __float2half_rn(Wq[i]);
        wkh[i] = __float2half_rn(Wk[i]);
        wvh[i] = __float2half_rn(Wv[i]);
    }
    if (i < OCH * OCH) woh[i] = __float2half_rn(Wo[i]);
    if (i < BATCH * NTOK) Z[i] = 0.f;
}

// ---------------------------------------------------------------------------
// w_v = Wq^T bk, w_u = Wk^T bq, c0 = bq.bk
// grid = 3 blocks x 512 threads: 128 i-columns per block, 4 o-groups of 128.
// ---------------------------------------------------------------------------
__global__ __launch_bounds__(512)
void uvw_kernel(const float* __restrict__ Wq, const float* __restrict__ Wk,
                const float* __restrict__ bq, const float* __restrict__ bk,
                float* __restrict__ wv, float* __restrict__ wu, float* __restrict__ c0)
{
    __shared__ float sv[4][128], su[4][128], red[256];
    const int t = threadIdx.x & 127, g = threadIdx.x >> 7;
    const int i = blockIdx.x * 128 + t;

    float av = 0.f, au = 0.f;
#pragma unroll 4
    for (int o = g * 128; o < (g + 1) * 128; o++) {
        av += Wq[(size_t)o * CIN + i] * bk[o];
        au += Wk[(size_t)o * CIN + i] * bq[o];
    }
    sv[g][t] = av; su[g][t] = au;

    if (threadIdx.x < 256)
        red[threadIdx.x] = bq[threadIdx.x] * bk[threadIdx.x]
                         + bq[threadIdx.x + 256] * bk[threadIdx.x + 256];
    __syncthreads();

    if (g == 0) {
        wv[i] = sv[0][t] + sv[1][t] + sv[2][t] + sv[3][t];
        wu[i] = su[0][t] + su[1][t] + su[2][t] + su[3][t];
    }
    for (int s = 128; s > 0; s >>= 1) {
        if (threadIdx.x < s) red[threadIdx.x] += red[threadIdx.x + s];
        __syncthreads();
    }
    if (blockIdx.x == 0 && threadIdx.x == 0) c0[0] = red[0];
}

// ---------------------------------------------------------------------------
// Fused x convert + rank-1 terms. One pass over x:
//   xh = half(x); rv[b][n] = w_v.x_n + c0; cu[b][n] = w_u.x_n
// grid = B*NTOK/64 = 288 blocks x 512 threads: 64 tokens, 8 channel groups of 48.
// ---------------------------------------------------------------------------
__global__ __launch_bounds__(512)
void xuv_kernel(const float* __restrict__ x, __half* __restrict__ xh,
                const float* __restrict__ wv, const float* __restrict__ wu,
                const float* __restrict__ c0,
                float* __restrict__ rv, float* __restrict__ cu)
{
    __shared__ float swv[CIN], swu[CIN];
    __shared__ float redv[8][64], redu[8][64];
    const int tid = threadIdx.x;
    if (tid < CIN) { swv[tid] = wv[tid]; swu[tid] = wu[tid]; }
    __syncthreads();

    const int tile = blockIdx.x;
    const int b = tile / (NTOK / 64);
    const int n0 = (tile % (NTOK / 64)) * 64;
    const size_t base = (size_t)b * CIN * NTOK;
    const float* xb = x + base;
    __half* xhb = xh + base;
    const int t = tid & 63, g = tid >> 6;

    float sv = 0.f, su = 0.f;
#pragma unroll 6
    for (int c = g * 48; c < (g + 1) * 48; c++) {
        const size_t off = (size_t)c * NTOK + n0 + t;
        const float xv = xb[off];
        xhb[off] = __float2half_rn(xv);
        sv += swv[c] * xv;
        su += swu[c] * xv;
    }
    redv[g][t] = sv; redu[g][t] = su;
    __syncthreads();

    if (g == 0) {
        const int idx = b * NTOK + n0 + t;
        float av = 0.f, au = 0.f;
#pragma unroll
        for (int q = 0; q < 8; q++) { av += redv[q][t]; au += redu[q][t]; }
        rv[idx] = av + c0[0];
        cu[idx] = au;
    }
}

// ---------------------------------------------------------------------------
extern "C" void kernel_launch(void* const* d_in, const int* in_sizes, int n_in,
                              void* d_out, int out_size)
{
    const float* x  = (const float*)d_in[0];
    const float* Wq = (const float*)d_in[1];
    const float* bq = (const float*)d_in[2];
    const float* Wk = (const float*)d_in[3];
    const float* bk = (const float*)d_in[4];
    const float* Wv = (const float*)d_in[5];
    const float* bv = (const float*)d_in[6];
    const float* Wo = (const float*)d_in[7];
    const float* bo = (const float*)d_in[8];
    float* out = (float*)d_out;

    __half *xh, *yh, *vh, *p, *ao, *wqh, *wkh, *wvh, *woh, *mh;
    float *z, *rv, *cu, *wv, *wu, *c0;
    cudaGetSymbolAddress((void**)&xh,  g_xh);
    cudaGetSymbolAddress((void**)&yh,  g_yh);
    cudaGetSymbolAddress((void**)&vh,  g_vh);
    cudaGetSymbolAddress((void**)&p,   g_p);
    cudaGetSymbolAddress((void**)&ao,  g_ao);
    cudaGetSymbolAddress((void**)&z,   g_z);
    cudaGetSymbolAddress((void**)&rv,  g_rv);
    cudaGetSymbolAddress((void**)&cu,  g_cu);
    cudaGetSymbolAddress((void**)&wqh, g_wqh);
    cudaGetSymbolAddress((void**)&wkh, g_wkh);
    cudaGetSymbolAddress((void**)&wvh, g_wvh);
    cudaGetSymbolAddress((void**)&woh, g_woh);
    cudaGetSymbolAddress((void**)&mh,  g_mh);
    cudaGetSymbolAddress((void**)&wv,  g_wv);
    cudaGetSymbolAddress((void**)&wu,  g_wu);
    cudaGetSymbolAddress((void**)&c0,  g_c0);

    cudaFuncSetAttribute(hgemm<3,3,1,0,0,0>, cudaFuncAttributeMaxDynamicSharedMemorySize, SMEM_BYTES);
    cudaFuncSetAttribute(hgemm<3,0,1,2,0,0>, cudaFuncAttributeMaxDynamicSharedMemorySize, SMEM_BYTES);
    cudaFuncSetAttribute(hgemm<0,3,1,0,0,0>, cudaFuncAttributeMaxDynamicSharedMemorySize, SMEM_BYTES);
    cudaFuncSetAttribute(hgemm<3,3,1,4,1,1>, cudaFuncAttributeMaxDynamicSharedMemorySize, SMEM_BYTES);
    cudaFuncSetAttribute(hgemm<0,3,1,3,0,0>, cudaFuncAttributeMaxDynamicSharedMemorySize, SMEM_BYTES);
    cudaFuncSetAttribute(hgemm<0,0,0,1,0,0>, cudaFuncAttributeMaxDynamicSharedMemorySize, SMEM_BYTES);

    const dim3 blk(NTHREADS);
    const size_t sX  = (size_t)CIN * NTOK;
    const size_t sY  = (size_t)CIN * NTOK;
    const size_t sV  = (size_t)NTOK * OCH;
    const size_t sS  = (size_t)NTOK * NTOK;
    const size_t sAO = (size_t)NTOK * OCH;
    const float scale = 0.044194173824159216f; // 1/sqrt(512)

    // 0) weight packing, rank-1 vectors, fused x-convert + rank-1 terms
    pack_kernel<<<(OCH * OCH + 255) / 256, 256>>>(Wq, Wk, Wv, Wo, wqh, wkh, wvh, woh, z);
    uvw_kernel<<<CIN / 128, 512>>>(Wq, Wk, bq, bk, wv, wu, c0);
    xuv_kernel<<<BATCH * NTOK / 64, 512>>>(x, xh, wv, wu, c0, rv, cu);

    // 1) M = Wq^T Wk  (384x384, K=512; both operands TR)
    {
        dim3 g(CIN / 128, CIN / 128, 1);
        hgemm<3,3,1,0,0,0><<<g, blk, SMEM_BYTES>>>(wqh, wkh, mh, OCH, CIN, CIN, CIN,
                                                   0, 0, 0, nullptr, nullptr, nullptr, 0, 1.0f);
    }
    // 2) V[tok][och] = x^T Wv^T + bv  (A = xh TR, B = wvh NT, col bias)
    {
        dim3 g(OCH / 128, NTOK / 128, BATCH);
        hgemm<3,0,1,2,0,0><<<g, blk, SMEM_BYTES>>>(xh, wvh, vh, CIN, NTOK, CIN, OCH,
                                                   sX, 0, sV, bv, nullptr, nullptr, 0, 1.0f);
    }
    // 3) Y[c][tok] = M x   (A = mh NT, B = xh TR)
    {
        dim3 g(NTOK / 128, CIN / 128, BATCH);
        hgemm<0,3,1,0,0,0><<<g, blk, SMEM_BYTES>>>(mh, xh, yh, CIN, CIN, NTOK, NTOK,
                                                   0, sX, sY, nullptr, nullptr, nullptr, 0, 1.0f);
    }
    // 4) P' = exp(scale*(x^T Y + rv[n] + cu[m]))  (K=384, fused exp + atomic Z)
    {
        dim3 g(NTOK / 128, NTOK / 128, BATCH);
        hgemm<3,3,1,4,1,1><<<g, blk, SMEM_BYTES>>>(xh, yh, p, CIN, NTOK, NTOK, NTOK,
                                                   sX, sY, sS, rv, cu, z, NTOK, scale);
    }
    // 5) AO[tok][och] = (P' V) / Z[tok]   (B = vh TR)
    {
        dim3 g(OCH / 128, NTOK / 128, BATCH);
        hgemm<0,3,1,3,0,0><<<g, blk, SMEM_BYTES>>>(p, vh, ao, NTOK, NTOK, OCH, OCH,
                                                   sS, sV, sAO, z, nullptr, nullptr, NTOK, 1.0f);
    }
    // 6) out[och][tok] = Wo AO^T + bo
    {
        dim3 g(NTOK / 128, OCH / 128, BATCH);
        hgemm<0,0,0,1,0,0><<<g, blk, SMEM_BYTES>>>(woh, ao, out, OCH, OCH, OCH, NTOK,
                                                   0, sAO, (size_t)OCH * NTOK, bo, nullptr, nullptr, 0, 1.0f);
    }
}

// round 14
// speedup vs baseline: 2.9227x; 1.0103x over previous
#include <cuda_runtime.h>
#include <cuda_fp16.h>
#include <math.h>
#include <stdint.h>

// Problem constants
#define BATCH 8
#define CIN   384
#define OCH   512
#define NTOK  2304   // 48*48

#define NTHREADS 128
// Block tile 128x128, K-tile = 32 halves, warp tile 64x64 (2x2 warps)
#define SNT 40     // NT smem tile row stride (halves): [128 r][40]
#define STR 136    // TR smem tile row stride (halves): [32 k][136]
#define SLOT 5120  // halves per stage slot (10240 B)
#define SLOTB 10240
#define NSTAGE 4
#define SMEM_BYTES (2 * NSTAGE * SLOTB)   // 81920
#define MSPLIT 4   // K-splits for the M = Wq^T Wk GEMM

// Static scratch (no allocations allowed)
__device__ __half g_xh [(size_t)BATCH * CIN * NTOK];   // x half, [B][c][tok]
__device__ __half g_yh [(size_t)BATCH * CIN * NTOK];   // Y = M*X, [B][c][tok]
__device__ __half g_vh [(size_t)BATCH * NTOK * OCH];   // V proj, [B][tok][och]
__device__ __half g_p  [(size_t)BATCH * NTOK * NTOK];  // P' = exp(scores), half
__device__ __half g_ao [(size_t)BATCH * NTOK * OCH];   // [B][tok][och]
__device__ float  g_z  [(size_t)BATCH * NTOK];         // rowsum(P') via atomics
__device__ float  g_rv [(size_t)BATCH * NTOK];         // v[n] + c0 (row bias of S)
__device__ float  g_cu [(size_t)BATCH * NTOK];         // u[m]      (col bias of S)
__device__ __half g_wqh[(size_t)OCH * CIN];            // Wq half
__device__ __half g_wkh[(size_t)OCH * CIN];            // Wk half
__device__ __half g_wvh[(size_t)OCH * CIN];            // Wv half
__device__ __half g_woh[(size_t)OCH * OCH];            // Wo half
__device__ __half g_mp [(size_t)MSPLIT * CIN * CIN];   // M split-K partials
__device__ __half g_mh [(size_t)CIN * CIN];            // M = Wq^T Wk (half)
__device__ float  g_wv [CIN];                           // Wq^T bk
__device__ float  g_wu [CIN];                           // Wk^T bq
__device__ float  g_c0 [1];                             // bq . bk

// ---------------------------------------------------------------------------
// Helpers
// ---------------------------------------------------------------------------
__device__ __forceinline__ uint32_t smem_u32(const void* p) {
    uint32_t a;
    asm("{ .reg .u64 t; cvta.to.shared.u64 t, %1; cvt.u32.u64 %0, t; }" : "=r"(a) : "l"(p));
    return a;
}
__device__ __forceinline__ void ldsm4(uint32_t r[4], uint32_t addr) {
    asm volatile("ldmatrix.sync.aligned.m8n8.x4.shared.b16 {%0,%1,%2,%3}, [%4];"
                 : "=r"(r[0]), "=r"(r[1]), "=r"(r[2]), "=r"(r[3]) : "r"(addr));
}
__device__ __forceinline__ void ldsm4t(uint32_t r[4], uint32_t addr) {
    asm volatile("ldmatrix.sync.aligned.m8n8.x4.trans.shared.b16 {%0,%1,%2,%3}, [%4];"
                 : "=r"(r[0]), "=r"(r[1]), "=r"(r[2]), "=r"(r[3]) : "r"(addr));
}
__device__ __forceinline__ void mma16816(float c[4], const uint32_t a[4],
                                         uint32_t b0, uint32_t b1) {
    asm volatile(
        "mma.sync.aligned.m16n8k16.row.col.f32.f16.f16.f32 "
        "{%0,%1,%2,%3}, {%4,%5,%6,%7}, {%8,%9}, {%0,%1,%2,%3};"
        : "+f"(c[0]), "+f"(c[1]), "+f"(c[2]), "+f"(c[3])
        : "r"(a[0]), "r"(a[1]), "r"(a[2]), "r"(a[3]), "r"(b0), "r"(b1));
}
__device__ __forceinline__ void cp16(uint32_t saddr, const void* gaddr) {
    asm volatile("cp.async.cg.shared.global [%0], [%1], 16;" :: "r"(saddr), "l"(gaddr));
}
__device__ __forceinline__ void cp_commit() { asm volatile("cp.async.commit_group;"); }
template <int N>
__device__ __forceinline__ void cp_waitg() {
    asm volatile("cp.async.wait_group %0;" :: "n"(N) : "memory");
}

// ---------------------------------------------------------------------------
// cp.async staging. TRT=0: NT tile [128][SNT] from [r][k] src.
// TRT=1: TR tile [32][STR] from [k][r] src (r contiguous).
// ---------------------------------------------------------------------------
template <int TRT>
__device__ __forceinline__ void cp_stage(uint32_t sbase, const __half* __restrict__ S,
                                         int ld, int r0, int kt, int tid)
{
    if (TRT == 0) {
#pragma unroll
        for (int i = 0; i < 4; i++) {
            const int idx = tid + i * 128;
            const int r = idx >> 2, c8 = (idx & 3) * 8;
            cp16(sbase + (uint32_t)(r * SNT + c8) * 2, &S[(size_t)(r0 + r) * ld + kt + c8]);
        }
    } else {
#pragma unroll
        for (int i = 0; i < 4; i++) {
            const int idx = tid + i * 128;
            const int k = idx >> 4, c8 = (idx & 15) * 8;
            cp16(sbase + (uint32_t)(k * STR + c8) * 2, &S[(size_t)(kt + k) * ld + r0 + c8]);
        }
    }
}

// ---------------------------------------------------------------------------
// One 128x128x32 tile step. Warp tile 64x64 via m16n8k16 + ldmatrix.
// Mode: 0 = NT tile (ldsm4), 3 = TR tile (ldsm4t).
// ---------------------------------------------------------------------------
template <int AM, int BM>
__device__ __forceinline__ void compute_bk(uint32_t sa, uint32_t sb,
                                           float acc[4][8][4], int lane, int wm, int wn)
{
    constexpr bool ATR = (AM == 3), BTR = (BM == 3);
#pragma unroll
    for (int ks = 0; ks < 32; ks += 16) {
        uint32_t a[4][4];
#pragma unroll
        for (int mb = 0; mb < 4; mb++) {
            if (!ATR) {
                const int row = wm + mb * 16 + (lane & 15);
                const int col = ks + ((lane >> 4) << 3);
                ldsm4(a[mb], sa + (uint32_t)(row * SNT + col) * 2);
            } else {
                const int k   = ks + (lane & 7) + ((lane & 16) >> 1);
                const int col = wm + mb * 16 + (lane & 8);
                ldsm4t(a[mb], sa + (uint32_t)(k * STR + col) * 2);
            }
        }
        uint32_t bfr[4][4];
#pragma unroll
        for (int nb2 = 0; nb2 < 4; nb2++) {
            if (!BTR) {
                const int row = wn + nb2 * 16 + (lane & 15);
                const int col = ks + ((lane >> 4) << 3);
                ldsm4(bfr[nb2], sb + (uint32_t)(row * SNT + col) * 2);
            } else {
                const int k   = ks + (lane & 7) + (lane & 8);
                const int col = wn + nb2 * 16 + ((lane & 16) >> 1);
                ldsm4t(bfr[nb2], sb + (uint32_t)(k * STR + col) * 2);
            }
        }
#pragma unroll
        for (int mb = 0; mb < 4; mb++)
#pragma unroll
            for (int nb = 0; nb < 8; nb++) {
                uint32_t b0, b1;
                if (!BTR) { b0 = bfr[nb >> 1][nb & 1];       b1 = bfr[nb >> 1][(nb & 1) + 2]; }
                else      { b0 = bfr[nb >> 1][2 * (nb & 1)]; b1 = bfr[nb >> 1][2 * (nb & 1) + 1]; }
                mma16816(acc[mb][nb], a[mb], b0, b1);
            }
    }
}

// ---------------------------------------------------------------------------
// Universal batched all-f16 GEMM:
//   C[m][n] = f((acc + biases) * scale)
// AM/BM: 0 = f16 NT, 3 = f16 TR (both cp.async 4-stage).
// OUTH: 1 = half out. BIAS: 0 none, 1 row add, 2 col add, 3 row DIVIDE (by Z),
//       4 row add (bias) + col add (bias2).
// EXPM: 1 = __expf after scale. SUMZ: 1 = atomic row sums into zsum.
// The z grid dim + (sA,sB,sC) strides also express split-K (slice offsets).
// ---------------------------------------------------------------------------
template <int AM, int BM, int OUTH, int BIAS, int EXPM, int SUMZ>
__global__ __launch_bounds__(NTHREADS, 2)
void hgemm(const __half* __restrict__ A, const __half* __restrict__ B, void* __restrict__ C,
           int K, int ldA, int ldB, int ldC,
           size_t sA, size_t sB, size_t sC,
           const float* __restrict__ bias, const float* __restrict__ bias2,
           float* __restrict__ zsum, size_t sBias, float scale)
{
    extern __shared__ __half dsm[];

    const int tid = threadIdx.x;
    const int warp = tid >> 5, lane = tid & 31;
    const int wm = (warp >> 1) * 64, wn = (warp & 1) * 64;
    const int b = blockIdx.z;
    const int row0 = blockIdx.y * 128;
    const int col0 = blockIdx.x * 128;

    const __half* Ab = A + (size_t)b * sA;
    const __half* Bb = B + (size_t)b * sB;
    const float* biasb  = bias  ? bias  + (size_t)b * sBias : nullptr;
    const float* bias2b = bias2 ? bias2 + (size_t)b * sBias : nullptr;
    float* zsumb = zsum ? zsum + (size_t)b * sBias : nullptr;

    const uint32_t uA = smem_u32(dsm);
    const uint32_t uB = uA + NSTAGE * SLOTB;

    float acc[4][8][4];
#pragma unroll
    for (int i = 0; i < 4; i++)
#pragma unroll
        for (int j = 0; j < 8; j++)
#pragma unroll
            for (int q = 0; q < 4; q++) acc[i][j][q] = 0.f;

    const int T = K / 32;

    // Prologue: fill stages 0..2
#pragma unroll
    for (int s = 0; s < NSTAGE - 1; s++) {
        cp_stage<(AM == 3)>(uA + s * SLOTB, Ab, ldA, row0, s * 32, tid);
        cp_stage<(BM == 3)>(uB + s * SLOTB, Bb, ldB, col0, s * 32, tid);
        cp_commit();
    }

    for (int t = 0; t < T; t++) {
        cp_waitg<NSTAGE - 2>();
        __syncthreads();

        const int p = t & (NSTAGE - 1);
        const int tn = t + NSTAGE - 1;
        if (tn < T) {
            const int pn = tn & (NSTAGE - 1);
            cp_stage<(AM == 3)>(uA + pn * SLOTB, Ab, ldA, row0, tn * 32, tid);
            cp_stage<(BM == 3)>(uB + pn * SLOTB, Bb, ldB, col0, tn * 32, tid);
        }
        cp_commit();   // empty group at tail keeps FIFO accounting uniform

        compute_bk<AM, BM>(uA + p * SLOTB, uB + p * SLOTB, acc, lane, wm, wn);
    }

    // Epilogue
#pragma unroll
    for (int mb = 0; mb < 4; mb++) {
        const int m0 = row0 + wm + mb * 16 + (lane >> 2);
        const float ar0 = (BIAS == 1 || BIAS == 4) ? biasb[m0] : 0.f;
        const float ar1 = (BIAS == 1 || BIAS == 4) ? biasb[m0 + 8] : 0.f;
        const float rs0 = (BIAS == 3) ? (1.0f / biasb[m0]) : 1.f;
        const float rs1 = (BIAS == 3) ? (1.0f / biasb[m0 + 8]) : 1.f;
        float s0 = 0.f, s1 = 0.f;
#pragma unroll
        for (int nb = 0; nb < 8; nb++) {
            const int n = col0 + wn + nb * 8 + 2 * (lane & 3);
            float ac0 = 0.f, ac1 = 0.f;
            if (BIAS == 2) { ac0 = biasb[n]; ac1 = biasb[n + 1]; }
            if (BIAS == 4) { ac0 = bias2b[n]; ac1 = bias2b[n + 1]; }
            float v0 = (acc[mb][nb][0] + ar0 + ac0) * scale;
            float v1 = (acc[mb][nb][1] + ar0 + ac1) * scale;
            float v2 = (acc[mb][nb][2] + ar1 + ac0) * scale;
            float v3 = (acc[mb][nb][3] + ar1 + ac1) * scale;
            if (EXPM) { v0 = __expf(v0); v1 = __expf(v1); v2 = __expf(v2); v3 = __expf(v3); }
            if (BIAS == 3) { v0 *= rs0; v1 *= rs0; v2 *= rs1; v3 *= rs1; }
            if (SUMZ) { s0 += v0 + v1; s1 += v2 + v3; }
            if (OUTH) {
                __half* Ch = (__half*)C + (size_t)b * sC;
                *reinterpret_cast<__half2*>(&Ch[(size_t)m0 * ldC + n])       = __floats2half2_rn(v0, v1);
                *reinterpret_cast<__half2*>(&Ch[(size_t)(m0 + 8) * ldC + n]) = __floats2half2_rn(v2, v3);
            } else {
                float* Cf = (float*)C + (size_t)b * sC;
                *reinterpret_cast<float2*>(&Cf[(size_t)m0 * ldC + n])       = make_float2(v0, v1);
                *reinterpret_cast<float2*>(&Cf[(size_t)(m0 + 8) * ldC + n]) = make_float2(v2, v3);
            }
        }
        if (SUMZ) {
            s0 += __shfl_xor_sync(0xffffffffu, s0, 1);
            s0 += __shfl_xor_sync(0xffffffffu, s0, 2);
            s1 += __shfl_xor_sync(0xffffffffu, s1, 1);
            s1 += __shfl_xor_sync(0xffffffffu, s1, 2);
            if ((lane & 3) == 0) {
                atomicAdd(&zsumb[m0], s0);
                atomicAdd(&zsumb[m0 + 8], s1);
            }
        }
    }
}

// ---------------------------------------------------------------------------
// Pack weights -> half; zero Z.
// ---------------------------------------------------------------------------
__global__ __launch_bounds__(256)
void pack_kernel(const float* __restrict__ Wq, const float* __restrict__ Wk,
                 const float* __restrict__ Wv, const float* __restrict__ Wo,
                 __half* __restrict__ wqh, __half* __restrict__ wkh,
                 __half* __restrict__ wvh, __half* __restrict__ woh,
                 float* __restrict__ Z)
{
    const int i = blockIdx.x * 256 + threadIdx.x;
    if (i < OCH * CIN) {
        wqh[i] = __float2half_rn(Wq[i]);
        wkh[i] = __float2half_rn(Wk[i]);
        wvh[i] = __float2half_rn(Wv[i]);
    }
    if (i < OCH * OCH) woh[i] = __float2half_rn(Wo[i]);
    if (i < BATCH * NTOK) Z[i] = 0.f;
}

// ---------------------------------------------------------------------------
// Reduce MSPLIT half partials -> half M. 8 halves (uint4) per thread.
// ---------------------------------------------------------------------------
__global__ __launch_bounds__(256)
void mred_kernel(const __half* __restrict__ mp, __half* __restrict__ mh)
{
    const int i = blockIdx.x * 256 + threadIdx.x;   // uint4 index
    constexpr int NU = CIN * CIN / 8;
    if (i >= NU) return;
    float acc[8];
#pragma unroll
    for (int q = 0; q < 8; q++) acc[q] = 0.f;
#pragma unroll
    for (int s = 0; s < MSPLIT; s++) {
        const uint4 u = reinterpret_cast<const uint4*>(mp + (size_t)s * CIN * CIN)[i];
        const __half2* h = reinterpret_cast<const __half2*>(&u);
#pragma unroll
        for (int q = 0; q < 4; q++) {
            const float2 f = __half22float2(h[q]);
            acc[2 * q] += f.x; acc[2 * q + 1] += f.y;
        }
    }
    uint4 o;
    __half2* oh = reinterpret_cast<__half2*>(&o);
#pragma unroll
    for (int q = 0; q < 4; q++) oh[q] = __floats2half2_rn(acc[2 * q], acc[2 * q + 1]);
    reinterpret_cast<uint4*>(mh)[i] = o;
}

// ---------------------------------------------------------------------------
// w_v = Wq^T bk, w_u = Wk^T bq, c0 = bq.bk
// grid = 3 blocks x 512 threads: 128 i-columns per block, 4 o-groups of 128.
// ---------------------------------------------------------------------------
__global__ __launch_bounds__(512)
void uvw_kernel(const float* __restrict__ Wq, const float* __restrict__ Wk,
                const float* __restrict__ bq, const float* __restrict__ bk,
                float* __restrict__ wv, float* __restrict__ wu, float* __restrict__ c0)
{
    __shared__ float sv[4][128], su[4][128], red[256];
    const int t = threadIdx.x & 127, g = threadIdx.x >> 7;
    const int i = blockIdx.x * 128 + t;

    float av = 0.f, au = 0.f;
#pragma unroll 4
    for (int o = g * 128; o < (g + 1) * 128; o++) {
        av += Wq[(size_t)o * CIN + i] * bk[o];
        au += Wk[(size_t)o * CIN + i] * bq[o];
    }
    sv[g][t] = av; su[g][t] = au;

    if (threadIdx.x < 256)
        red[threadIdx.x] = bq[threadIdx.x] * bk[threadIdx.x]
                         + bq[threadIdx.x + 256] * bk[threadIdx.x + 256];
    __syncthreads();

    if (g == 0) {
        wv[i] = sv[0][t] + sv[1][t] + sv[2][t] + sv[3][t];
        wu[i] = su[0][t] + su[1][t] + su[2][t] + su[3][t];
    }
    for (int s = 128; s > 0; s >>= 1) {
        if (threadIdx.x < s) red[threadIdx.x] += red[threadIdx.x + s];
        __syncthreads();
    }
    if (blockIdx.x == 0 && threadIdx.x == 0) c0[0] = red[0];
}

// ---------------------------------------------------------------------------
// Fused x convert + rank-1 terms. One pass over x:
//   xh = half(x); rv[b][n] = w_v.x_n + c0; cu[b][n] = w_u.x_n
// grid = B*NTOK/64 = 288 blocks x 512 threads: 64 tokens, 8 channel groups of 48.
// ---------------------------------------------------------------------------
__global__ __launch_bounds__(512)
void xuv_kernel(const float* __restrict__ x, __half* __restrict__ xh,
                const float* __restrict__ wv, const float* __restrict__ wu,
                const float* __restrict__ c0,
                float* __restrict__ rv, float* __restrict__ cu)
{
    __shared__ float swv[CIN], swu[CIN];
    __shared__ float redv[8][64], redu[8][64];
    const int tid = threadIdx.x;
    if (tid < CIN) { swv[tid] = wv[tid]; swu[tid] = wu[tid]; }
    __syncthreads();

    const int tile = blockIdx.x;
    const int b = tile / (NTOK / 64);
    const int n0 = (tile % (NTOK / 64)) * 64;
    const size_t base = (size_t)b * CIN * NTOK;
    const float* xb = x + base;
    __half* xhb = xh + base;
    const int t = tid & 63, g = tid >> 6;

    float sv = 0.f, su = 0.f;
#pragma unroll 6
    for (int c = g * 48; c < (g + 1) * 48; c++) {
        const size_t off = (size_t)c * NTOK + n0 + t;
        const float xv = xb[off];
        xhb[off] = __float2half_rn(xv);
        sv += swv[c] * xv;
        su += swu[c] * xv;
    }
    redv[g][t] = sv; redu[g][t] = su;
    __syncthreads();

    if (g == 0) {
        const int idx = b * NTOK + n0 + t;
        float av = 0.f, au = 0.f;
#pragma unroll
        for (int q = 0; q < 8; q++) { av += redv[q][t]; au += redu[q][t]; }
        rv[idx] = av + c0[0];
        cu[idx] = au;
    }
}

// ---------------------------------------------------------------------------
extern "C" void kernel_launch(void* const* d_in, const int* in_sizes, int n_in,
                              void* d_out, int out_size)
{
    const float* x  = (const float*)d_in[0];
    const float* Wq = (const float*)d_in[1];
    const float* bq = (const float*)d_in[2];
    const float* Wk = (const float*)d_in[3];
    const float* bk = (const float*)d_in[4];
    const float* Wv = (const float*)d_in[5];
    const float* bv = (const float*)d_in[6];
    const float* Wo = (const float*)d_in[7];
    const float* bo = (const float*)d_in[8];
    float* out = (float*)d_out;

    __half *xh, *yh, *vh, *p, *ao, *wqh, *wkh, *wvh, *woh, *mp, *mh;
    float *z, *rv, *cu, *wv, *wu, *c0;
    cudaGetSymbolAddress((void**)&xh,  g_xh);
    cudaGetSymbolAddress((void**)&yh,  g_yh);
    cudaGetSymbolAddress((void**)&vh,  g_vh);
    cudaGetSymbolAddress((void**)&p,   g_p);
    cudaGetSymbolAddress((void**)&ao,  g_ao);
    cudaGetSymbolAddress((void**)&z,   g_z);
    cudaGetSymbolAddress((void**)&rv,  g_rv);
    cudaGetSymbolAddress((void**)&cu,  g_cu);
    cudaGetSymbolAddress((void**)&wqh, g_wqh);
    cudaGetSymbolAddress((void**)&wkh, g_wkh);
    cudaGetSymbolAddress((void**)&wvh, g_wvh);
    cudaGetSymbolAddress((void**)&woh, g_woh);
    cudaGetSymbolAddress((void**)&mp,  g_mp);
    cudaGetSymbolAddress((void**)&mh,  g_mh);
    cudaGetSymbolAddress((void**)&wv,  g_wv);
    cudaGetSymbolAddress((void**)&wu,  g_wu);
    cudaGetSymbolAddress((void**)&c0,  g_c0);

    cudaFuncSetAttribute(hgemm<3,3,1,0,0,0>, cudaFuncAttributeMaxDynamicSharedMemorySize, SMEM_BYTES);
    cudaFuncSetAttribute(hgemm<3,0,1,2,0,0>, cudaFuncAttributeMaxDynamicSharedMemorySize, SMEM_BYTES);
    cudaFuncSetAttribute(hgemm<0,3,1,0,0,0>, cudaFuncAttributeMaxDynamicSharedMemorySize, SMEM_BYTES);
    cudaFuncSetAttribute(hgemm<3,3,1,4,1,1>, cudaFuncAttributeMaxDynamicSharedMemorySize, SMEM_BYTES);
    cudaFuncSetAttribute(hgemm<0,3,1,3,0,0>, cudaFuncAttributeMaxDynamicSharedMemorySize, SMEM_BYTES);
    cudaFuncSetAttribute(hgemm<0,0,0,1,0,0>, cudaFuncAttributeMaxDynamicSharedMemorySize, SMEM_BYTES);

    const dim3 blk(NTHREADS);
    const size_t sX  = (size_t)CIN * NTOK;
    const size_t sY  = (size_t)CIN * NTOK;
    const size_t sV  = (size_t)NTOK * OCH;
    const size_t sS  = (size_t)NTOK * NTOK;
    const size_t sAO = (size_t)NTOK * OCH;
    const float scale = 0.044194173824159216f; // 1/sqrt(512)

    // 0) weight packing, rank-1 vectors, fused x-convert + rank-1 terms
    pack_kernel<<<(OCH * OCH + 255) / 256, 256>>>(Wq, Wk, Wv, Wo, wqh, wkh, wvh, woh, z);
    uvw_kernel<<<CIN / 128, 512>>>(Wq, Wk, bq, bk, wv, wu, c0);
    xuv_kernel<<<BATCH * NTOK / 64, 512>>>(x, xh, wv, wu, c0, rv, cu);

    // 1) M = Wq^T Wk, split-K over z (4 slices of 128), then reduce
    {
        dim3 g(CIN / 128, CIN / 128, MSPLIT);
        hgemm<3,3,1,0,0,0><<<g, blk, SMEM_BYTES>>>(wqh, wkh, mp, OCH / MSPLIT, CIN, CIN, CIN,
                                                   (size_t)(OCH / MSPLIT) * CIN,
                                                   (size_t)(OCH / MSPLIT) * CIN,
                                                   (size_t)CIN * CIN,
                                                   nullptr, nullptr, nullptr, 0, 1.0f);
        mred_kernel<<<(CIN * CIN / 8 + 255) / 256, 256>>>(mp, mh);
    }
    // 2) V[tok][och] = x^T Wv^T + bv  (A = xh TR, B = wvh NT, col bias)
    {
        dim3 g(OCH / 128, NTOK / 128, BATCH);
        hgemm<3,0,1,2,0,0><<<g, blk, SMEM_BYTES>>>(xh, wvh, vh, CIN, NTOK, CIN, OCH,
                                                   sX, 0, sV, bv, nullptr, nullptr, 0, 1.0f);
    }
    // 3) Y[c][tok] = M x   (A = mh NT, B = xh TR)
    {
        dim3 g(NTOK / 128, CIN / 128, BATCH);
        hgemm<0,3,1,0,0,0><<<g, blk, SMEM_BYTES>>>(mh, xh, yh, CIN, CIN, NTOK, NTOK,
                                                   0, sX, sY, nullptr, nullptr, nullptr, 0, 1.0f);
    }
    // 4) P' = exp(scale*(x^T Y + rv[n] + cu[m]))  (K=384, fused exp + atomic Z)
    {
        dim3 g(NTOK / 128, NTOK / 128, BATCH);
        hgemm<3,3,1,4,1,1><<<g, blk, SMEM_BYTES>>>(xh, yh, p, CIN, NTOK, NTOK, NTOK,
                                                   sX, sY, sS, rv, cu, z, NTOK, scale);
    }
    // 5) AO[tok][och] = (P' V) / Z[tok]   (B = vh TR)
    {
        dim3 g(OCH / 128, NTOK / 128, BATCH);
        hgemm<0,3,1,3,0,0><<<g, blk, SMEM_BYTES>>>(p, vh, ao, NTOK, NTOK, OCH, OCH,
                                                   sS, sV, sAO, z, nullptr, nullptr, NTOK, 1.0f);
    }
    // 6) out[och][tok] = Wo AO^T + bo
    {
        dim3 g(NTOK / 128, OCH / 128, BATCH);
        hgemm<0,0,0,1,0,0><<<g, blk, SMEM_BYTES>>>(woh, ao, out, OCH, OCH, OCH, NTOK,
                                                   0, sAO, (size_t)OCH * NTOK, bo, nullptr, nullptr, 0, 1.0f);
    }
}